// round 10
// baseline (speedup 1.0000x reference)
#include <cuda_runtime.h>
#include <math.h>

#define NN 20000
#define NE 2000
#define NS 3
#define NPAIR 10016          // n-pairs (20032/2)

typedef unsigned int u32;

// ---------------- scratch (__device__ globals; zero-init, self-cleaning) ---------
__device__ u32 g_xTh[NPAIR * 64], g_xTl[NPAIR * 64];  // (fe@W2)^T as [npair][d]
__device__ u32 g_yTh[1024 * 64],  g_yTl[1024 * 64];   // (edge@W3)^T as [epair][d]
__device__ u32 g_nTh[NPAIR * 64], g_nTl[NPAIR * 64];  // node^T as [npair][d]
__device__ __align__(16) float g_acc [NE * 64];       // zeroed by finalize1
__device__ __align__(16) float g_acc2[NE * 64];       // zeroed by fusion_fin3
__device__ float g_csum[NE];                          // zeroed by fusion_fin3
__device__ __align__(16) float g_node[NN * 64];

// ---------------- helpers ----------------
__device__ __forceinline__ u32 bf16hi(float v) {      // RNE bf16, bits in top half
    u32 u = __float_as_uint(v);
    return (u + 0x7FFFu + ((u >> 16) & 1u)) & 0xFFFF0000u;
}
__device__ __forceinline__ void pack2(float v0, float v1, u32& h, u32& l) {
    u32 h0 = bf16hi(v0), h1 = bf16hi(v1);
    h = (h0 >> 16) | h1;
    u32 l0 = bf16hi(v0 - __uint_as_float(h0));
    u32 l1 = bf16hi(v1 - __uint_as_float(h1));
    l = (l0 >> 16) | l1;
}
__device__ __forceinline__ u32 packhi2(float v0, float v1) {
    return (bf16hi(v0) >> 16) | bf16hi(v1);
}
__device__ __forceinline__ void MMA(float* c, const u32* a, const u32* b) {
    asm volatile("mma.sync.aligned.m16n8k16.row.col.f32.bf16.bf16.f32 "
        "{%0,%1,%2,%3}, {%4,%5,%6,%7}, {%8,%9}, {%0,%1,%2,%3};"
        : "+f"(c[0]), "+f"(c[1]), "+f"(c[2]), "+f"(c[3])
        : "r"(a[0]), "r"(a[1]), "r"(a[2]), "r"(a[3]), "r"(b[0]), "r"(b[1]));
}
__device__ __forceinline__ void red2(float* p, float a, float b) {
    asm volatile("red.global.add.v2.f32 [%0], {%1,%2};" :: "l"(p), "f"(a), "f"(b) : "memory");
}

// ---------------- gemm_x: x = fe @ W2, writes xT [npair][d] hi/lo ----------------
__global__ __launch_bounds__(256) void gemm_x_kernel(const float* __restrict__ Fe,
                                                     const float* __restrict__ W2) {
    __shared__ __align__(16) float Fs[64][64];
    __shared__ __align__(16) float Ws[64][64];
    const int t  = threadIdx.x;
    const int n0 = blockIdx.x * 64;
    const int tx = t & 15, ty = t >> 4;
#pragma unroll
    for (int i = 0; i < 16; i++) {
        int idx = t + 256 * i;
        int r = idx >> 6, c = idx & 63;
        int n = n0 + r;
        Fs[r][c] = (n < NN) ? Fe[n * 64 + c] : 0.f;
        Ws[r][c] = W2[idx];
    }
    __syncthreads();
    float a[4][4];
#pragma unroll
    for (int i = 0; i < 4; i++)
#pragma unroll
        for (int j = 0; j < 4; j++) a[i][j] = 0.f;
#pragma unroll
    for (int k = 0; k < 64; k++) {
        float fv[4];
#pragma unroll
        for (int i = 0; i < 4; i++) fv[i] = Fs[ty * 4 + i][k];
        float4 w4 = *(const float4*)&Ws[k][tx * 4];
        float wv[4] = {w4.x, w4.y, w4.z, w4.w};
#pragma unroll
        for (int i = 0; i < 4; i++)
#pragma unroll
            for (int j = 0; j < 4; j++) a[i][j] = fmaf(fv[i], wv[j], a[i][j]);
    }
#pragma unroll
    for (int ip = 0; ip < 2; ip++)
#pragma unroll
        for (int j = 0; j < 4; j++) {
            u32 h, l; pack2(a[2 * ip][j], a[2 * ip + 1][j], h, l);
            int idx = ((n0 >> 1) + ty * 2 + ip) * 64 + tx * 4 + j;
            g_xTh[idx] = h;
            g_xTl[idx] = l;
        }
}

// ---------------- GEMM1/3: acc[e,d] += sum_n exp(adj[n,e]) * B[n,d] ----------------
// A = exp(adj) recomputed on the fly, bf16-hi only. B = hi+lo.
// MODE 1: B=xT, acc=g_acc, ones column -> csum.  MODE 3: B=nT, acc=g_acc2.
template <int MODE>
__global__ __launch_bounds__(256, 2) void gemm_et(const float* __restrict__ A) {
    extern __shared__ __align__(16) char sm[];
    u32* Ah = (u32*)sm;                  // [32 kpair][136]  (m = e)
    u32* Bh = Ah + 32 * 136;             // [32 kpair][72]   (n = d + ones col 64)
    u32* Bl = Bh + 32 * 72;
    const int t = threadIdx.x, w = t >> 5, lane = t & 31;
    const int g = lane >> 2, tg = lane & 3;
    const int e0 = blockIdx.x * 128;
    const int sp = blockIdx.y;
    const int c0  = sp * 17 + (sp < 7 ? sp : 7);
    const int nch = 17 + (sp < 7 ? 1 : 0);
    const int wm = w >> 1, wn = w & 1;
    const int rowb = wm * 32;
    const int e_l = t & 127, half = t >> 7;
    const u32* __restrict__ BTh = (MODE == 1) ? g_xTh : g_nTh;
    const u32* __restrict__ BTl = (MODE == 1) ? g_xTl : g_nTl;
    const bool e_ok = (e0 + e_l) < NE;

    float c[2][4][4];
    float ce[2][4];
#pragma unroll
    for (int mt = 0; mt < 2; mt++) {
#pragma unroll
        for (int nt = 0; nt < 4; nt++)
#pragma unroll
            for (int q = 0; q < 4; q++) c[mt][nt][q] = 0.f;
#pragma unroll
        for (int q = 0; q < 4; q++) ce[mt][q] = 0.f;
    }

    for (int ci = 0; ci < nch; ci++) {
        const int n0  = (c0 + ci) * 64;
        const int np0 = n0 >> 1;
        // ---- fill A tile [32 kpair][128 e]: exp + bf16-hi pack ----
#pragma unroll
        for (int i = 0; i < 16; i++) {
            int p_l = 2 * i + half;
            int n = n0 + 2 * p_l;
            float v0 = 0.f, v1 = 0.f;
            if (e_ok) {
                if (n < NN)     v0 = __expf(A[(size_t)n * NE + e0 + e_l]);
                if (n + 1 < NN) v1 = __expf(A[(size_t)(n + 1) * NE + e0 + e_l]);
            }
            Ah[p_l * 136 + e_l] = packhi2(v0, v1);
        }
        // ---- fill B tile [32 kpair][64 d] + ones col ----
        {
            int d = t & 63;
#pragma unroll
            for (int i = 0; i < 8; i++) {
                int r = (t >> 6) + 4 * i;
                Bh[r * 72 + d] = BTh[(np0 + r) * 64 + d];
                Bl[r * 72 + d] = BTl[(np0 + r) * 64 + d];
            }
            int r = t >> 3, cc = 64 + (t & 7);
            Bh[r * 72 + cc] = (MODE == 1 && cc == 64) ? 0x3F803F80u : 0u;
            Bl[r * 72 + cc] = 0u;
        }
        __syncthreads();
        // ---- mma ----
#pragma unroll
        for (int kt = 0; kt < 4; kt++) {
            int kp = kt * 8;
            u32 ah[2][4];
#pragma unroll
            for (int mt = 0; mt < 2; mt++) {
                int rb = rowb + mt * 16;
                ah[mt][0] = Ah[(kp + tg) * 136 + rb + g];
                ah[mt][1] = Ah[(kp + tg) * 136 + rb + g + 8];
                ah[mt][2] = Ah[(kp + tg + 4) * 136 + rb + g];
                ah[mt][3] = Ah[(kp + tg + 4) * 136 + rb + g + 8];
            }
#pragma unroll
            for (int nt = 0; nt < 4; nt++) {
                int cb = wn * 32 + nt * 8;
                u32 bh[2] = { Bh[(kp + tg) * 72 + cb + g], Bh[(kp + tg + 4) * 72 + cb + g] };
                u32 bl[2] = { Bl[(kp + tg) * 72 + cb + g], Bl[(kp + tg + 4) * 72 + cb + g] };
#pragma unroll
                for (int mt = 0; mt < 2; mt++) {
                    MMA(c[mt][nt], ah[mt], bh);
                    MMA(c[mt][nt], ah[mt], bl);
                }
            }
            if (MODE == 1 && wn == 1) {
                u32 be[2] = { Bh[(kp + tg) * 72 + 64 + g], Bh[(kp + tg + 4) * 72 + 64 + g] };
#pragma unroll
                for (int mt = 0; mt < 2; mt++) MMA(ce[mt], ah[mt], be);
            }
        }
        __syncthreads();
    }
    // ---- epilogue: split-K reduce ----
    float* acc = (MODE == 1) ? g_acc : g_acc2;
#pragma unroll
    for (int mt = 0; mt < 2; mt++)
#pragma unroll
        for (int nt = 0; nt < 4; nt++) {
            int row = e0 + rowb + mt * 16 + g;
            int col = wn * 32 + nt * 8 + 2 * tg;
            if (row < NE)     red2(&acc[row * 64 + col],       c[mt][nt][0], c[mt][nt][1]);
            if (row + 8 < NE) red2(&acc[(row + 8) * 64 + col], c[mt][nt][2], c[mt][nt][3]);
        }
    if (MODE == 1 && wn == 1 && tg == 0) {
#pragma unroll
        for (int mt = 0; mt < 2; mt++) {
            int row = e0 + rowb + mt * 16 + g;
            if (row < NE)     atomicAdd(&g_csum[row],     ce[mt][0]);
            if (row + 8 < NE) atomicAdd(&g_csum[row + 8], ce[mt][2]);
        }
    }
}

// ---------------- finalize1: edge = relu(acc/csum); y = edge@W3 -> yT; zero acc --
__global__ __launch_bounds__(256) void finalize1_kernel(const float* __restrict__ W3) {
    __shared__ __align__(16) float EsT[64][17];
    __shared__ __align__(16) float Ws[64][64];
    __shared__ __align__(16) float Ys[16][64];
    const int t  = threadIdx.x;
    const int e0 = blockIdx.x * 16;      // 125 blocks * 16 = 2000
#pragma unroll
    for (int i = 0; i < 16; i++) {
        int idx = t + 256 * i;
        Ws[idx >> 6][idx & 63] = W3[idx];
    }
#pragma unroll
    for (int i = 0; i < 4; i++) {
        int idx = t + 256 * i;
        int r = idx >> 6, c = idx & 63;
        int ge = e0 + r;
        EsT[c][r] = fmaxf(g_acc[ge * 64 + c] / g_csum[ge], 0.f);
        g_acc[ge * 64 + c] = 0.f;        // self-clean for next subgraph / replay
    }
    __syncthreads();
    const int ty = t >> 4, tx = t & 15;  // 1 row, 4 cols per thread
    float a0 = 0.f, a1 = 0.f, a2 = 0.f, a3 = 0.f;
#pragma unroll
    for (int k = 0; k < 64; k++) {
        float ev = EsT[k][ty];
        float4 w4 = *(const float4*)&Ws[k][tx * 4];
        a0 = fmaf(ev, w4.x, a0); a1 = fmaf(ev, w4.y, a1);
        a2 = fmaf(ev, w4.z, a2); a3 = fmaf(ev, w4.w, a3);
    }
    float4 r4 = {a0, a1, a2, a3};
    *(float4*)&Ys[ty][tx * 4] = r4;
    __syncthreads();
#pragma unroll
    for (int i = 0; i < 2; i++) {        // pack 8 epairs x 64 d
        int idx = t + 256 * i;
        int pp = idx >> 6, d = idx & 63;
        u32 h, l; pack2(Ys[2 * pp][d], Ys[2 * pp + 1][d], h, l);
        int gp = (e0 >> 1) + pp;
        g_yTh[gp * 64 + d] = h;
        g_yTl[gp * 64 + d] = l;
    }
}

// ---------------- GEMM2: node = relu((exp(adj)@y)/rsum); writes g_node + nT ------
__global__ __launch_bounds__(256, 3) void gemm_n(const float* __restrict__ A) {
    extern __shared__ __align__(16) char sm[];
    u32* A2h = (u32*)sm;                 // [64 n][36 epair]
    u32* Bh  = A2h + 64 * 36;            // [32 epair][72]
    u32* Bl  = Bh + 32 * 72;
    float* rsum   = (float*)(Bl + 32 * 72);  // [64]
    float* bounce = (float*)sm;          // [64][68] overlay on A2h+Bh after mma done
    const int t = threadIdx.x, w = t >> 5, lane = t & 31;
    const int g = lane >> 2, tg = lane & 3;
    const int p0 = blockIdx.x * 32;
    const int n0 = p0 * 2;
    const int wm = w >> 1, wn = w & 1;
    const int rowb = wm * 16;

    float c[4][4];
    float ce[4];
#pragma unroll
    for (int nt = 0; nt < 4; nt++)
#pragma unroll
        for (int q = 0; q < 4; q++) c[nt][q] = 0.f;
#pragma unroll
    for (int q = 0; q < 4; q++) ce[q] = 0.f;

    for (int ech = 0; ech < 32; ech++) {
        const int e0 = ech * 64, ep0 = ech * 32;
        // ---- fill A2 [64 n][32 epair]: exp from adj, natural coalesced ----
#pragma unroll
        for (int i = 0; i < 8; i++) {
            int idx = t + 256 * i;
            int n_l = idx >> 5, cc = idx & 31;
            int n = n0 + n_l, e = e0 + 2 * cc;
            float v0 = 0.f, v1 = 0.f;
            if (n < NN && e < NE) {
                float2 f2 = *(const float2*)(A + (size_t)n * NE + e);
                v0 = __expf(f2.x); v1 = __expf(f2.y);
            }
            A2h[n_l * 36 + cc] = packhi2(v0, v1);
        }
        // ---- fill B [32 epair][64 d] + ones col ----
        {
            int d = t & 63;
#pragma unroll
            for (int i = 0; i < 8; i++) {
                int r = (t >> 6) + 4 * i;
                Bh[r * 72 + d] = g_yTh[(ep0 + r) * 64 + d];
                Bl[r * 72 + d] = g_yTl[(ep0 + r) * 64 + d];
            }
            int r = t >> 3, cc = 64 + (t & 7);
            Bh[r * 72 + cc] = (cc == 64) ? 0x3F803F80u : 0u;
            Bl[r * 72 + cc] = 0u;
        }
        __syncthreads();
#pragma unroll
        for (int kt = 0; kt < 4; kt++) {
            int kp = kt * 8;
            u32 ah[4] = { A2h[(rowb + g) * 36 + kp + tg],     A2h[(rowb + g + 8) * 36 + kp + tg],
                          A2h[(rowb + g) * 36 + kp + tg + 4], A2h[(rowb + g + 8) * 36 + kp + tg + 4] };
#pragma unroll
            for (int nt = 0; nt < 4; nt++) {
                int cb = wn * 32 + nt * 8;
                u32 bh[2] = { Bh[(kp + tg) * 72 + cb + g], Bh[(kp + tg + 4) * 72 + cb + g] };
                u32 bl[2] = { Bl[(kp + tg) * 72 + cb + g], Bl[(kp + tg + 4) * 72 + cb + g] };
                MMA(c[nt], ah, bh);
                MMA(c[nt], ah, bl);
            }
            if (wn == 1) {
                u32 be[2] = { Bh[(kp + tg) * 72 + 64 + g], Bh[(kp + tg + 4) * 72 + 64 + g] };
                MMA(ce, ah, be);
            }
        }
        __syncthreads();
    }
    // ---- rsum from ones column ----
    if (wn == 1 && tg == 0) {
        rsum[rowb + g]     = ce[0];
        rsum[rowb + g + 8] = ce[2];
    }
    __syncthreads();
    float s0 = rsum[rowb + g],     ri0 = (s0 > 0.f) ? 1.f / s0 : 0.f;
    float s1 = rsum[rowb + g + 8], ri1 = (s1 > 0.f) ? 1.f / s1 : 0.f;
#pragma unroll
    for (int nt = 0; nt < 4; nt++) {
        int col = wn * 32 + nt * 8 + 2 * tg;
        bounce[(rowb + g) * 68 + col]         = fmaxf(c[nt][0], 0.f) * ri0;
        bounce[(rowb + g) * 68 + col + 1]     = fmaxf(c[nt][1], 0.f) * ri0;
        bounce[(rowb + g + 8) * 68 + col]     = fmaxf(c[nt][2], 0.f) * ri1;
        bounce[(rowb + g + 8) * 68 + col + 1] = fmaxf(c[nt][3], 0.f) * ri1;
    }
    __syncthreads();
#pragma unroll
    for (int i = 0; i < 4; i++) {            // g_node fp32 coalesced
        int idx = t + 256 * i;
        int r = idx >> 4, q = idx & 15;
        if (n0 + r < NN)
            *(float4*)&g_node[(n0 + r) * 64 + q * 4] = *(const float4*)&bounce[r * 68 + q * 4];
    }
#pragma unroll
    for (int i = 0; i < 8; i++) {            // nT [npair][d] hi/lo
        int idx = t + 256 * i;
        int d = idx & 63, pp = idx >> 6;
        u32 h, l;
        pack2(bounce[(2 * pp) * 68 + d], bounce[(2 * pp + 1) * 68 + d], h, l);
        g_nTh[(p0 + pp) * 64 + d] = h;
        g_nTl[(p0 + pp) * 64 + d] = l;
    }
}

// ---------------- fusion + finalize3 merged; zeros acc2/csum ----------------
__global__ __launch_bounds__(256) void fusion_fin3_kernel(const float* __restrict__ fe_old,
                                                          const float* __restrict__ gamma,
                                                          const float* __restrict__ beta,
                                                          const float* __restrict__ w1,
                                                          const float* __restrict__ b1,
                                                          const float* __restrict__ w2,
                                                          float* __restrict__ out_nodes,
                                                          float* __restrict__ out_edges) {
    const int t = threadIdx.x;
    if (blockIdx.x >= 625) {                 // finalize3 part: 500 blocks
        int idx = (int)(blockIdx.x - 625) * 256 + t;
        int e = idx >> 6, d = idx & 63;
        float v = fmaxf(g_acc2[idx] / g_csum[e], 0.f);
        out_edges[idx] = v * (gamma[d] * rsqrtf(1.f + 1e-5f)) + beta[d];
        g_acc2[idx] = 0.f;
        __syncthreads();                     // all csum reads in this block done
        if (d == 0) g_csum[e] = 0.f;
        return;
    }
    __shared__ float w1s[64 * 64];
    __shared__ float b1s[64], w2s[64], gs[64], bs[64];
#pragma unroll
    for (int i = 0; i < 16; i++) w1s[t + 256 * i] = w1[t + 256 * i];
    if (t < 64) {
        b1s[t] = b1[t]; w2s[t] = w2[t];
        gs[t] = gamma[t] * rsqrtf(1.f + 1e-5f); bs[t] = beta[t];
    }
    __syncthreads();
    const int warp = t >> 5, lane = t & 31;
    const int nbase = blockIdx.x * 32 + warp * 4;
    for (int it = 0; it < 4; it++) {
        int n = nbase + it;
        if (n >= NN) break;
        int off = n * 64;
        float f0 = fe_old[off + lane], f1 = fe_old[off + lane + 32];
        float nb0 = fmaf(g_node[off + lane],      gs[lane],      bs[lane]);
        float nb1 = fmaf(g_node[off + lane + 32], gs[lane + 32], bs[lane + 32]);
        float ha0 = b1s[lane], ha1 = b1s[lane + 32];
        float hb0 = ha0, hb1 = ha1;
#pragma unroll
        for (int k = 0; k < 64; k++) {
            float fk = __shfl_sync(0xffffffffu, (k < 32) ? f0 : f1, k & 31);
            float nk = __shfl_sync(0xffffffffu, (k < 32) ? nb0 : nb1, k & 31);
            float wa = w1s[k * 64 + lane], wb = w1s[k * 64 + lane + 32];
            ha0 = fmaf(fk, wa, ha0); ha1 = fmaf(fk, wb, ha1);
            hb0 = fmaf(nk, wa, hb0); hb1 = fmaf(nk, wb, hb1);
        }
        ha0 = tanhf(ha0); ha1 = tanhf(ha1);
        hb0 = tanhf(hb0); hb1 = tanhf(hb1);
        float pa = ha0 * w2s[lane] + ha1 * w2s[lane + 32];
        float pb = hb0 * w2s[lane] + hb1 * w2s[lane + 32];
#pragma unroll
        for (int o = 16; o > 0; o >>= 1) {
            pa += __shfl_down_sync(0xffffffffu, pa, o);
            pb += __shfl_down_sync(0xffffffffu, pb, o);
        }
        pa = __shfl_sync(0xffffffffu, pa, 0);
        pb = __shfl_sync(0xffffffffu, pb, 0);
        float s0 = 1.f / (1.f + expf(pb - pa));
        out_nodes[off + lane]      = s0 * f0 + (1.f - s0) * nb0;
        out_nodes[off + lane + 32] = s0 * f1 + (1.f - s0) * nb1;
    }
}

// ---------------- launch ----------------
#define SM_ET ((32*136 + 32*72*2) * 4)              // 35840
#define SM_N  ((64*36 + 32*72*2) * 4 + 256)         // 27904

extern "C" void kernel_launch(void* const* d_in, const int* in_sizes, int n_in,
                              void* d_out, int out_size) {
    const float* fe    = (const float*)d_in[0];
    const float* adj   = (const float*)d_in[1];
    const float* W2    = (const float*)d_in[2];
    const float* W3    = (const float*)d_in[3];
    const float* gamma = (const float*)d_in[4];
    const float* beta  = (const float*)d_in[5];
    const float* fw1   = (const float*)d_in[6];
    const float* fb1   = (const float*)d_in[7];
    const float* fw2   = (const float*)d_in[8];
    float* out = (float*)d_out;

    cudaFuncSetAttribute((const void*)gemm_et<1>, cudaFuncAttributeMaxDynamicSharedMemorySize, SM_ET);
    cudaFuncSetAttribute((const void*)gemm_et<3>, cudaFuncAttributeMaxDynamicSharedMemorySize, SM_ET);
    cudaFuncSetAttribute((const void*)gemm_n,     cudaFuncAttributeMaxDynamicSharedMemorySize, SM_N);

    const float* fe_cur = fe;
    for (int s = 0; s < NS; s++) {
        const float* A   = adj + (size_t)s * NN * NE;
        float* out_nodes = out + (size_t)s * (NN + NE) * 64;
        float* out_edges = out_nodes + (size_t)NN * 64;

        gemm_x_kernel<<<313, 256>>>(fe_cur, W2);
        gemm_et<1><<<dim3(16, 18), 256, SM_ET>>>(A);   // exp on the fly + edge_pre + csum
        finalize1_kernel<<<125, 256>>>(W3);            // edge -> yT; zeros g_acc
        gemm_n<<<313, 256, SM_N>>>(A);                 // node + nT (+rsum via ones col)
        gemm_et<3><<<dim3(16, 18), 256, SM_ET>>>(A);   // edge2_pre (exp recomputed)
        fusion_fin3_kernel<<<1125, 256>>>(fe_cur, gamma, beta, fw1, fb1, fw2,
                                          out_nodes, out_edges);   // zeros acc2/csum

        fe_cur = out_nodes;
    }
}

// round 11
// speedup vs baseline: 1.4459x; 1.4459x over previous
#include <cuda_runtime.h>
#include <math.h>

#define NN 20000
#define NE 2000
#define NS 3
#define EPAD 2048
#define NPAIR 10016          // n-pairs (20032/2)

typedef unsigned int u32;

// ---------------- scratch (__device__ globals; zero-init, self-cleaning) ---------
__device__ u32 g_Ph[(size_t)NPAIR * EPAD];            // packed bf16-hi pairs of exp(adj): [npair][e]
__device__ u32 g_xTh[NPAIR * 64], g_xTl[NPAIR * 64];  // (fe@W2)^T as [npair][d]
__device__ u32 g_yTh[1024 * 64],  g_yTl[1024 * 64];   // (edge@W3)^T as [epair][d]
__device__ u32 g_nTh[NPAIR * 64], g_nTl[NPAIR * 64];  // node^T as [npair][d]
__device__ __align__(16) float g_acc [NE * 64];       // zeroed by finalize1
__device__ __align__(16) float g_acc2[NE * 64];       // zeroed by fusion_fin3
__device__ float g_csum[NE];                          // zeroed by fusion_fin3
__device__ __align__(16) float g_node[NN * 64];

// ---------------- helpers ----------------
__device__ __forceinline__ u32 bf16hi(float v) {      // RNE bf16, bits in top half
    u32 u = __float_as_uint(v);
    return (u + 0x7FFFu + ((u >> 16) & 1u)) & 0xFFFF0000u;
}
__device__ __forceinline__ void pack2(float v0, float v1, u32& h, u32& l) {
    u32 h0 = bf16hi(v0), h1 = bf16hi(v1);
    h = (h0 >> 16) | h1;
    u32 l0 = bf16hi(v0 - __uint_as_float(h0));
    u32 l1 = bf16hi(v1 - __uint_as_float(h1));
    l = (l0 >> 16) | l1;
}
__device__ __forceinline__ u32 packhi2(float v0, float v1) {
    return (bf16hi(v0) >> 16) | bf16hi(v1);
}
__device__ __forceinline__ void MMA(float* c, const u32* a, const u32* b) {
    asm volatile("mma.sync.aligned.m16n8k16.row.col.f32.bf16.bf16.f32 "
        "{%0,%1,%2,%3}, {%4,%5,%6,%7}, {%8,%9}, {%0,%1,%2,%3};"
        : "+f"(c[0]), "+f"(c[1]), "+f"(c[2]), "+f"(c[3])
        : "r"(a[0]), "r"(a[1]), "r"(a[2]), "r"(a[3]), "r"(b[0]), "r"(b[1]));
}
__device__ __forceinline__ void red2(float* p, float a, float b) {
    asm volatile("red.global.add.v2.f32 [%0], {%1,%2};" :: "l"(p), "f"(a), "f"(b) : "memory");
}

// ---------------- gemm_x: x = fe @ W2, writes xT [npair][d] hi/lo ----------------
__global__ __launch_bounds__(256) void gemm_x_kernel(const float* __restrict__ Fe,
                                                     const float* __restrict__ W2) {
    __shared__ __align__(16) float Fs[64][64];
    __shared__ __align__(16) float Ws[64][64];
    const int t  = threadIdx.x;
    const int n0 = blockIdx.x * 64;
    const int tx = t & 15, ty = t >> 4;
#pragma unroll
    for (int i = 0; i < 16; i++) {
        int idx = t + 256 * i;
        int r = idx >> 6, c = idx & 63;
        int n = n0 + r;
        Fs[r][c] = (n < NN) ? Fe[n * 64 + c] : 0.f;
        Ws[r][c] = W2[idx];
    }
    __syncthreads();
    float a[4][4];
#pragma unroll
    for (int i = 0; i < 4; i++)
#pragma unroll
        for (int j = 0; j < 4; j++) a[i][j] = 0.f;
#pragma unroll
    for (int k = 0; k < 64; k++) {
        float fv[4];
#pragma unroll
        for (int i = 0; i < 4; i++) fv[i] = Fs[ty * 4 + i][k];
        float4 w4 = *(const float4*)&Ws[k][tx * 4];
        float wv[4] = {w4.x, w4.y, w4.z, w4.w};
#pragma unroll
        for (int i = 0; i < 4; i++)
#pragma unroll
            for (int j = 0; j < 4; j++) a[i][j] = fmaf(fv[i], wv[j], a[i][j]);
    }
#pragma unroll
    for (int ip = 0; ip < 2; ip++)
#pragma unroll
        for (int j = 0; j < 4; j++) {
            u32 h, l; pack2(a[2 * ip][j], a[2 * ip + 1][j], h, l);
            int idx = ((n0 >> 1) + ty * 2 + ip) * 64 + tx * 4 + j;
            g_xTh[idx] = h;
            g_xTl[idx] = l;
        }
}

// ---------------- GEMM1/3: acc[e,d] += sum_n exp(adj[n,e]) * B[n,d] ----------------
// A = exp(adj) bf16-hi only. MODE 1: exp computed here, cached to g_Ph; B=xT;
// ones column -> csum. MODE 3: A loaded from g_Ph; B=nT.
template <int MODE>
__global__ __launch_bounds__(256, 2) void gemm_et(const float* __restrict__ A) {
    extern __shared__ __align__(16) char sm[];
    u32* Ah = (u32*)sm;                  // [32 kpair][136]  (m = e)
    u32* Bh = Ah + 32 * 136;             // [32 kpair][72]   (n = d + ones col 64)
    u32* Bl = Bh + 32 * 72;
    const int t = threadIdx.x, w = t >> 5, lane = t & 31;
    const int g = lane >> 2, tg = lane & 3;
    const int e0 = blockIdx.x * 128;
    const int sp = blockIdx.y;
    const int c0  = sp * 17 + (sp < 7 ? sp : 7);
    const int nch = 17 + (sp < 7 ? 1 : 0);
    const int wm = w >> 1, wn = w & 1;
    const int rowb = wm * 32;
    const int e_l = t & 127, half = t >> 7;
    const u32* __restrict__ BTh = (MODE == 1) ? g_xTh : g_nTh;
    const u32* __restrict__ BTl = (MODE == 1) ? g_xTl : g_nTl;
    const bool e_ok = (e0 + e_l) < NE;

    float c[2][4][4];
    float ce[2][4];
#pragma unroll
    for (int mt = 0; mt < 2; mt++) {
#pragma unroll
        for (int nt = 0; nt < 4; nt++)
#pragma unroll
            for (int q = 0; q < 4; q++) c[mt][nt][q] = 0.f;
#pragma unroll
        for (int q = 0; q < 4; q++) ce[mt][q] = 0.f;
    }

    for (int ci = 0; ci < nch; ci++) {
        const int n0  = (c0 + ci) * 64;
        const int np0 = n0 >> 1;
        // ---- fill A tile [32 kpair][128 e] ----
        if (MODE == 1) {
#pragma unroll
            for (int i = 0; i < 16; i++) {
                int p_l = 2 * i + half;
                int n = n0 + 2 * p_l;
                float v0 = 0.f, v1 = 0.f;
                if (e_ok) {
                    if (n < NN)     v0 = __expf(A[(size_t)n * NE + e0 + e_l]);
                    if (n + 1 < NN) v1 = __expf(A[(size_t)(n + 1) * NE + e0 + e_l]);
                }
                u32 h = packhi2(v0, v1);
                Ah[p_l * 136 + e_l] = h;
                g_Ph[(size_t)(np0 + p_l) * EPAD + e0 + e_l] = h;   // cache once
            }
        } else {
#pragma unroll
            for (int i = 0; i < 16; i++) {
                int p_l = 2 * i + half;
                Ah[p_l * 136 + e_l] = g_Ph[(size_t)(np0 + p_l) * EPAD + e0 + e_l];
            }
        }
        // ---- fill B tile [32 kpair][64 d] + ones col ----
        {
            int d = t & 63;
#pragma unroll
            for (int i = 0; i < 8; i++) {
                int r = (t >> 6) + 4 * i;
                Bh[r * 72 + d] = BTh[(np0 + r) * 64 + d];
                Bl[r * 72 + d] = BTl[(np0 + r) * 64 + d];
            }
            int r = t >> 3, cc = 64 + (t & 7);
            Bh[r * 72 + cc] = (MODE == 1 && cc == 64) ? 0x3F803F80u : 0u;
            Bl[r * 72 + cc] = 0u;
        }
        __syncthreads();
        // ---- mma ----
#pragma unroll
        for (int kt = 0; kt < 4; kt++) {
            int kp = kt * 8;
            u32 ah[2][4];
#pragma unroll
            for (int mt = 0; mt < 2; mt++) {
                int rb = rowb + mt * 16;
                ah[mt][0] = Ah[(kp + tg) * 136 + rb + g];
                ah[mt][1] = Ah[(kp + tg) * 136 + rb + g + 8];
                ah[mt][2] = Ah[(kp + tg + 4) * 136 + rb + g];
                ah[mt][3] = Ah[(kp + tg + 4) * 136 + rb + g + 8];
            }
#pragma unroll
            for (int nt = 0; nt < 4; nt++) {
                int cb = wn * 32 + nt * 8;
                u32 bh[2] = { Bh[(kp + tg) * 72 + cb + g], Bh[(kp + tg + 4) * 72 + cb + g] };
                u32 bl[2] = { Bl[(kp + tg) * 72 + cb + g], Bl[(kp + tg + 4) * 72 + cb + g] };
#pragma unroll
                for (int mt = 0; mt < 2; mt++) {
                    MMA(c[mt][nt], ah[mt], bh);
                    MMA(c[mt][nt], ah[mt], bl);
                }
            }
            if (MODE == 1 && wn == 1) {
                u32 be[2] = { Bh[(kp + tg) * 72 + 64 + g], Bh[(kp + tg + 4) * 72 + 64 + g] };
#pragma unroll
                for (int mt = 0; mt < 2; mt++) MMA(ce[mt], ah[mt], be);
            }
        }
        __syncthreads();
    }
    // ---- epilogue: split-K reduce ----
    float* acc = (MODE == 1) ? g_acc : g_acc2;
#pragma unroll
    for (int mt = 0; mt < 2; mt++)
#pragma unroll
        for (int nt = 0; nt < 4; nt++) {
            int row = e0 + rowb + mt * 16 + g;
            int col = wn * 32 + nt * 8 + 2 * tg;
            if (row < NE)     red2(&acc[row * 64 + col],       c[mt][nt][0], c[mt][nt][1]);
            if (row + 8 < NE) red2(&acc[(row + 8) * 64 + col], c[mt][nt][2], c[mt][nt][3]);
        }
    if (MODE == 1 && wn == 1 && tg == 0) {
#pragma unroll
        for (int mt = 0; mt < 2; mt++) {
            int row = e0 + rowb + mt * 16 + g;
            if (row < NE)     atomicAdd(&g_csum[row],     ce[mt][0]);
            if (row + 8 < NE) atomicAdd(&g_csum[row + 8], ce[mt][2]);
        }
    }
}

// ---------------- finalize1: edge = relu(acc/csum); y = edge@W3 -> yT; zero acc --
__global__ __launch_bounds__(256) void finalize1_kernel(const float* __restrict__ W3) {
    __shared__ __align__(16) float EsT[64][17];
    __shared__ __align__(16) float Ws[64][64];
    __shared__ __align__(16) float Ys[16][64];
    const int t  = threadIdx.x;
    const int e0 = blockIdx.x * 16;      // 125 blocks * 16 = 2000
#pragma unroll
    for (int i = 0; i < 16; i++) {
        int idx = t + 256 * i;
        Ws[idx >> 6][idx & 63] = W3[idx];
    }
#pragma unroll
    for (int i = 0; i < 4; i++) {
        int idx = t + 256 * i;
        int r = idx >> 6, c = idx & 63;
        int ge = e0 + r;
        EsT[c][r] = fmaxf(g_acc[ge * 64 + c] / g_csum[ge], 0.f);
        g_acc[ge * 64 + c] = 0.f;        // self-clean for next subgraph / replay
    }
    __syncthreads();
    const int ty = t >> 4, tx = t & 15;  // 1 row, 4 cols per thread
    float a0 = 0.f, a1 = 0.f, a2 = 0.f, a3 = 0.f;
#pragma unroll
    for (int k = 0; k < 64; k++) {
        float ev = EsT[k][ty];
        float4 w4 = *(const float4*)&Ws[k][tx * 4];
        a0 = fmaf(ev, w4.x, a0); a1 = fmaf(ev, w4.y, a1);
        a2 = fmaf(ev, w4.z, a2); a3 = fmaf(ev, w4.w, a3);
    }
    float4 r4 = {a0, a1, a2, a3};
    *(float4*)&Ys[ty][tx * 4] = r4;
    __syncthreads();
#pragma unroll
    for (int i = 0; i < 2; i++) {        // pack 8 epairs x 64 d
        int idx = t + 256 * i;
        int pp = idx >> 6, d = idx & 63;
        u32 h, l; pack2(Ys[2 * pp][d], Ys[2 * pp + 1][d], h, l);
        int gp = (e0 >> 1) + pp;
        g_yTh[gp * 64 + d] = h;
        g_yTl[gp * 64 + d] = l;
    }
}

// ---------------- GEMM2: node = relu((exp(adj)@y)/rsum); writes g_node + nT ------
__global__ __launch_bounds__(256, 3) void gemm_n() {
    extern __shared__ __align__(16) char sm[];
    u32* A2h = (u32*)sm;                 // [64 n][36 epair]
    u32* Bh  = A2h + 64 * 36;            // [32 epair][72]
    u32* Bl  = Bh + 32 * 72;
    float* rsum   = (float*)(Bl + 32 * 72);  // [64]
    float* bounce = (float*)sm;          // [64][68] overlay after mma done
    const int t = threadIdx.x, w = t >> 5, lane = t & 31;
    const int g = lane >> 2, tg = lane & 3;
    const int p0 = blockIdx.x * 32;
    const int n0 = p0 * 2;
    const int wm = w >> 1, wn = w & 1;
    const int rowb = wm * 16;

    float c[4][4];
    float ce[4];
#pragma unroll
    for (int nt = 0; nt < 4; nt++)
#pragma unroll
        for (int q = 0; q < 4; q++) c[nt][q] = 0.f;
#pragma unroll
    for (int q = 0; q < 4; q++) ce[q] = 0.f;

    for (int ech = 0; ech < 32; ech++) {
        const int e0 = ech * 64, ep0 = ech * 32;
        // ---- fill A2 [64 n][32 epair] via prmt repack of cached g_Ph ----
#pragma unroll
        for (int i = 0; i < 4; i++) {
            int pl = w + 8 * i;
            size_t base = (size_t)(p0 + pl) * EPAD + e0 + 2 * lane;
            uint2 vh = *(const uint2*)&g_Ph[base];
            A2h[(2 * pl) * 36 + lane]     = __byte_perm(vh.x, vh.y, 0x5410);
            A2h[(2 * pl + 1) * 36 + lane] = __byte_perm(vh.x, vh.y, 0x7632);
        }
        // ---- fill B [32 epair][64 d] + ones col ----
        {
            int d = t & 63;
#pragma unroll
            for (int i = 0; i < 8; i++) {
                int r = (t >> 6) + 4 * i;
                Bh[r * 72 + d] = g_yTh[(ep0 + r) * 64 + d];
                Bl[r * 72 + d] = g_yTl[(ep0 + r) * 64 + d];
            }
            int r = t >> 3, cc = 64 + (t & 7);
            Bh[r * 72 + cc] = (cc == 64) ? 0x3F803F80u : 0u;
            Bl[r * 72 + cc] = 0u;
        }
        __syncthreads();
#pragma unroll
        for (int kt = 0; kt < 4; kt++) {
            int kp = kt * 8;
            u32 ah[4] = { A2h[(rowb + g) * 36 + kp + tg],     A2h[(rowb + g + 8) * 36 + kp + tg],
                          A2h[(rowb + g) * 36 + kp + tg + 4], A2h[(rowb + g + 8) * 36 + kp + tg + 4] };
#pragma unroll
            for (int nt = 0; nt < 4; nt++) {
                int cb = wn * 32 + nt * 8;
                u32 bh[2] = { Bh[(kp + tg) * 72 + cb + g], Bh[(kp + tg + 4) * 72 + cb + g] };
                u32 bl[2] = { Bl[(kp + tg) * 72 + cb + g], Bl[(kp + tg + 4) * 72 + cb + g] };
                MMA(c[nt], ah, bh);
                MMA(c[nt], ah, bl);
            }
            if (wn == 1) {
                u32 be[2] = { Bh[(kp + tg) * 72 + 64 + g], Bh[(kp + tg + 4) * 72 + 64 + g] };
                MMA(ce, ah, be);
            }
        }
        __syncthreads();
    }
    // ---- rsum from ones column ----
    if (wn == 1 && tg == 0) {
        rsum[rowb + g]     = ce[0];
        rsum[rowb + g + 8] = ce[2];
    }
    __syncthreads();
    float s0 = rsum[rowb + g],     ri0 = (s0 > 0.f) ? 1.f / s0 : 0.f;
    float s1 = rsum[rowb + g + 8], ri1 = (s1 > 0.f) ? 1.f / s1 : 0.f;
#pragma unroll
    for (int nt = 0; nt < 4; nt++) {
        int col = wn * 32 + nt * 8 + 2 * tg;
        bounce[(rowb + g) * 68 + col]         = fmaxf(c[nt][0], 0.f) * ri0;
        bounce[(rowb + g) * 68 + col + 1]     = fmaxf(c[nt][1], 0.f) * ri0;
        bounce[(rowb + g + 8) * 68 + col]     = fmaxf(c[nt][2], 0.f) * ri1;
        bounce[(rowb + g + 8) * 68 + col + 1] = fmaxf(c[nt][3], 0.f) * ri1;
    }
    __syncthreads();
#pragma unroll
    for (int i = 0; i < 4; i++) {            // g_node fp32 coalesced
        int idx = t + 256 * i;
        int r = idx >> 4, q = idx & 15;
        if (n0 + r < NN)
            *(float4*)&g_node[(n0 + r) * 64 + q * 4] = *(const float4*)&bounce[r * 68 + q * 4];
    }
#pragma unroll
    for (int i = 0; i < 8; i++) {            // nT [npair][d] hi/lo
        int idx = t + 256 * i;
        int d = idx & 63, pp = idx >> 6;
        u32 h, l;
        pack2(bounce[(2 * pp) * 68 + d], bounce[(2 * pp + 1) * 68 + d], h, l);
        g_nTh[(p0 + pp) * 64 + d] = h;
        g_nTl[(p0 + pp) * 64 + d] = l;
    }
}

// ---------------- fusion + finalize3 merged; zeros acc2/csum ----------------
__global__ __launch_bounds__(256) void fusion_fin3_kernel(const float* __restrict__ fe_old,
                                                          const float* __restrict__ gamma,
                                                          const float* __restrict__ beta,
                                                          const float* __restrict__ w1,
                                                          const float* __restrict__ b1,
                                                          const float* __restrict__ w2,
                                                          float* __restrict__ out_nodes,
                                                          float* __restrict__ out_edges) {
    const int t = threadIdx.x;
    if (blockIdx.x >= 625) {                 // finalize3 part: 500 blocks
        int idx = (int)(blockIdx.x - 625) * 256 + t;
        int e = idx >> 6, d = idx & 63;
        float v = fmaxf(g_acc2[idx] / g_csum[e], 0.f);
        out_edges[idx] = v * (gamma[d] * rsqrtf(1.f + 1e-5f)) + beta[d];
        g_acc2[idx] = 0.f;
        __syncthreads();                     // all csum reads in this block done
        if (d == 0) g_csum[e] = 0.f;
        return;
    }
    __shared__ float w1s[64 * 64];
    __shared__ float b1s[64], w2s[64], gs[64], bs[64];
#pragma unroll
    for (int i = 0; i < 16; i++) w1s[t + 256 * i] = w1[t + 256 * i];
    if (t < 64) {
        b1s[t] = b1[t]; w2s[t] = w2[t];
        gs[t] = gamma[t] * rsqrtf(1.f + 1e-5f); bs[t] = beta[t];
    }
    __syncthreads();
    const int warp = t >> 5, lane = t & 31;
    const int nbase = blockIdx.x * 32 + warp * 4;
    for (int it = 0; it < 4; it++) {
        int n = nbase + it;
        if (n >= NN) break;
        int off = n * 64;
        float f0 = fe_old[off + lane], f1 = fe_old[off + lane + 32];
        float nb0 = fmaf(g_node[off + lane],      gs[lane],      bs[lane]);
        float nb1 = fmaf(g_node[off + lane + 32], gs[lane + 32], bs[lane + 32]);
        float ha0 = b1s[lane], ha1 = b1s[lane + 32];
        float hb0 = ha0, hb1 = ha1;
#pragma unroll
        for (int k = 0; k < 64; k++) {
            float fk = __shfl_sync(0xffffffffu, (k < 32) ? f0 : f1, k & 31);
            float nk = __shfl_sync(0xffffffffu, (k < 32) ? nb0 : nb1, k & 31);
            float wa = w1s[k * 64 + lane], wb = w1s[k * 64 + lane + 32];
            ha0 = fmaf(fk, wa, ha0); ha1 = fmaf(fk, wb, ha1);
            hb0 = fmaf(nk, wa, hb0); hb1 = fmaf(nk, wb, hb1);
        }
        ha0 = tanhf(ha0); ha1 = tanhf(ha1);
        hb0 = tanhf(hb0); hb1 = tanhf(hb1);
        float pa = ha0 * w2s[lane] + ha1 * w2s[lane + 32];
        float pb = hb0 * w2s[lane] + hb1 * w2s[lane + 32];
#pragma unroll
        for (int o = 16; o > 0; o >>= 1) {
            pa += __shfl_down_sync(0xffffffffu, pa, o);
            pb += __shfl_down_sync(0xffffffffu, pb, o);
        }
        pa = __shfl_sync(0xffffffffu, pa, 0);
        pb = __shfl_sync(0xffffffffu, pb, 0);
        float s0 = 1.f / (1.f + expf(pb - pa));
        out_nodes[off + lane]      = s0 * f0 + (1.f - s0) * nb0;
        out_nodes[off + lane + 32] = s0 * f1 + (1.f - s0) * nb1;
    }
}

// ---------------- launch ----------------
#define SM_ET ((32*136 + 32*72*2) * 4)              // 35840
#define SM_N  ((64*36 + 32*72*2) * 4 + 256)         // 27904

extern "C" void kernel_launch(void* const* d_in, const int* in_sizes, int n_in,
                              void* d_out, int out_size) {
    const float* fe    = (const float*)d_in[0];
    const float* adj   = (const float*)d_in[1];
    const float* W2    = (const float*)d_in[2];
    const float* W3    = (const float*)d_in[3];
    const float* gamma = (const float*)d_in[4];
    const float* beta  = (const float*)d_in[5];
    const float* fw1   = (const float*)d_in[6];
    const float* fb1   = (const float*)d_in[7];
    const float* fw2   = (const float*)d_in[8];
    float* out = (float*)d_out;

    cudaFuncSetAttribute((const void*)gemm_et<1>, cudaFuncAttributeMaxDynamicSharedMemorySize, SM_ET);
    cudaFuncSetAttribute((const void*)gemm_et<3>, cudaFuncAttributeMaxDynamicSharedMemorySize, SM_ET);
    cudaFuncSetAttribute((const void*)gemm_n,     cudaFuncAttributeMaxDynamicSharedMemorySize, SM_N);

    const float* fe_cur = fe;
    for (int s = 0; s < NS; s++) {
        const float* A   = adj + (size_t)s * NN * NE;
        float* out_nodes = out + (size_t)s * (NN + NE) * 64;
        float* out_edges = out_nodes + (size_t)NN * 64;

        gemm_x_kernel<<<313, 256>>>(fe_cur, W2);
        gemm_et<1><<<dim3(16, 18), 256, SM_ET>>>(A);   // exp once + cache g_Ph + edge_pre + csum
        finalize1_kernel<<<125, 256>>>(W3);            // edge -> yT; zeros g_acc
        gemm_n<<<313, 256, SM_N>>>();                  // node + nT (reads g_Ph)
        gemm_et<3><<<dim3(16, 18), 256, SM_ET>>>(A);   // edge2_pre (reads g_Ph)
        fusion_fin3_kernel<<<1125, 256>>>(fe_cur, gamma, beta, fw1, fb1, fw2,
                                          out_nodes, out_edges);   // zeros acc2/csum

        fe_cur = out_nodes;
    }
}

// round 12
// speedup vs baseline: 2.2915x; 1.5848x over previous
#include <cuda_runtime.h>
#include <math.h>

#define NN 20000
#define NE 2000
#define NS 3
#define EPAD 2048
#define NPAIR 10016          // n-pairs (20032/2)

typedef unsigned int u32;

// ---------------- scratch (__device__ globals; zero-init, self-cleaning) ---------
__device__ __align__(16) u32 g_Ph[(size_t)NPAIR * EPAD]; // bf16-hi pairs of exp(adj): [npair][e]
__device__ __align__(16) u32 g_xTh[NPAIR * 64], g_xTl[NPAIR * 64];  // (fe@W2)^T [npair][d]
__device__ __align__(16) u32 g_yTh[1024 * 64],  g_yTl[1024 * 64];   // (edge@W3)^T [epair][d]
__device__ __align__(16) u32 g_nTh[NPAIR * 64], g_nTl[NPAIR * 64];  // node^T [npair][d]
__device__ __align__(16) float g_acc [NE * 64];       // zeroed by finalize1
__device__ __align__(16) float g_acc2[NE * 64];       // zeroed by fusion_fin3
__device__ float g_csum[NE];                          // zeroed by fusion_fin3
__device__ __align__(16) float g_node[NN * 64];

// ---------------- helpers ----------------
__device__ __forceinline__ u32 smem_u32(const void* p) {
    u32 a; asm("{ .reg .u64 t; cvta.to.shared.u64 t, %1; cvt.u32.u64 %0, t; }" : "=r"(a) : "l"(p));
    return a;
}
__device__ __forceinline__ u32 bf16hi(float v) {      // RNE bf16, bits in top half
    u32 u = __float_as_uint(v);
    return (u + 0x7FFFu + ((u >> 16) & 1u)) & 0xFFFF0000u;
}
__device__ __forceinline__ void pack2(float v0, float v1, u32& h, u32& l) {
    u32 h0 = bf16hi(v0), h1 = bf16hi(v1);
    h = (h0 >> 16) | h1;
    u32 l0 = bf16hi(v0 - __uint_as_float(h0));
    u32 l1 = bf16hi(v1 - __uint_as_float(h1));
    l = (l0 >> 16) | l1;
}
__device__ __forceinline__ u32 packhi2(float v0, float v1) {
    return (bf16hi(v0) >> 16) | bf16hi(v1);
}
__device__ __forceinline__ void MMA(float* c, const u32* a, const u32* b) {
    asm volatile("mma.sync.aligned.m16n8k16.row.col.f32.bf16.bf16.f32 "
        "{%0,%1,%2,%3}, {%4,%5,%6,%7}, {%8,%9}, {%0,%1,%2,%3};"
        : "+f"(c[0]), "+f"(c[1]), "+f"(c[2]), "+f"(c[3])
        : "r"(a[0]), "r"(a[1]), "r"(a[2]), "r"(a[3]), "r"(b[0]), "r"(b[1]));
}
__device__ __forceinline__ void red2(float* p, float a, float b) {
    asm volatile("red.global.add.v2.f32 [%0], {%1,%2};" :: "l"(p), "f"(a), "f"(b) : "memory");
}
__device__ __forceinline__ void cpa16(u32 dst, const void* src, u32 sz) {
    asm volatile("cp.async.cg.shared.global [%0], [%1], 16, %2;"
                 :: "r"(dst), "l"(src), "r"(sz) : "memory");
}
#define CPA_COMMIT() asm volatile("cp.async.commit_group;" ::: "memory")
#define CPA_WAIT1()  asm volatile("cp.async.wait_group 1;" ::: "memory")

// ---------------- gemm_x: x = fe @ W2, writes xT [npair][d] hi/lo ----------------
__global__ __launch_bounds__(256) void gemm_x_kernel(const float* __restrict__ Fe,
                                                     const float* __restrict__ W2) {
    __shared__ __align__(16) float Fs[64][64];
    __shared__ __align__(16) float Ws[64][64];
    const int t  = threadIdx.x;
    const int n0 = blockIdx.x * 64;
    const int tx = t & 15, ty = t >> 4;
#pragma unroll
    for (int i = 0; i < 16; i++) {
        int idx = t + 256 * i;
        int r = idx >> 6, c = idx & 63;
        int n = n0 + r;
        Fs[r][c] = (n < NN) ? Fe[n * 64 + c] : 0.f;
        Ws[r][c] = W2[idx];
    }
    __syncthreads();
    float a[4][4];
#pragma unroll
    for (int i = 0; i < 4; i++)
#pragma unroll
        for (int j = 0; j < 4; j++) a[i][j] = 0.f;
#pragma unroll
    for (int k = 0; k < 64; k++) {
        float fv[4];
#pragma unroll
        for (int i = 0; i < 4; i++) fv[i] = Fs[ty * 4 + i][k];
        float4 w4 = *(const float4*)&Ws[k][tx * 4];
        float wv[4] = {w4.x, w4.y, w4.z, w4.w};
#pragma unroll
        for (int i = 0; i < 4; i++)
#pragma unroll
            for (int j = 0; j < 4; j++) a[i][j] = fmaf(fv[i], wv[j], a[i][j]);
    }
#pragma unroll
    for (int ip = 0; ip < 2; ip++)
#pragma unroll
        for (int j = 0; j < 4; j++) {
            u32 h, l; pack2(a[2 * ip][j], a[2 * ip + 1][j], h, l);
            int idx = ((n0 >> 1) + ty * 2 + ip) * 64 + tx * 4 + j;
            g_xTh[idx] = h;
            g_xTl[idx] = l;
        }
}

// ---------------- GEMM1/3: acc[e,d] += sum_n exp(adj[n,e]) * B[n,d] ----------------
// Pipelined: cp.async double-buffered A source. MODE 1: raw adj staged, exp+pack in
// smem, cache g_Ph; B=xT; ones column -> csum. MODE 3: g_Ph cp.async'd straight into
// packed layout; B=nT.
template <int MODE>
__global__ __launch_bounds__(256, 2) void gemm_et(const float* __restrict__ A) {
    extern __shared__ __align__(16) char sm[];
    // MODE1: raw[2][64][128]f32 @0 (65536) | Ah[32][136] @65536 | B @82944
    // MODE3: Ah[2][32][136] @0 (34816)     | B @34816
    float* raw = (float*)sm;
    u32* Ah = (MODE == 1) ? (u32*)(sm + 65536) : (u32*)sm;
    u32* Bh = (MODE == 1) ? (u32*)(sm + 65536 + 17408) : (u32*)(sm + 34816);
    u32* Bl = Bh + 32 * 72;
    const u32 smb = smem_u32(sm);
    const int t = threadIdx.x, w = t >> 5, lane = t & 31;
    const int g = lane >> 2, tg = lane & 3;
    const int e0 = blockIdx.x * 128;
    const int sp = blockIdx.y;
    const int c0  = sp * 17 + (sp < 7 ? sp : 7);
    const int nch = 17 + (sp < 7 ? 1 : 0);
    const int wm = w >> 1, wn = w & 1;
    const int rowb = wm * 32;
    const int e_l = t & 127, half = t >> 7;
    const u32* __restrict__ BTh = (MODE == 1) ? g_xTh : g_nTh;
    const u32* __restrict__ BTl = (MODE == 1) ? g_xTl : g_nTl;
    const bool e_ok = (e0 + e_l) < NE;

    float c[2][4][4];
    float ce[2][4];
#pragma unroll
    for (int mt = 0; mt < 2; mt++) {
#pragma unroll
        for (int nt = 0; nt < 4; nt++)
#pragma unroll
            for (int q = 0; q < 4; q++) c[mt][nt][q] = 0.f;
#pragma unroll
        for (int q = 0; q < 4; q++) ce[mt][q] = 0.f;
    }

    // ---- prefetch lambda-equivalents (unrolled inline) ----
    // MODE1: stage = 32768B of raw floats; MODE3: stage = 17408B packed u32
#define ET_PREFETCH(cj, ss) do {                                                   \
    if (MODE == 1) {                                                               \
        int n0j = (c0 + (cj)) * 64;                                                \
        _Pragma("unroll")                                                          \
        for (int j = 0; j < 8; j++) {                                              \
            int idx = t + 256 * j;                                                 \
            int row = idx >> 5, seg = idx & 31;                                    \
            int n = n0j + row;                                                     \
            u32 sz = (n < NN && (e0 + seg * 4) < NE) ? 16u : 0u;                   \
            cpa16(smb + (ss) * 32768u + (u32)(row * 128 + seg * 4) * 4u,           \
                  A + (size_t)n * NE + e0 + seg * 4, sz);                          \
        }                                                                          \
    } else {                                                                       \
        int np0j = ((c0 + (cj)) * 64) >> 1;                                        \
        _Pragma("unroll")                                                          \
        for (int j = 0; j < 4; j++) {                                              \
            int idx = t + 256 * j;                                                 \
            int row = idx >> 5, seg = idx & 31;                                    \
            cpa16(smb + (ss) * 17408u + (u32)(row * 136 + seg * 4) * 4u,           \
                  g_Ph + (size_t)(np0j + row) * EPAD + e0 + seg * 4, 16u);         \
        }                                                                          \
    }                                                                              \
} while (0)

    ET_PREFETCH(0, 0);
    CPA_COMMIT();

    for (int ci = 0; ci < nch; ci++) {
        const int s = ci & 1;
        const int n0  = (c0 + ci) * 64;
        const int np0 = n0 >> 1;
        if (ci + 1 < nch) ET_PREFETCH(ci + 1, s ^ 1);
        CPA_COMMIT();
        CPA_WAIT1();
        __syncthreads();
        // ---- fill B tile [32 kpair][64 d] + ones col (single buffer, L2 source) ----
        {
            int d = t & 63;
#pragma unroll
            for (int i = 0; i < 8; i++) {
                int r = (t >> 6) + 4 * i;
                Bh[r * 72 + d] = BTh[(np0 + r) * 64 + d];
                Bl[r * 72 + d] = BTl[(np0 + r) * 64 + d];
            }
            int r = t >> 3, cc = 64 + (t & 7);
            Bh[r * 72 + cc] = (MODE == 1 && cc == 64) ? 0x3F803F80u : 0u;
            Bl[r * 72 + cc] = 0u;
        }
        // ---- MODE1: exp + pack from staged raw -> packed A + g_Ph cache ----
        if (MODE == 1) {
            const float* rw = raw + s * 8192;
#pragma unroll
            for (int i = 0; i < 16; i++) {
                int p_l = 2 * i + half;
                int n = n0 + 2 * p_l;
                float v0 = (e_ok && n < NN)     ? __expf(rw[(2 * p_l) * 128 + e_l])     : 0.f;
                float v1 = (e_ok && n + 1 < NN) ? __expf(rw[(2 * p_l + 1) * 128 + e_l]) : 0.f;
                u32 h = packhi2(v0, v1);
                Ah[p_l * 136 + e_l] = h;
                g_Ph[(size_t)(np0 + p_l) * EPAD + e0 + e_l] = h;
            }
        }
        __syncthreads();
        // ---- mma (identical fragment mapping to R10) ----
        const u32* Ap = (MODE == 1) ? Ah : Ah + s * (32 * 136);
#pragma unroll
        for (int kt = 0; kt < 4; kt++) {
            int kp = kt * 8;
            u32 ah[2][4];
#pragma unroll
            for (int mt = 0; mt < 2; mt++) {
                int rb = rowb + mt * 16;
                ah[mt][0] = Ap[(kp + tg) * 136 + rb + g];
                ah[mt][1] = Ap[(kp + tg) * 136 + rb + g + 8];
                ah[mt][2] = Ap[(kp + tg + 4) * 136 + rb + g];
                ah[mt][3] = Ap[(kp + tg + 4) * 136 + rb + g + 8];
            }
#pragma unroll
            for (int nt = 0; nt < 4; nt++) {
                int cb = wn * 32 + nt * 8;
                u32 bh[2] = { Bh[(kp + tg) * 72 + cb + g], Bh[(kp + tg + 4) * 72 + cb + g] };
                u32 bl[2] = { Bl[(kp + tg) * 72 + cb + g], Bl[(kp + tg + 4) * 72 + cb + g] };
#pragma unroll
                for (int mt = 0; mt < 2; mt++) {
                    MMA(c[mt][nt], ah[mt], bh);
                    MMA(c[mt][nt], ah[mt], bl);
                }
            }
            if (MODE == 1 && wn == 1) {
                u32 be[2] = { Bh[(kp + tg) * 72 + 64 + g], Bh[(kp + tg + 4) * 72 + 64 + g] };
#pragma unroll
                for (int mt = 0; mt < 2; mt++) MMA(ce[mt], ah[mt], be);
            }
        }
        __syncthreads();   // close MMA before next prefetch overwrites stage s^1 / B refill
    }
#undef ET_PREFETCH
    // ---- epilogue: split-K reduce ----
    float* acc = (MODE == 1) ? g_acc : g_acc2;
#pragma unroll
    for (int mt = 0; mt < 2; mt++)
#pragma unroll
        for (int nt = 0; nt < 4; nt++) {
            int row = e0 + rowb + mt * 16 + g;
            int col = wn * 32 + nt * 8 + 2 * tg;
            if (row < NE)     red2(&acc[row * 64 + col],       c[mt][nt][0], c[mt][nt][1]);
            if (row + 8 < NE) red2(&acc[(row + 8) * 64 + col], c[mt][nt][2], c[mt][nt][3]);
        }
    if (MODE == 1 && wn == 1 && tg == 0) {
#pragma unroll
        for (int mt = 0; mt < 2; mt++) {
            int row = e0 + rowb + mt * 16 + g;
            if (row < NE)     atomicAdd(&g_csum[row],     ce[mt][0]);
            if (row + 8 < NE) atomicAdd(&g_csum[row + 8], ce[mt][2]);
        }
    }
}

// ---------------- finalize1: edge = relu(acc/csum); y = edge@W3 -> yT; zero acc --
__global__ __launch_bounds__(256) void finalize1_kernel(const float* __restrict__ W3) {
    __shared__ __align__(16) float EsT[64][17];
    __shared__ __align__(16) float Ws[64][64];
    __shared__ __align__(16) float Ys[16][64];
    const int t  = threadIdx.x;
    const int e0 = blockIdx.x * 16;      // 125 blocks * 16 = 2000
#pragma unroll
    for (int i = 0; i < 16; i++) {
        int idx = t + 256 * i;
        Ws[idx >> 6][idx & 63] = W3[idx];
    }
#pragma unroll
    for (int i = 0; i < 4; i++) {
        int idx = t + 256 * i;
        int r = idx >> 6, c = idx & 63;
        int ge = e0 + r;
        EsT[c][r] = fmaxf(g_acc[ge * 64 + c] / g_csum[ge], 0.f);
        g_acc[ge * 64 + c] = 0.f;        // self-clean
    }
    __syncthreads();
    const int ty = t >> 4, tx = t & 15;
    float a0 = 0.f, a1 = 0.f, a2 = 0.f, a3 = 0.f;
#pragma unroll
    for (int k = 0; k < 64; k++) {
        float ev = EsT[k][ty];
        float4 w4 = *(const float4*)&Ws[k][tx * 4];
        a0 = fmaf(ev, w4.x, a0); a1 = fmaf(ev, w4.y, a1);
        a2 = fmaf(ev, w4.z, a2); a3 = fmaf(ev, w4.w, a3);
    }
    float4 r4 = {a0, a1, a2, a3};
    *(float4*)&Ys[ty][tx * 4] = r4;
    __syncthreads();
#pragma unroll
    for (int i = 0; i < 2; i++) {
        int idx = t + 256 * i;
        int pp = idx >> 6, d = idx & 63;
        u32 h, l; pack2(Ys[2 * pp][d], Ys[2 * pp + 1][d], h, l);
        int gp = (e0 >> 1) + pp;
        g_yTh[gp * 64 + d] = h;
        g_yTl[gp * 64 + d] = l;
    }
}

// ---------------- GEMM2: node = relu((exp(adj)@y)/rsum); pipelined g_Ph stages ----
__global__ __launch_bounds__(256, 3) void gemm_n() {
    extern __shared__ __align__(16) char sm[];
    u32* raw = (u32*)sm;                       // [2][32][64] = 16384B
    u32* A2h = (u32*)(sm + 16384);             // [64][36]    = 9216B
    u32* Bh  = (u32*)(sm + 16384 + 9216);      // [32][72]
    u32* Bl  = Bh + 32 * 72;                   // [32][72]  (ends @44032)
    float* rsum   = (float*)(sm + 44032);      // [64]
    float* bounce = (float*)sm;                // [64][68] overlay after mma done
    const u32 smb = smem_u32(sm);
    const int t = threadIdx.x, w = t >> 5, lane = t & 31;
    const int g = lane >> 2, tg = lane & 3;
    const int p0 = blockIdx.x * 32;
    const int n0 = p0 * 2;
    const int wm = w >> 1, wn = w & 1;
    const int rowb = wm * 16;

    float c[4][4];
    float ce[4];
#pragma unroll
    for (int nt = 0; nt < 4; nt++)
#pragma unroll
        for (int q = 0; q < 4; q++) c[nt][q] = 0.f;
#pragma unroll
    for (int q = 0; q < 4; q++) ce[q] = 0.f;

#define N_PREFETCH(cj, ss) do {                                                    \
    _Pragma("unroll")                                                              \
    for (int j = 0; j < 2; j++) {                                                  \
        int idx = t + 256 * j;                                                     \
        int row = idx >> 4, seg = idx & 15;                                        \
        cpa16(smb + (ss) * 8192u + (u32)(row * 64 + seg * 4) * 4u,                 \
              g_Ph + (size_t)(p0 + row) * EPAD + (cj) * 64 + seg * 4, 16u);        \
    }                                                                              \
} while (0)

    N_PREFETCH(0, 0);
    CPA_COMMIT();

    for (int ech = 0; ech < 32; ech++) {
        const int s = ech & 1;
        const int ep0 = ech * 32;
        if (ech + 1 < 32) N_PREFETCH(ech + 1, s ^ 1);
        CPA_COMMIT();
        CPA_WAIT1();
        __syncthreads();
        // ---- fill B [32 epair][64 d] + ones col ----
        {
            int d = t & 63;
#pragma unroll
            for (int i = 0; i < 8; i++) {
                int r = (t >> 6) + 4 * i;
                Bh[r * 72 + d] = g_yTh[(ep0 + r) * 64 + d];
                Bl[r * 72 + d] = g_yTl[(ep0 + r) * 64 + d];
            }
            int r = t >> 3, cc = 64 + (t & 7);
            Bh[r * 72 + cc] = (cc == 64) ? 0x3F803F80u : 0u;
            Bl[r * 72 + cc] = 0u;
        }
        // ---- prmt repack staged g_Ph -> A2h [64 n][32 epair] ----
#pragma unroll
        for (int i = 0; i < 4; i++) {
            int pl = w + 8 * i;
            uint2 vh = *(const uint2*)&raw[s * 2048 + pl * 64 + 2 * lane];
            A2h[(2 * pl) * 36 + lane]     = __byte_perm(vh.x, vh.y, 0x5410);
            A2h[(2 * pl + 1) * 36 + lane] = __byte_perm(vh.x, vh.y, 0x7632);
        }
        __syncthreads();
#pragma unroll
        for (int kt = 0; kt < 4; kt++) {
            int kp = kt * 8;
            u32 ah[4] = { A2h[(rowb + g) * 36 + kp + tg],     A2h[(rowb + g + 8) * 36 + kp + tg],
                          A2h[(rowb + g) * 36 + kp + tg + 4], A2h[(rowb + g + 8) * 36 + kp + tg + 4] };
#pragma unroll
            for (int nt = 0; nt < 4; nt++) {
                int cb = wn * 32 + nt * 8;
                u32 bh[2] = { Bh[(kp + tg) * 72 + cb + g], Bh[(kp + tg + 4) * 72 + cb + g] };
                u32 bl[2] = { Bl[(kp + tg) * 72 + cb + g], Bl[(kp + tg + 4) * 72 + cb + g] };
                MMA(c[nt], ah, bh);
                MMA(c[nt], ah, bl);
            }
            if (wn == 1) {
                u32 be[2] = { Bh[(kp + tg) * 72 + 64 + g], Bh[(kp + tg + 4) * 72 + 64 + g] };
                MMA(ce, ah, be);
            }
        }
        __syncthreads();   // close MMA before next prefetch/B refill
    }
#undef N_PREFETCH
    // ---- rsum from ones column ----
    if (wn == 1 && tg == 0) {
        rsum[rowb + g]     = ce[0];
        rsum[rowb + g + 8] = ce[2];
    }
    __syncthreads();
    float s0 = rsum[rowb + g],     ri0 = (s0 > 0.f) ? 1.f / s0 : 0.f;
    float s1 = rsum[rowb + g + 8], ri1 = (s1 > 0.f) ? 1.f / s1 : 0.f;
#pragma unroll
    for (int nt = 0; nt < 4; nt++) {
        int col = wn * 32 + nt * 8 + 2 * tg;
        bounce[(rowb + g) * 68 + col]         = fmaxf(c[nt][0], 0.f) * ri0;
        bounce[(rowb + g) * 68 + col + 1]     = fmaxf(c[nt][1], 0.f) * ri0;
        bounce[(rowb + g + 8) * 68 + col]     = fmaxf(c[nt][2], 0.f) * ri1;
        bounce[(rowb + g + 8) * 68 + col + 1] = fmaxf(c[nt][3], 0.f) * ri1;
    }
    __syncthreads();
#pragma unroll
    for (int i = 0; i < 4; i++) {            // g_node fp32 coalesced
        int idx = t + 256 * i;
        int r = idx >> 4, q = idx & 15;
        if (n0 + r < NN)
            *(float4*)&g_node[(n0 + r) * 64 + q * 4] = *(const float4*)&bounce[r * 68 + q * 4];
    }
#pragma unroll
    for (int i = 0; i < 8; i++) {            // nT [npair][d] hi/lo
        int idx = t + 256 * i;
        int d = idx & 63, pp = idx >> 6;
        u32 h, l;
        pack2(bounce[(2 * pp) * 68 + d], bounce[(2 * pp + 1) * 68 + d], h, l);
        g_nTh[(p0 + pp) * 64 + d] = h;
        g_nTl[(p0 + pp) * 64 + d] = l;
    }
}

// ---------------- fusion + finalize3 merged; zeros acc2/csum ----------------
__global__ __launch_bounds__(256) void fusion_fin3_kernel(const float* __restrict__ fe_old,
                                                          const float* __restrict__ gamma,
                                                          const float* __restrict__ beta,
                                                          const float* __restrict__ w1,
                                                          const float* __restrict__ b1,
                                                          const float* __restrict__ w2,
                                                          float* __restrict__ out_nodes,
                                                          float* __restrict__ out_edges) {
    const int t = threadIdx.x;
    if (blockIdx.x >= 625) {                 // finalize3 part: 500 blocks
        int idx = (int)(blockIdx.x - 625) * 256 + t;
        int e = idx >> 6, d = idx & 63;
        float v = fmaxf(g_acc2[idx] / g_csum[e], 0.f);
        out_edges[idx] = v * (gamma[d] * rsqrtf(1.f + 1e-5f)) + beta[d];
        g_acc2[idx] = 0.f;
        __syncthreads();                     // all csum reads in this block done
        if (d == 0) g_csum[e] = 0.f;
        return;
    }
    __shared__ float w1s[64 * 64];
    __shared__ float b1s[64], w2s[64], gs[64], bs[64];
#pragma unroll
    for (int i = 0; i < 16; i++) w1s[t + 256 * i] = w1[t + 256 * i];
    if (t < 64) {
        b1s[t] = b1[t]; w2s[t] = w2[t];
        gs[t] = gamma[t] * rsqrtf(1.f + 1e-5f); bs[t] = beta[t];
    }
    __syncthreads();
    const int warp = t >> 5, lane = t & 31;
    const int nbase = blockIdx.x * 32 + warp * 4;
    for (int it = 0; it < 4; it++) {
        int n = nbase + it;
        if (n >= NN) break;
        int off = n * 64;
        float f0 = fe_old[off + lane], f1 = fe_old[off + lane + 32];
        float nb0 = fmaf(g_node[off + lane],      gs[lane],      bs[lane]);
        float nb1 = fmaf(g_node[off + lane + 32], gs[lane + 32], bs[lane + 32]);
        float ha0 = b1s[lane], ha1 = b1s[lane + 32];
        float hb0 = ha0, hb1 = ha1;
#pragma unroll
        for (int k = 0; k < 64; k++) {
            float fk = __shfl_sync(0xffffffffu, (k < 32) ? f0 : f1, k & 31);
            float nk = __shfl_sync(0xffffffffu, (k < 32) ? nb0 : nb1, k & 31);
            float wa = w1s[k * 64 + lane], wb = w1s[k * 64 + lane + 32];
            ha0 = fmaf(fk, wa, ha0); ha1 = fmaf(fk, wb, ha1);
            hb0 = fmaf(nk, wa, hb0); hb1 = fmaf(nk, wb, hb1);
        }
        ha0 = tanhf(ha0); ha1 = tanhf(ha1);
        hb0 = tanhf(hb0); hb1 = tanhf(hb1);
        float pa = ha0 * w2s[lane] + ha1 * w2s[lane + 32];
        float pb = hb0 * w2s[lane] + hb1 * w2s[lane + 32];
#pragma unroll
        for (int o = 16; o > 0; o >>= 1) {
            pa += __shfl_down_sync(0xffffffffu, pa, o);
            pb += __shfl_down_sync(0xffffffffu, pb, o);
        }
        pa = __shfl_sync(0xffffffffu, pa, 0);
        pb = __shfl_sync(0xffffffffu, pb, 0);
        float s0 = 1.f / (1.f + expf(pb - pa));
        out_nodes[off + lane]      = s0 * f0 + (1.f - s0) * nb0;
        out_nodes[off + lane + 32] = s0 * f1 + (1.f - s0) * nb1;
    }
}

// ---------------- launch ----------------
#define SM_ET1 (65536 + 17408 + 18432)   // 101376: raw x2 + packedA + B
#define SM_ET3 (34816 + 18432)           // 53248 : packedA x2 + B
#define SM_N   (16384 + 9216 + 18432 + 256)  // 44288

extern "C" void kernel_launch(void* const* d_in, const int* in_sizes, int n_in,
                              void* d_out, int out_size) {
    const float* fe    = (const float*)d_in[0];
    const float* adj   = (const float*)d_in[1];
    const float* W2    = (const float*)d_in[2];
    const float* W3    = (const float*)d_in[3];
    const float* gamma = (const float*)d_in[4];
    const float* beta  = (const float*)d_in[5];
    const float* fw1   = (const float*)d_in[6];
    const float* fb1   = (const float*)d_in[7];
    const float* fw2   = (const float*)d_in[8];
    float* out = (float*)d_out;

    cudaFuncSetAttribute((const void*)gemm_et<1>, cudaFuncAttributeMaxDynamicSharedMemorySize, SM_ET1);
    cudaFuncSetAttribute((const void*)gemm_et<3>, cudaFuncAttributeMaxDynamicSharedMemorySize, SM_ET3);
    cudaFuncSetAttribute((const void*)gemm_n,     cudaFuncAttributeMaxDynamicSharedMemorySize, SM_N);

    const float* fe_cur = fe;
    for (int s = 0; s < NS; s++) {
        const float* A   = adj + (size_t)s * NN * NE;
        float* out_nodes = out + (size_t)s * (NN + NE) * 64;
        float* out_edges = out_nodes + (size_t)NN * 64;

        gemm_x_kernel<<<313, 256>>>(fe_cur, W2);
        gemm_et<1><<<dim3(16, 18), 256, SM_ET1>>>(A);  // exp once + cache g_Ph + edge_pre + csum
        finalize1_kernel<<<125, 256>>>(W3);            // edge -> yT; zeros g_acc
        gemm_n<<<313, 256, SM_N>>>();                  // node + nT (reads g_Ph, pipelined)
        gemm_et<3><<<dim3(16, 18), 256, SM_ET3>>>(A);  // edge2_pre (reads g_Ph, pipelined)
        fusion_fin3_kernel<<<1125, 256>>>(fe_cur, gamma, beta, fw1, fb1, fw2,
                                          out_nodes, out_edges);   // zeros acc2/csum

        fe_cur = out_nodes;
    }
}

// round 13
// speedup vs baseline: 2.4756x; 1.0804x over previous
#include <cuda_runtime.h>
#include <math.h>

#define NN 20000
#define NE 2000
#define NS 3
#define EPAD 2048
#define NPAIR 10016          // n-pairs (20032/2)

typedef unsigned int u32;

// ---------------- scratch (__device__ globals; zero-init, self-cleaning) ---------
__device__ __align__(16) u32 g_Ph[(size_t)NPAIR * EPAD]; // bf16-hi pairs of exp(adj): [npair][e]
__device__ __align__(16) u32 g_xTh[NPAIR * 64], g_xTl[NPAIR * 64];  // (fe@W2)^T [npair][d]
__device__ __align__(16) u32 g_yTh[1024 * 64],  g_yTl[1024 * 64];   // (edge@W3)^T [epair][d]
__device__ __align__(16) u32 g_nTh[NPAIR * 64], g_nTl[NPAIR * 64];  // node^T [npair][d]
__device__ __align__(16) float g_acc [NE * 64];       // zeroed by finalize1
__device__ __align__(16) float g_acc2[NE * 64];       // zeroed by fusion_fin3
__device__ float g_csum[NE];                          // zeroed by fusion_fin3
__device__ __align__(16) float g_node[NN * 64];

// ---------------- helpers ----------------
__device__ __forceinline__ u32 smem_u32(const void* p) {
    u32 a; asm("{ .reg .u64 t; cvta.to.shared.u64 t, %1; cvt.u32.u64 %0, t; }" : "=r"(a) : "l"(p));
    return a;
}
__device__ __forceinline__ u32 bf16hi(float v) {      // RNE bf16, bits in top half
    u32 u = __float_as_uint(v);
    return (u + 0x7FFFu + ((u >> 16) & 1u)) & 0xFFFF0000u;
}
__device__ __forceinline__ void pack2(float v0, float v1, u32& h, u32& l) {
    u32 h0 = bf16hi(v0), h1 = bf16hi(v1);
    h = (h0 >> 16) | h1;
    u32 l0 = bf16hi(v0 - __uint_as_float(h0));
    u32 l1 = bf16hi(v1 - __uint_as_float(h1));
    l = (l0 >> 16) | l1;
}
__device__ __forceinline__ u32 packhi2(float v0, float v1) {
    return (bf16hi(v0) >> 16) | bf16hi(v1);
}
__device__ __forceinline__ void MMA(float* c, const u32* a, const u32* b) {
    asm volatile("mma.sync.aligned.m16n8k16.row.col.f32.bf16.bf16.f32 "
        "{%0,%1,%2,%3}, {%4,%5,%6,%7}, {%8,%9}, {%0,%1,%2,%3};"
        : "+f"(c[0]), "+f"(c[1]), "+f"(c[2]), "+f"(c[3])
        : "r"(a[0]), "r"(a[1]), "r"(a[2]), "r"(a[3]), "r"(b[0]), "r"(b[1]));
}
__device__ __forceinline__ void red2(float* p, float a, float b) {
    asm volatile("red.global.add.v2.f32 [%0], {%1,%2};" :: "l"(p), "f"(a), "f"(b) : "memory");
}
__device__ __forceinline__ void cpa16(u32 dst, const void* src, u32 sz) {
    asm volatile("cp.async.cg.shared.global [%0], [%1], 16, %2;"
                 :: "r"(dst), "l"(src), "r"(sz) : "memory");
}
#define CPA_COMMIT() asm volatile("cp.async.commit_group;" ::: "memory")
#define CPA_WAIT1()  asm volatile("cp.async.wait_group 1;" ::: "memory")
#define CPA_WAIT2()  asm volatile("cp.async.wait_group 2;" ::: "memory")
#define CPA_WAIT0()  asm volatile("cp.async.wait_group 0;" ::: "memory")

// ---------------- gemm_x: x = fe @ W2, writes xT [npair][d] hi/lo ----------------
__global__ __launch_bounds__(256) void gemm_x_kernel(const float* __restrict__ Fe,
                                                     const float* __restrict__ W2) {
    __shared__ __align__(16) float Fs[64][64];
    __shared__ __align__(16) float Ws[64][64];
    const int t  = threadIdx.x;
    const int n0 = blockIdx.x * 64;
    const int tx = t & 15, ty = t >> 4;
#pragma unroll
    for (int i = 0; i < 16; i++) {
        int idx = t + 256 * i;
        int r = idx >> 6, c = idx & 63;
        int n = n0 + r;
        Fs[r][c] = (n < NN) ? Fe[n * 64 + c] : 0.f;
        Ws[r][c] = W2[idx];
    }
    __syncthreads();
    float a[4][4];
#pragma unroll
    for (int i = 0; i < 4; i++)
#pragma unroll
        for (int j = 0; j < 4; j++) a[i][j] = 0.f;
#pragma unroll
    for (int k = 0; k < 64; k++) {
        float fv[4];
#pragma unroll
        for (int i = 0; i < 4; i++) fv[i] = Fs[ty * 4 + i][k];
        float4 w4 = *(const float4*)&Ws[k][tx * 4];
        float wv[4] = {w4.x, w4.y, w4.z, w4.w};
#pragma unroll
        for (int i = 0; i < 4; i++)
#pragma unroll
            for (int j = 0; j < 4; j++) a[i][j] = fmaf(fv[i], wv[j], a[i][j]);
    }
#pragma unroll
    for (int ip = 0; ip < 2; ip++)
#pragma unroll
        for (int j = 0; j < 4; j++) {
            u32 h, l; pack2(a[2 * ip][j], a[2 * ip + 1][j], h, l);
            int idx = ((n0 >> 1) + ty * 2 + ip) * 64 + tx * 4 + j;
            g_xTh[idx] = h;
            g_xTl[idx] = l;
        }
}

// ---------------- GEMM1: acc[e,d] += sum_n exp(adj[n,e]) * x[n,d] ----------------
// 2-stage cp.async raw adj; exp+pack in smem; caches g_Ph; B=xT sync; ones->csum.
__global__ __launch_bounds__(256, 2) void gemm_et1(const float* __restrict__ A) {
    extern __shared__ __align__(16) char sm[];
    // raw[2][64][128]f32 @0 (65536) | Ah[32][136] @65536 | B @82944
    float* raw = (float*)sm;
    u32* Ah = (u32*)(sm + 65536);
    u32* Bh = (u32*)(sm + 65536 + 17408);
    u32* Bl = Bh + 32 * 72;
    const u32 smb = smem_u32(sm);
    const int t = threadIdx.x, w = t >> 5, lane = t & 31;
    const int g = lane >> 2, tg = lane & 3;
    const int e0 = blockIdx.x * 128;
    const int sp = blockIdx.y;
    const int c0  = sp * 17 + (sp < 7 ? sp : 7);
    const int nch = 17 + (sp < 7 ? 1 : 0);
    const int wm = w >> 1, wn = w & 1;
    const int rowb = wm * 32;
    const int e_l = t & 127, half = t >> 7;
    const bool e_ok = (e0 + e_l) < NE;

    float c[2][4][4];
    float ce[2][4];
#pragma unroll
    for (int mt = 0; mt < 2; mt++) {
#pragma unroll
        for (int nt = 0; nt < 4; nt++)
#pragma unroll
            for (int q = 0; q < 4; q++) c[mt][nt][q] = 0.f;
#pragma unroll
        for (int q = 0; q < 4; q++) ce[mt][q] = 0.f;
    }

#define E1_PRE(cj, ss) do {                                                        \
    int n0j = (c0 + (cj)) * 64;                                                    \
    _Pragma("unroll")                                                              \
    for (int j = 0; j < 8; j++) {                                                  \
        int idx = t + 256 * j;                                                     \
        int row = idx >> 5, seg = idx & 31;                                        \
        int n = n0j + row;                                                         \
        u32 sz = (n < NN && (e0 + seg * 4) < NE) ? 16u : 0u;                       \
        cpa16(smb + (ss) * 32768u + (u32)(row * 128 + seg * 4) * 4u,               \
              A + (size_t)n * NE + e0 + seg * 4, sz);                              \
    }                                                                              \
} while (0)

    E1_PRE(0, 0);
    CPA_COMMIT();

    for (int ci = 0; ci < nch; ci++) {
        const int s = ci & 1;
        const int n0  = (c0 + ci) * 64;
        const int np0 = n0 >> 1;
        if (ci + 1 < nch) E1_PRE(ci + 1, s ^ 1);
        CPA_COMMIT();
        CPA_WAIT1();
        __syncthreads();
        // ---- fill B tile [32 kpair][64 d] + ones col (sync, L2 source) ----
        {
            int d = t & 63;
#pragma unroll
            for (int i = 0; i < 8; i++) {
                int r = (t >> 6) + 4 * i;
                Bh[r * 72 + d] = g_xTh[(np0 + r) * 64 + d];
                Bl[r * 72 + d] = g_xTl[(np0 + r) * 64 + d];
            }
            int r = t >> 3, cc = 64 + (t & 7);
            Bh[r * 72 + cc] = (cc == 64) ? 0x3F803F80u : 0u;
            Bl[r * 72 + cc] = 0u;
        }
        // ---- exp + pack from staged raw -> packed A + g_Ph cache ----
        {
            const float* rw = raw + s * 8192;
#pragma unroll
            for (int i = 0; i < 16; i++) {
                int p_l = 2 * i + half;
                int n = n0 + 2 * p_l;
                float v0 = (e_ok && n < NN)     ? __expf(rw[(2 * p_l) * 128 + e_l])     : 0.f;
                float v1 = (e_ok && n + 1 < NN) ? __expf(rw[(2 * p_l + 1) * 128 + e_l]) : 0.f;
                u32 h = packhi2(v0, v1);
                Ah[p_l * 136 + e_l] = h;
                g_Ph[(size_t)(np0 + p_l) * EPAD + e0 + e_l] = h;
            }
        }
        __syncthreads();
        // ---- mma ----
#pragma unroll
        for (int kt = 0; kt < 4; kt++) {
            int kp = kt * 8;
            u32 ah[2][4];
#pragma unroll
            for (int mt = 0; mt < 2; mt++) {
                int rb = rowb + mt * 16;
                ah[mt][0] = Ah[(kp + tg) * 136 + rb + g];
                ah[mt][1] = Ah[(kp + tg) * 136 + rb + g + 8];
                ah[mt][2] = Ah[(kp + tg + 4) * 136 + rb + g];
                ah[mt][3] = Ah[(kp + tg + 4) * 136 + rb + g + 8];
            }
#pragma unroll
            for (int nt = 0; nt < 4; nt++) {
                int cb = wn * 32 + nt * 8;
                u32 bh[2] = { Bh[(kp + tg) * 72 + cb + g], Bh[(kp + tg + 4) * 72 + cb + g] };
                u32 bl[2] = { Bl[(kp + tg) * 72 + cb + g], Bl[(kp + tg + 4) * 72 + cb + g] };
#pragma unroll
                for (int mt = 0; mt < 2; mt++) {
                    MMA(c[mt][nt], ah[mt], bh);
                    MMA(c[mt][nt], ah[mt], bl);
                }
            }
            if (wn == 1) {
                u32 be[2] = { Bh[(kp + tg) * 72 + 64 + g], Bh[(kp + tg + 4) * 72 + 64 + g] };
#pragma unroll
                for (int mt = 0; mt < 2; mt++) MMA(ce[mt], ah[mt], be);
            }
        }
        __syncthreads();   // close MMA before next prefetch/B refill
    }
#undef E1_PRE
#pragma unroll
    for (int mt = 0; mt < 2; mt++)
#pragma unroll
        for (int nt = 0; nt < 4; nt++) {
            int row = e0 + rowb + mt * 16 + g;
            int col = wn * 32 + nt * 8 + 2 * tg;
            if (row < NE)     red2(&g_acc[row * 64 + col],       c[mt][nt][0], c[mt][nt][1]);
            if (row + 8 < NE) red2(&g_acc[(row + 8) * 64 + col], c[mt][nt][2], c[mt][nt][3]);
        }
    if (wn == 1 && tg == 0) {
#pragma unroll
        for (int mt = 0; mt < 2; mt++) {
            int row = e0 + rowb + mt * 16 + g;
            if (row < NE)     atomicAdd(&g_csum[row],     ce[mt][0]);
            if (row + 8 < NE) atomicAdd(&g_csum[row + 8], ce[mt][2]);
        }
    }
}

// ---------------- GEMM3: acc2[e,d] += sum_n exp(adj[n,e]) * node[n,d] -------------
// 3-stage cp.async for BOTH packed A (g_Ph) and B (nT hi/lo). Pure wait->mma loop.
__global__ __launch_bounds__(256, 2) void gemm_et3() {
    extern __shared__ __align__(16) char sm[];
    // Ah[3][32*136] @0 (52224) | B[3][Bh 2304 | Bl 2304]u32 @52224 (55296) = 107520
    const u32 smb = smem_u32(sm);
    const int t = threadIdx.x, w = t >> 5, lane = t & 31;
    const int g = lane >> 2, tg = lane & 3;
    const int e0 = blockIdx.x * 128;
    const int sp = blockIdx.y;
    const int c0  = sp * 17 + (sp < 7 ? sp : 7);
    const int nch = 17 + (sp < 7 ? 1 : 0);
    const int wm = w >> 1, wn = w & 1;
    const int rowb = wm * 32;

    float c[2][4][4];
#pragma unroll
    for (int mt = 0; mt < 2; mt++)
#pragma unroll
        for (int nt = 0; nt < 4; nt++)
#pragma unroll
            for (int q = 0; q < 4; q++) c[mt][nt][q] = 0.f;

#define E3_PRE(cj, ss) do {                                                        \
    int np0j = (c0 + (cj)) * 32;                                                   \
    _Pragma("unroll")                                                              \
    for (int j = 0; j < 4; j++) {                                                  \
        int idx = t + 256 * j;                                                     \
        int row = idx >> 5, seg = idx & 31;                                        \
        cpa16(smb + (ss) * 17408u + (u32)(row * 136 + seg * 4) * 4u,               \
              g_Ph + (size_t)(np0j + row) * EPAD + e0 + seg * 4, 16u);             \
    }                                                                              \
    _Pragma("unroll")                                                              \
    for (int j = 0; j < 2; j++) {                                                  \
        int k = t + 256 * j;                                                       \
        int r = k >> 4, s4 = k & 15;                                               \
        u32 doff = (u32)(r * 72 + s4 * 4) * 4u;                                    \
        cpa16(smb + 52224u + (ss) * 18432u + doff,         g_nTh + (size_t)np0j * 64 + k * 4, 16u); \
        cpa16(smb + 52224u + (ss) * 18432u + 9216u + doff, g_nTl + (size_t)np0j * 64 + k * 4, 16u); \
    }                                                                              \
} while (0)

    E3_PRE(0, 0);
    CPA_COMMIT();
    E3_PRE(1, 1);
    CPA_COMMIT();

    for (int ci = 0; ci < nch; ci++) {
        const int s = ci - (ci / 3) * 3;
        if (ci + 2 < nch) { int s2 = (ci + 2) - ((ci + 2) / 3) * 3; E3_PRE(ci + 2, s2); }
        CPA_COMMIT();
        CPA_WAIT2();
        __syncthreads();
        const u32* Ap = (const u32*)(sm + s * 17408);
        const u32* Bh = (const u32*)(sm + 52224 + s * 18432);
        const u32* Bl = Bh + 2304;
#pragma unroll
        for (int kt = 0; kt < 4; kt++) {
            int kp = kt * 8;
            u32 ah[2][4];
#pragma unroll
            for (int mt = 0; mt < 2; mt++) {
                int rb = rowb + mt * 16;
                ah[mt][0] = Ap[(kp + tg) * 136 + rb + g];
                ah[mt][1] = Ap[(kp + tg) * 136 + rb + g + 8];
                ah[mt][2] = Ap[(kp + tg + 4) * 136 + rb + g];
                ah[mt][3] = Ap[(kp + tg + 4) * 136 + rb + g + 8];
            }
#pragma unroll
            for (int nt = 0; nt < 4; nt++) {
                int cb = wn * 32 + nt * 8;
                u32 bh[2] = { Bh[(kp + tg) * 72 + cb + g], Bh[(kp + tg + 4) * 72 + cb + g] };
                u32 bl[2] = { Bl[(kp + tg) * 72 + cb + g], Bl[(kp + tg + 4) * 72 + cb + g] };
#pragma unroll
                for (int mt = 0; mt < 2; mt++) {
                    MMA(c[mt][nt], ah[mt], bh);
                    MMA(c[mt][nt], ah[mt], bl);
                }
            }
        }
        __syncthreads();   // close MMA before stage s is re-prefetched
    }
#undef E3_PRE
#pragma unroll
    for (int mt = 0; mt < 2; mt++)
#pragma unroll
        for (int nt = 0; nt < 4; nt++) {
            int row = e0 + rowb + mt * 16 + g;
            int col = wn * 32 + nt * 8 + 2 * tg;
            if (row < NE)     red2(&g_acc2[row * 64 + col],       c[mt][nt][0], c[mt][nt][1]);
            if (row + 8 < NE) red2(&g_acc2[(row + 8) * 64 + col], c[mt][nt][2], c[mt][nt][3]);
        }
}

// ---------------- finalize1: edge = relu(acc/csum); y = edge@W3 -> yT; zero acc --
__global__ __launch_bounds__(256) void finalize1_kernel(const float* __restrict__ W3) {
    __shared__ __align__(16) float EsT[64][17];
    __shared__ __align__(16) float Ws[64][64];
    __shared__ __align__(16) float Ys[16][64];
    const int t  = threadIdx.x;
    const int e0 = blockIdx.x * 16;      // 125 blocks * 16 = 2000
#pragma unroll
    for (int i = 0; i < 16; i++) {
        int idx = t + 256 * i;
        Ws[idx >> 6][idx & 63] = W3[idx];
    }
#pragma unroll
    for (int i = 0; i < 4; i++) {
        int idx = t + 256 * i;
        int r = idx >> 6, c = idx & 63;
        int ge = e0 + r;
        EsT[c][r] = fmaxf(g_acc[ge * 64 + c] / g_csum[ge], 0.f);
        g_acc[ge * 64 + c] = 0.f;        // self-clean
    }
    __syncthreads();
    const int ty = t >> 4, tx = t & 15;
    float a0 = 0.f, a1 = 0.f, a2 = 0.f, a3 = 0.f;
#pragma unroll
    for (int k = 0; k < 64; k++) {
        float ev = EsT[k][ty];
        float4 w4 = *(const float4*)&Ws[k][tx * 4];
        a0 = fmaf(ev, w4.x, a0); a1 = fmaf(ev, w4.y, a1);
        a2 = fmaf(ev, w4.z, a2); a3 = fmaf(ev, w4.w, a3);
    }
    float4 r4 = {a0, a1, a2, a3};
    *(float4*)&Ys[ty][tx * 4] = r4;
    __syncthreads();
#pragma unroll
    for (int i = 0; i < 2; i++) {
        int idx = t + 256 * i;
        int pp = idx >> 6, d = idx & 63;
        u32 h, l; pack2(Ys[2 * pp][d], Ys[2 * pp + 1][d], h, l);
        int gp = (e0 >> 1) + pp;
        g_yTh[gp * 64 + d] = h;
        g_yTl[gp * 64 + d] = l;
    }
}

// ---------------- GEMM2: node = relu((exp(adj)@y)/rsum); 3-stage A+B pipeline ----
__global__ __launch_bounds__(256, 2) void gemm_n() {
    extern __shared__ __align__(16) char sm[];
    // raw[3][2048]u32 @0 (24576) | B[3][Bh 2304 | Bl 2304] @24576 (55296)
    // A2h[64][36] @79872 (9216) | rsum @89088 (256) = 89344. bounce overlays raw.
    u32* raw = (u32*)sm;
    u32* A2h = (u32*)(sm + 79872);
    float* rsum   = (float*)(sm + 89088);
    float* bounce = (float*)sm;          // [64][68] = 17408B, inside raw region
    const u32 smb = smem_u32(sm);
    const int t = threadIdx.x, w = t >> 5, lane = t & 31;
    const int g = lane >> 2, tg = lane & 3;
    const int p0 = blockIdx.x * 32;
    const int n0 = p0 * 2;
    const int wm = w >> 1, wn = w & 1;
    const int rowb = wm * 16;

    float c[4][4];
    float ce[4];
#pragma unroll
    for (int nt = 0; nt < 4; nt++)
#pragma unroll
        for (int q = 0; q < 4; q++) c[nt][q] = 0.f;
#pragma unroll
    for (int q = 0; q < 4; q++) ce[q] = 0.f;

    // init ones cols (64-71) of all 3 B stages; cp.async never writes them
    {
        int r = t >> 3, cc = 64 + (t & 7);
        u32 val = (cc == 64) ? 0x3F803F80u : 0u;
#pragma unroll
        for (int st = 0; st < 3; st++)
            ((u32*)(sm + 24576 + st * 18432))[r * 72 + cc] = val;
    }

#define N_PRE(cj, ss) do {                                                         \
    _Pragma("unroll")                                                              \
    for (int j = 0; j < 2; j++) {                                                  \
        int idx = t + 256 * j;                                                     \
        int row = idx >> 4, seg = idx & 15;                                        \
        cpa16(smb + (ss) * 8192u + (u32)(row * 64 + seg * 4) * 4u,                 \
              g_Ph + (size_t)(p0 + row) * EPAD + (cj) * 64 + seg * 4, 16u);        \
    }                                                                              \
    _Pragma("unroll")                                                              \
    for (int j = 0; j < 2; j++) {                                                  \
        int k = t + 256 * j;                                                       \
        int r = k >> 4, s4 = k & 15;                                               \
        u32 doff = (u32)(r * 72 + s4 * 4) * 4u;                                    \
        cpa16(smb + 24576u + (ss) * 18432u + doff,         g_yTh + (size_t)(cj) * 2048 + k * 4, 16u); \
        cpa16(smb + 24576u + (ss) * 18432u + 9216u + doff, g_yTl + (size_t)(cj) * 2048 + k * 4, 16u); \
    }                                                                              \
} while (0)

    N_PRE(0, 0);
    CPA_COMMIT();
    N_PRE(1, 1);
    CPA_COMMIT();

    for (int ech = 0; ech < 32; ech++) {
        const int s = ech - (ech / 3) * 3;
        if (ech + 2 < 32) { int s2 = (ech + 2) - ((ech + 2) / 3) * 3; N_PRE(ech + 2, s2); }
        CPA_COMMIT();
        CPA_WAIT2();
        __syncthreads();
        // ---- prmt repack staged g_Ph -> A2h [64 n][32 epair] ----
#pragma unroll
        for (int i = 0; i < 4; i++) {
            int pl = w + 8 * i;
            uint2 vh = *(const uint2*)&raw[s * 2048 + pl * 64 + 2 * lane];
            A2h[(2 * pl) * 36 + lane]     = __byte_perm(vh.x, vh.y, 0x5410);
            A2h[(2 * pl + 1) * 36 + lane] = __byte_perm(vh.x, vh.y, 0x7632);
        }
        __syncthreads();
        const u32* Bh = (const u32*)(sm + 24576 + s * 18432);
        const u32* Bl = Bh + 2304;
#pragma unroll
        for (int kt = 0; kt < 4; kt++) {
            int kp = kt * 8;
            u32 ah[4] = { A2h[(rowb + g) * 36 + kp + tg],     A2h[(rowb + g + 8) * 36 + kp + tg],
                          A2h[(rowb + g) * 36 + kp + tg + 4], A2h[(rowb + g + 8) * 36 + kp + tg + 4] };
#pragma unroll
            for (int nt = 0; nt < 4; nt++) {
                int cb = wn * 32 + nt * 8;
                u32 bh[2] = { Bh[(kp + tg) * 72 + cb + g], Bh[(kp + tg + 4) * 72 + cb + g] };
                u32 bl[2] = { Bl[(kp + tg) * 72 + cb + g], Bl[(kp + tg + 4) * 72 + cb + g] };
                MMA(c[nt], ah, bh);
                MMA(c[nt], ah, bl);
            }
            if (wn == 1) {
                u32 be[2] = { Bh[(kp + tg) * 72 + 64 + g], Bh[(kp + tg + 4) * 72 + 64 + g] };
                MMA(ce, ah, be);
            }
        }
        __syncthreads();   // close MMA before stage s is re-prefetched
    }
#undef N_PRE
    CPA_WAIT0();           // drain before bounce overlays the raw region
    // ---- rsum from ones column ----
    if (wn == 1 && tg == 0) {
        rsum[rowb + g]     = ce[0];
        rsum[rowb + g + 8] = ce[2];
    }
    __syncthreads();
    float s0 = rsum[rowb + g],     ri0 = (s0 > 0.f) ? 1.f / s0 : 0.f;
    float s1 = rsum[rowb + g + 8], ri1 = (s1 > 0.f) ? 1.f / s1 : 0.f;
#pragma unroll
    for (int nt = 0; nt < 4; nt++) {
        int col = wn * 32 + nt * 8 + 2 * tg;
        bounce[(rowb + g) * 68 + col]         = fmaxf(c[nt][0], 0.f) * ri0;
        bounce[(rowb + g) * 68 + col + 1]     = fmaxf(c[nt][1], 0.f) * ri0;
        bounce[(rowb + g + 8) * 68 + col]     = fmaxf(c[nt][2], 0.f) * ri1;
        bounce[(rowb + g + 8) * 68 + col + 1] = fmaxf(c[nt][3], 0.f) * ri1;
    }
    __syncthreads();
#pragma unroll
    for (int i = 0; i < 4; i++) {            // g_node fp32 coalesced
        int idx = t + 256 * i;
        int r = idx >> 4, q = idx & 15;
        if (n0 + r < NN)
            *(float4*)&g_node[(n0 + r) * 64 + q * 4] = *(const float4*)&bounce[r * 68 + q * 4];
    }
#pragma unroll
    for (int i = 0; i < 8; i++) {            // nT [npair][d] hi/lo
        int idx = t + 256 * i;
        int d = idx & 63, pp = idx >> 6;
        u32 h, l;
        pack2(bounce[(2 * pp) * 68 + d], bounce[(2 * pp + 1) * 68 + d], h, l);
        g_nTh[(p0 + pp) * 64 + d] = h;
        g_nTl[(p0 + pp) * 64 + d] = l;
    }
}

// ---------------- fusion + finalize3 merged; zeros acc2/csum ----------------
__global__ __launch_bounds__(256) void fusion_fin3_kernel(const float* __restrict__ fe_old,
                                                          const float* __restrict__ gamma,
                                                          const float* __restrict__ beta,
                                                          const float* __restrict__ w1,
                                                          const float* __restrict__ b1,
                                                          const float* __restrict__ w2,
                                                          float* __restrict__ out_nodes,
                                                          float* __restrict__ out_edges) {
    const int t = threadIdx.x;
    if (blockIdx.x >= 625) {                 // finalize3 part: 500 blocks
        int idx = (int)(blockIdx.x - 625) * 256 + t;
        int e = idx >> 6, d = idx & 63;
        float v = fmaxf(g_acc2[idx] / g_csum[e], 0.f);
        out_edges[idx] = v * (gamma[d] * rsqrtf(1.f + 1e-5f)) + beta[d];
        g_acc2[idx] = 0.f;
        __syncthreads();                     // all csum reads in this block done
        if (d == 0) g_csum[e] = 0.f;
        return;
    }
    __shared__ float w1s[64 * 64];
    __shared__ float b1s[64], w2s[64], gs[64], bs[64];
#pragma unroll
    for (int i = 0; i < 16; i++) w1s[t + 256 * i] = w1[t + 256 * i];
    if (t < 64) {
        b1s[t] = b1[t]; w2s[t] = w2[t];
        gs[t] = gamma[t] * rsqrtf(1.f + 1e-5f); bs[t] = beta[t];
    }
    __syncthreads();
    const int warp = t >> 5, lane = t & 31;
    const int nbase = blockIdx.x * 32 + warp * 4;
    for (int it = 0; it < 4; it++) {
        int n = nbase + it;
        if (n >= NN) break;
        int off = n * 64;
        float f0 = fe_old[off + lane], f1 = fe_old[off + lane + 32];
        float nb0 = fmaf(g_node[off + lane],      gs[lane],      bs[lane]);
        float nb1 = fmaf(g_node[off + lane + 32], gs[lane + 32], bs[lane + 32]);
        float ha0 = b1s[lane], ha1 = b1s[lane + 32];
        float hb0 = ha0, hb1 = ha1;
#pragma unroll
        for (int k = 0; k < 64; k++) {
            float fk = __shfl_sync(0xffffffffu, (k < 32) ? f0 : f1, k & 31);
            float nk = __shfl_sync(0xffffffffu, (k < 32) ? nb0 : nb1, k & 31);
            float wa = w1s[k * 64 + lane], wb = w1s[k * 64 + lane + 32];
            ha0 = fmaf(fk, wa, ha0); ha1 = fmaf(fk, wb, ha1);
            hb0 = fmaf(nk, wa, hb0); hb1 = fmaf(nk, wb, hb1);
        }
        ha0 = tanhf(ha0); ha1 = tanhf(ha1);
        hb0 = tanhf(hb0); hb1 = tanhf(hb1);
        float pa = ha0 * w2s[lane] + ha1 * w2s[lane + 32];
        float pb = hb0 * w2s[lane] + hb1 * w2s[lane + 32];
#pragma unroll
        for (int o = 16; o > 0; o >>= 1) {
            pa += __shfl_down_sync(0xffffffffu, pa, o);
            pb += __shfl_down_sync(0xffffffffu, pb, o);
        }
        pa = __shfl_sync(0xffffffffu, pa, 0);
        pb = __shfl_sync(0xffffffffu, pb, 0);
        float s0 = 1.f / (1.f + expf(pb - pa));
        out_nodes[off + lane]      = s0 * f0 + (1.f - s0) * nb0;
        out_nodes[off + lane + 32] = s0 * f1 + (1.f - s0) * nb1;
    }
}

// ---------------- launch ----------------
#define SM_ET1 (65536 + 17408 + 18432)       // 101376
#define SM_ET3 (52224 + 55296)               // 107520
#define SM_N   (24576 + 55296 + 9216 + 256)  // 89344

extern "C" void kernel_launch(void* const* d_in, const int* in_sizes, int n_in,
                              void* d_out, int out_size) {
    const float* fe    = (const float*)d_in[0];
    const float* adj   = (const float*)d_in[1];
    const float* W2    = (const float*)d_in[2];
    const float* W3    = (const float*)d_in[3];
    const float* gamma = (const float*)d_in[4];
    const float* beta  = (const float*)d_in[5];
    const float* fw1   = (const float*)d_in[6];
    const float* fb1   = (const float*)d_in[7];
    const float* fw2   = (const float*)d_in[8];
    float* out = (float*)d_out;

    cudaFuncSetAttribute((const void*)gemm_et1, cudaFuncAttributeMaxDynamicSharedMemorySize, SM_ET1);
    cudaFuncSetAttribute((const void*)gemm_et3, cudaFuncAttributeMaxDynamicSharedMemorySize, SM_ET3);
    cudaFuncSetAttribute((const void*)gemm_n,   cudaFuncAttributeMaxDynamicSharedMemorySize, SM_N);

    const float* fe_cur = fe;
    for (int s = 0; s < NS; s++) {
        const float* A   = adj + (size_t)s * NN * NE;
        float* out_nodes = out + (size_t)s * (NN + NE) * 64;
        float* out_edges = out_nodes + (size_t)NN * 64;

        gemm_x_kernel<<<313, 256>>>(fe_cur, W2);
        gemm_et1<<<dim3(16, 18), 256, SM_ET1>>>(A);    // exp once + cache g_Ph + edge_pre + csum
        finalize1_kernel<<<125, 256>>>(W3);            // edge -> yT; zeros g_acc
        gemm_n<<<313, 256, SM_N>>>();                  // node + nT (3-stage A+B pipeline)
        gemm_et3<<<dim3(16, 18), 256, SM_ET3>>>();     // edge2_pre (3-stage A+B pipeline)
        fusion_fin3_kernel<<<1125, 256>>>(fe_cur, gamma, beta, fw1, fb1, fw2,
                                          out_nodes, out_edges);   // zeros acc2/csum

        fe_cur = out_nodes;
    }
}

// round 14
// speedup vs baseline: 2.5330x; 1.0232x over previous
#include <cuda_runtime.h>
#include <math.h>

#define NN 20000
#define NE 2000
#define NS 3
#define EPAD 2048
#define NPAIR 10016          // n-pairs (20032/2)

typedef unsigned int u32;

// ---------------- scratch (__device__ globals; zero-init, self-cleaning) ---------
__device__ __align__(16) u32 g_Ph[(size_t)NPAIR * EPAD]; // bf16-hi pairs of exp(adj): [npair][e]
__device__ __align__(16) u32 g_xTh[NPAIR * 64], g_xTl[NPAIR * 64];  // (fe@W2)^T [npair][d]
__device__ __align__(16) u32 g_yTh[1024 * 64],  g_yTl[1024 * 64];   // (edge@W3)^T [epair][d]
__device__ __align__(16) u32 g_nTh[NPAIR * 64], g_nTl[NPAIR * 64];  // node^T [npair][d]
__device__ __align__(16) float g_acc [NE * 64];       // zeroed by finalize1
__device__ __align__(16) float g_acc2[NE * 64];       // zeroed by fusion_fin3
__device__ float g_csum[NE];                          // zeroed by fusion_fin3
__device__ __align__(16) float g_node[NN * 64];

// ---------------- helpers ----------------
__device__ __forceinline__ u32 smem_u32(const void* p) {
    u32 a; asm("{ .reg .u64 t; cvta.to.shared.u64 t, %1; cvt.u32.u64 %0, t; }" : "=r"(a) : "l"(p));
    return a;
}
__device__ __forceinline__ u32 bf16hi(float v) {      // RNE bf16, bits in top half
    u32 u = __float_as_uint(v);
    return (u + 0x7FFFu + ((u >> 16) & 1u)) & 0xFFFF0000u;
}
__device__ __forceinline__ void pack2(float v0, float v1, u32& h, u32& l) {
    u32 h0 = bf16hi(v0), h1 = bf16hi(v1);
    h = (h0 >> 16) | h1;
    u32 l0 = bf16hi(v0 - __uint_as_float(h0));
    u32 l1 = bf16hi(v1 - __uint_as_float(h1));
    l = (l0 >> 16) | l1;
}
__device__ __forceinline__ u32 packhi2(float v0, float v1) {
    return (bf16hi(v0) >> 16) | bf16hi(v1);
}
__device__ __forceinline__ void MMA(float* c, const u32* a, const u32* b) {
    asm volatile("mma.sync.aligned.m16n8k16.row.col.f32.bf16.bf16.f32 "
        "{%0,%1,%2,%3}, {%4,%5,%6,%7}, {%8,%9}, {%0,%1,%2,%3};"
        : "+f"(c[0]), "+f"(c[1]), "+f"(c[2]), "+f"(c[3])
        : "r"(a[0]), "r"(a[1]), "r"(a[2]), "r"(a[3]), "r"(b[0]), "r"(b[1]));
}
__device__ __forceinline__ void red2(float* p, float a, float b) {
    asm volatile("red.global.add.v2.f32 [%0], {%1,%2};" :: "l"(p), "f"(a), "f"(b) : "memory");
}
__device__ __forceinline__ void cpa16(u32 dst, const void* src, u32 sz) {
    asm volatile("cp.async.cg.shared.global [%0], [%1], 16, %2;"
                 :: "r"(dst), "l"(src), "r"(sz) : "memory");
}
#define CPA_COMMIT() asm volatile("cp.async.commit_group;" ::: "memory")
#define CPA_WAIT1()  asm volatile("cp.async.wait_group 1;" ::: "memory")
#define CPA_WAIT0()  asm volatile("cp.async.wait_group 0;" ::: "memory")

// ---------------- gemm_x: x = fe @ W2, writes xT [npair][d] hi/lo ----------------
__global__ __launch_bounds__(256) void gemm_x_kernel(const float* __restrict__ Fe,
                                                     const float* __restrict__ W2) {
    __shared__ __align__(16) float Fs[64][64];
    __shared__ __align__(16) float Ws[64][64];
    const int t  = threadIdx.x;
    const int n0 = blockIdx.x * 64;
    const int tx = t & 15, ty = t >> 4;
#pragma unroll
    for (int i = 0; i < 16; i++) {
        int idx = t + 256 * i;
        int r = idx >> 6, c = idx & 63;
        int n = n0 + r;
        Fs[r][c] = (n < NN) ? Fe[n * 64 + c] : 0.f;
        Ws[r][c] = W2[idx];
    }
    __syncthreads();
    float a[4][4];
#pragma unroll
    for (int i = 0; i < 4; i++)
#pragma unroll
        for (int j = 0; j < 4; j++) a[i][j] = 0.f;
#pragma unroll
    for (int k = 0; k < 64; k++) {
        float fv[4];
#pragma unroll
        for (int i = 0; i < 4; i++) fv[i] = Fs[ty * 4 + i][k];
        float4 w4 = *(const float4*)&Ws[k][tx * 4];
        float wv[4] = {w4.x, w4.y, w4.z, w4.w};
#pragma unroll
        for (int i = 0; i < 4; i++)
#pragma unroll
            for (int j = 0; j < 4; j++) a[i][j] = fmaf(fv[i], wv[j], a[i][j]);
    }
#pragma unroll
    for (int ip = 0; ip < 2; ip++)
#pragma unroll
        for (int j = 0; j < 4; j++) {
            u32 h, l; pack2(a[2 * ip][j], a[2 * ip + 1][j], h, l);
            int idx = ((n0 >> 1) + ty * 2 + ip) * 64 + tx * 4 + j;
            g_xTh[idx] = h;
            g_xTl[idx] = l;
        }
}

// ---------------- GEMM1: acc[e,d] += sum_n exp(adj[n,e]) * x[n,d] ----------------
// 2-stage cp.async raw adj; B LDGs issued into regs BEFORE the wait (latency overlap);
// exp+pack in smem; caches g_Ph; ones->csum.
__global__ __launch_bounds__(256, 2) void gemm_et1(const float* __restrict__ A) {
    extern __shared__ __align__(16) char sm[];
    // raw[2][64][128]f32 @0 (65536) | Ah[32][136] @65536 | B @82944
    float* raw = (float*)sm;
    u32* Ah = (u32*)(sm + 65536);
    u32* Bh = (u32*)(sm + 65536 + 17408);
    u32* Bl = Bh + 32 * 72;
    const u32 smb = smem_u32(sm);
    const int t = threadIdx.x, w = t >> 5, lane = t & 31;
    const int g = lane >> 2, tg = lane & 3;
    const int e0 = blockIdx.x * 128;
    const int sp = blockIdx.y;
    const int c0  = sp * 17 + (sp < 7 ? sp : 7);
    const int nch = 17 + (sp < 7 ? 1 : 0);
    const int wm = w >> 1, wn = w & 1;
    const int rowb = wm * 32;
    const int e_l = t & 127, half = t >> 7;
    const bool e_ok = (e0 + e_l) < NE;

    float c[2][4][4];
    float ce[2][4];
#pragma unroll
    for (int mt = 0; mt < 2; mt++) {
#pragma unroll
        for (int nt = 0; nt < 4; nt++)
#pragma unroll
            for (int q = 0; q < 4; q++) c[mt][nt][q] = 0.f;
#pragma unroll
        for (int q = 0; q < 4; q++) ce[mt][q] = 0.f;
    }
    // ones cols of B written once (cp.async / STS never touch cols 64-71 elsewhere)
    {
        int r = t >> 3, cc = 64 + (t & 7);
        Bh[r * 72 + cc] = (cc == 64) ? 0x3F803F80u : 0u;
        Bl[r * 72 + cc] = 0u;
    }

#define E1_PRE(cj, ss) do {                                                        \
    int n0j = (c0 + (cj)) * 64;                                                    \
    _Pragma("unroll")                                                              \
    for (int j = 0; j < 8; j++) {                                                  \
        int idx = t + 256 * j;                                                     \
        int row = idx >> 5, seg = idx & 31;                                        \
        int n = n0j + row;                                                         \
        u32 sz = (n < NN && (e0 + seg * 4) < NE) ? 16u : 0u;                       \
        cpa16(smb + (ss) * 32768u + (u32)(row * 128 + seg * 4) * 4u,               \
              A + (size_t)n * NE + e0 + seg * 4, sz);                              \
    }                                                                              \
} while (0)

    E1_PRE(0, 0);
    CPA_COMMIT();

    for (int ci = 0; ci < nch; ci++) {
        const int s = ci & 1;
        const int n0  = (c0 + ci) * 64;
        const int np0 = n0 >> 1;
        if (ci + 1 < nch) E1_PRE(ci + 1, s ^ 1);
        CPA_COMMIT();
        // ---- issue B LDGs into regs BEFORE the wait: latency overlaps cp.async ----
        u32 bhv[8], blv[8];
        const int d = t & 63;
#pragma unroll
        for (int i = 0; i < 8; i++) {
            int r = (t >> 6) + 4 * i;
            bhv[i] = g_xTh[(np0 + r) * 64 + d];
            blv[i] = g_xTl[(np0 + r) * 64 + d];
        }
        CPA_WAIT1();
        __syncthreads();
        // ---- STS B tile ----
#pragma unroll
        for (int i = 0; i < 8; i++) {
            int r = (t >> 6) + 4 * i;
            Bh[r * 72 + d] = bhv[i];
            Bl[r * 72 + d] = blv[i];
        }
        // ---- exp + pack from staged raw -> packed A + g_Ph cache ----
        {
            const float* rw = raw + s * 8192;
#pragma unroll
            for (int i = 0; i < 16; i++) {
                int p_l = 2 * i + half;
                int n = n0 + 2 * p_l;
                float v0 = (e_ok && n < NN)     ? __expf(rw[(2 * p_l) * 128 + e_l])     : 0.f;
                float v1 = (e_ok && n + 1 < NN) ? __expf(rw[(2 * p_l + 1) * 128 + e_l]) : 0.f;
                u32 h = packhi2(v0, v1);
                Ah[p_l * 136 + e_l] = h;
                g_Ph[(size_t)(np0 + p_l) * EPAD + e0 + e_l] = h;
            }
        }
        __syncthreads();
        // ---- mma ----
#pragma unroll
        for (int kt = 0; kt < 4; kt++) {
            int kp = kt * 8;
            u32 ah[2][4];
#pragma unroll
            for (int mt = 0; mt < 2; mt++) {
                int rb = rowb + mt * 16;
                ah[mt][0] = Ah[(kp + tg) * 136 + rb + g];
                ah[mt][1] = Ah[(kp + tg) * 136 + rb + g + 8];
                ah[mt][2] = Ah[(kp + tg + 4) * 136 + rb + g];
                ah[mt][3] = Ah[(kp + tg + 4) * 136 + rb + g + 8];
            }
#pragma unroll
            for (int nt = 0; nt < 4; nt++) {
                int cb = wn * 32 + nt * 8;
                u32 bh[2] = { Bh[(kp + tg) * 72 + cb + g], Bh[(kp + tg + 4) * 72 + cb + g] };
                u32 bl[2] = { Bl[(kp + tg) * 72 + cb + g], Bl[(kp + tg + 4) * 72 + cb + g] };
#pragma unroll
                for (int mt = 0; mt < 2; mt++) {
                    MMA(c[mt][nt], ah[mt], bh);
                    MMA(c[mt][nt], ah[mt], bl);
                }
            }
            if (wn == 1) {
                u32 be[2] = { Bh[(kp + tg) * 72 + 64 + g], Bh[(kp + tg + 4) * 72 + 64 + g] };
#pragma unroll
                for (int mt = 0; mt < 2; mt++) MMA(ce[mt], ah[mt], be);
            }
        }
        __syncthreads();   // close MMA before next prefetch/B refill
    }
#undef E1_PRE
#pragma unroll
    for (int mt = 0; mt < 2; mt++)
#pragma unroll
        for (int nt = 0; nt < 4; nt++) {
            int row = e0 + rowb + mt * 16 + g;
            int col = wn * 32 + nt * 8 + 2 * tg;
            if (row < NE)     red2(&g_acc[row * 64 + col],       c[mt][nt][0], c[mt][nt][1]);
            if (row + 8 < NE) red2(&g_acc[(row + 8) * 64 + col], c[mt][nt][2], c[mt][nt][3]);
        }
    if (wn == 1 && tg == 0) {
#pragma unroll
        for (int mt = 0; mt < 2; mt++) {
            int row = e0 + rowb + mt * 16 + g;
            if (row < NE)     atomicAdd(&g_csum[row],     ce[mt][0]);
            if (row + 8 < NE) atomicAdd(&g_csum[row + 8], ce[mt][2]);
        }
    }
}

// ---------------- GEMM3: acc2[e,d] += sum_n exp(adj[n,e]) * node[n,d] -------------
// 2-stage cp.async for packed A (g_Ph) and B (nT hi/lo); 3 CTAs/SM.
__global__ __launch_bounds__(256, 3) void gemm_et3() {
    extern __shared__ __align__(16) char sm[];
    // Ah[2][32*136] @0 (34816) | B[2][Bh 2304 | Bl 2304]u32 @34816 (36864) = 71680
    const u32 smb = smem_u32(sm);
    const int t = threadIdx.x, w = t >> 5, lane = t & 31;
    const int g = lane >> 2, tg = lane & 3;
    const int e0 = blockIdx.x * 128;
    const int sp = blockIdx.y;
    const int c0  = sp * 17 + (sp < 7 ? sp : 7);
    const int nch = 17 + (sp < 7 ? 1 : 0);
    const int wm = w >> 1, wn = w & 1;
    const int rowb = wm * 32;

    float c[2][4][4];
#pragma unroll
    for (int mt = 0; mt < 2; mt++)
#pragma unroll
        for (int nt = 0; nt < 4; nt++)
#pragma unroll
            for (int q = 0; q < 4; q++) c[mt][nt][q] = 0.f;

#define E3_PRE(cj, ss) do {                                                        \
    int np0j = (c0 + (cj)) * 32;                                                   \
    _Pragma("unroll")                                                              \
    for (int j = 0; j < 4; j++) {                                                  \
        int idx = t + 256 * j;                                                     \
        int row = idx >> 5, seg = idx & 31;                                        \
        cpa16(smb + (ss) * 17408u + (u32)(row * 136 + seg * 4) * 4u,               \
              g_Ph + (size_t)(np0j + row) * EPAD + e0 + seg * 4, 16u);             \
    }                                                                              \
    _Pragma("unroll")                                                              \
    for (int j = 0; j < 2; j++) {                                                  \
        int k = t + 256 * j;                                                       \
        int r = k >> 4, s4 = k & 15;                                               \
        u32 doff = (u32)(r * 72 + s4 * 4) * 4u;                                    \
        cpa16(smb + 34816u + (ss) * 18432u + doff,         g_nTh + (size_t)np0j * 64 + k * 4, 16u); \
        cpa16(smb + 34816u + (ss) * 18432u + 9216u + doff, g_nTl + (size_t)np0j * 64 + k * 4, 16u); \
    }                                                                              \
} while (0)

    E3_PRE(0, 0);
    CPA_COMMIT();

    for (int ci = 0; ci < nch; ci++) {
        const int s = ci & 1;
        if (ci + 1 < nch) E3_PRE(ci + 1, s ^ 1);
        CPA_COMMIT();
        CPA_WAIT1();
        __syncthreads();
        const u32* Ap = (const u32*)(sm + s * 17408);
        const u32* Bh = (const u32*)(sm + 34816 + s * 18432);
        const u32* Bl = Bh + 2304;
#pragma unroll
        for (int kt = 0; kt < 4; kt++) {
            int kp = kt * 8;
            u32 ah[2][4];
#pragma unroll
            for (int mt = 0; mt < 2; mt++) {
                int rb = rowb + mt * 16;
                ah[mt][0] = Ap[(kp + tg) * 136 + rb + g];
                ah[mt][1] = Ap[(kp + tg) * 136 + rb + g + 8];
                ah[mt][2] = Ap[(kp + tg + 4) * 136 + rb + g];
                ah[mt][3] = Ap[(kp + tg + 4) * 136 + rb + g + 8];
            }
#pragma unroll
            for (int nt = 0; nt < 4; nt++) {
                int cb = wn * 32 + nt * 8;
                u32 bh[2] = { Bh[(kp + tg) * 72 + cb + g], Bh[(kp + tg + 4) * 72 + cb + g] };
                u32 bl[2] = { Bl[(kp + tg) * 72 + cb + g], Bl[(kp + tg + 4) * 72 + cb + g] };
#pragma unroll
                for (int mt = 0; mt < 2; mt++) {
                    MMA(c[mt][nt], ah[mt], bh);
                    MMA(c[mt][nt], ah[mt], bl);
                }
            }
        }
        __syncthreads();   // close MMA before stage s is re-prefetched
    }
#undef E3_PRE
#pragma unroll
    for (int mt = 0; mt < 2; mt++)
#pragma unroll
        for (int nt = 0; nt < 4; nt++) {
            int row = e0 + rowb + mt * 16 + g;
            int col = wn * 32 + nt * 8 + 2 * tg;
            if (row < NE)     red2(&g_acc2[row * 64 + col],       c[mt][nt][0], c[mt][nt][1]);
            if (row + 8 < NE) red2(&g_acc2[(row + 8) * 64 + col], c[mt][nt][2], c[mt][nt][3]);
        }
}

// ---------------- finalize1: edge = relu(acc/csum); y = edge@W3 -> yT; zero acc --
__global__ __launch_bounds__(256) void finalize1_kernel(const float* __restrict__ W3) {
    __shared__ __align__(16) float EsT[64][17];
    __shared__ __align__(16) float Ws[64][64];
    __shared__ __align__(16) float Ys[16][64];
    const int t  = threadIdx.x;
    const int e0 = blockIdx.x * 16;      // 125 blocks * 16 = 2000
#pragma unroll
    for (int i = 0; i < 16; i++) {
        int idx = t + 256 * i;
        Ws[idx >> 6][idx & 63] = W3[idx];
    }
#pragma unroll
    for (int i = 0; i < 4; i++) {
        int idx = t + 256 * i;
        int r = idx >> 6, c = idx & 63;
        int ge = e0 + r;
        EsT[c][r] = fmaxf(g_acc[ge * 64 + c] / g_csum[ge], 0.f);
        g_acc[ge * 64 + c] = 0.f;        // self-clean
    }
    __syncthreads();
    const int ty = t >> 4, tx = t & 15;
    float a0 = 0.f, a1 = 0.f, a2 = 0.f, a3 = 0.f;
#pragma unroll
    for (int k = 0; k < 64; k++) {
        float ev = EsT[k][ty];
        float4 w4 = *(const float4*)&Ws[k][tx * 4];
        a0 = fmaf(ev, w4.x, a0); a1 = fmaf(ev, w4.y, a1);
        a2 = fmaf(ev, w4.z, a2); a3 = fmaf(ev, w4.w, a3);
    }
    float4 r4 = {a0, a1, a2, a3};
    *(float4*)&Ys[ty][tx * 4] = r4;
    __syncthreads();
#pragma unroll
    for (int i = 0; i < 2; i++) {
        int idx = t + 256 * i;
        int pp = idx >> 6, d = idx & 63;
        u32 h, l; pack2(Ys[2 * pp][d], Ys[2 * pp + 1][d], h, l);
        int gp = (e0 >> 1) + pp;
        g_yTh[gp * 64 + d] = h;
        g_yTl[gp * 64 + d] = l;
    }
}

// ---------------- GEMM2: node = relu((exp(adj)@y)/rsum); 2-stage, 3 CTAs/SM ------
__global__ __launch_bounds__(256, 3) void gemm_n() {
    extern __shared__ __align__(16) char sm[];
    // raw[2][2048]u32 @0 (16384) | B[2][Bh 2304 | Bl 2304] @16384 (36864)
    // A2h[64][36] @53248 (9216) | rsum @62464 (256) = 62720. bounce overlays @0.
    u32* raw = (u32*)sm;
    u32* A2h = (u32*)(sm + 53248);
    float* rsum   = (float*)(sm + 62464);
    float* bounce = (float*)sm;          // [64][68] = 17408B (raw + 1KB of B st0, post-drain)
    const u32 smb = smem_u32(sm);
    const int t = threadIdx.x, w = t >> 5, lane = t & 31;
    const int g = lane >> 2, tg = lane & 3;
    const int p0 = blockIdx.x * 32;
    const int n0 = p0 * 2;
    const int wm = w >> 1, wn = w & 1;
    const int rowb = wm * 16;

    float c[4][4];
    float ce[4];
#pragma unroll
    for (int nt = 0; nt < 4; nt++)
#pragma unroll
        for (int q = 0; q < 4; q++) c[nt][q] = 0.f;
#pragma unroll
    for (int q = 0; q < 4; q++) ce[q] = 0.f;

    // init ones cols (64-71) of both B stages; cp.async never writes them
    {
        int r = t >> 3, cc = 64 + (t & 7);
        u32 val = (cc == 64) ? 0x3F803F80u : 0u;
#pragma unroll
        for (int st = 0; st < 2; st++)
            ((u32*)(sm + 16384 + st * 18432))[r * 72 + cc] = val;
    }

#define N_PRE(cj, ss) do {                                                         \
    _Pragma("unroll")                                                              \
    for (int j = 0; j < 2; j++) {                                                  \
        int idx = t + 256 * j;                                                     \
        int row = idx >> 4, seg = idx & 15;                                        \
        cpa16(smb + (ss) * 8192u + (u32)(row * 64 + seg * 4) * 4u,                 \
              g_Ph + (size_t)(p0 + row) * EPAD + (cj) * 64 + seg * 4, 16u);        \
    }                                                                              \
    _Pragma("unroll")                                                              \
    for (int j = 0; j < 2; j++) {                                                  \
        int k = t + 256 * j;                                                       \
        int r = k >> 4, s4 = k & 15;                                               \
        u32 doff = (u32)(r * 72 + s4 * 4) * 4u;                                    \
        cpa16(smb + 16384u + (ss) * 18432u + doff,         g_yTh + (size_t)(cj) * 2048 + k * 4, 16u); \
        cpa16(smb + 16384u + (ss) * 18432u + 9216u + doff, g_yTl + (size_t)(cj) * 2048 + k * 4, 16u); \
    }                                                                              \
} while (0)

    N_PRE(0, 0);
    CPA_COMMIT();

    for (int ech = 0; ech < 32; ech++) {
        const int s = ech & 1;
        if (ech + 1 < 32) N_PRE(ech + 1, s ^ 1);
        CPA_COMMIT();
        CPA_WAIT1();
        __syncthreads();
        // ---- prmt repack staged g_Ph -> A2h [64 n][32 epair] ----
#pragma unroll
        for (int i = 0; i < 4; i++) {
            int pl = w + 8 * i;
            uint2 vh = *(const uint2*)&raw[s * 2048 + pl * 64 + 2 * lane];
            A2h[(2 * pl) * 36 + lane]     = __byte_perm(vh.x, vh.y, 0x5410);
            A2h[(2 * pl + 1) * 36 + lane] = __byte_perm(vh.x, vh.y, 0x7632);
        }
        __syncthreads();
        const u32* Bh = (const u32*)(sm + 16384 + s * 18432);
        const u32* Bl = Bh + 2304;
#pragma unroll
        for (int kt = 0; kt < 4; kt++) {
            int kp = kt * 8;
            u32 ah[4] = { A2h[(rowb + g) * 36 + kp + tg],     A2h[(rowb + g + 8) * 36 + kp + tg],
                          A2h[(rowb + g) * 36 + kp + tg + 4], A2h[(rowb + g + 8) * 36 + kp + tg + 4] };
#pragma unroll
            for (int nt = 0; nt < 4; nt++) {
                int cb = wn * 32 + nt * 8;
                u32 bh[2] = { Bh[(kp + tg) * 72 + cb + g], Bh[(kp + tg + 4) * 72 + cb + g] };
                u32 bl[2] = { Bl[(kp + tg) * 72 + cb + g], Bl[(kp + tg + 4) * 72 + cb + g] };
                MMA(c[nt], ah, bh);
                MMA(c[nt], ah, bl);
            }
            if (wn == 1) {
                u32 be[2] = { Bh[(kp + tg) * 72 + 64 + g], Bh[(kp + tg + 4) * 72 + 64 + g] };
                MMA(ce, ah, be);
            }
        }
        __syncthreads();   // close MMA before stage s is re-prefetched
    }
#undef N_PRE
    CPA_WAIT0();           // drain before bounce overlays the raw/B region
    // ---- rsum from ones column ----
    if (wn == 1 && tg == 0) {
        rsum[rowb + g]     = ce[0];
        rsum[rowb + g + 8] = ce[2];
    }
    __syncthreads();
    float s0 = rsum[rowb + g],     ri0 = (s0 > 0.f) ? 1.f / s0 : 0.f;
    float s1 = rsum[rowb + g + 8], ri1 = (s1 > 0.f) ? 1.f / s1 : 0.f;
#pragma unroll
    for (int nt = 0; nt < 4; nt++) {
        int col = wn * 32 + nt * 8 + 2 * tg;
        bounce[(rowb + g) * 68 + col]         = fmaxf(c[nt][0], 0.f) * ri0;
        bounce[(rowb + g) * 68 + col + 1]     = fmaxf(c[nt][1], 0.f) * ri0;
        bounce[(rowb + g + 8) * 68 + col]     = fmaxf(c[nt][2], 0.f) * ri1;
        bounce[(rowb + g + 8) * 68 + col + 1] = fmaxf(c[nt][3], 0.f) * ri1;
    }
    __syncthreads();
#pragma unroll
    for (int i = 0; i < 4; i++) {            // g_node fp32 coalesced
        int idx = t + 256 * i;
        int r = idx >> 4, q = idx & 15;
        if (n0 + r < NN)
            *(float4*)&g_node[(n0 + r) * 64 + q * 4] = *(const float4*)&bounce[r * 68 + q * 4];
    }
#pragma unroll
    for (int i = 0; i < 8; i++) {            // nT [npair][d] hi/lo
        int idx = t + 256 * i;
        int d = idx & 63, pp = idx >> 6;
        u32 h, l;
        pack2(bounce[(2 * pp) * 68 + d], bounce[(2 * pp + 1) * 68 + d], h, l);
        g_nTh[(p0 + pp) * 64 + d] = h;
        g_nTl[(p0 + pp) * 64 + d] = l;
    }
}

// ---------------- fusion + finalize3 merged; zeros acc2/csum ----------------
__global__ __launch_bounds__(256) void fusion_fin3_kernel(const float* __restrict__ fe_old,
                                                          const float* __restrict__ gamma,
                                                          const float* __restrict__ beta,
                                                          const float* __restrict__ w1,
                                                          const float* __restrict__ b1,
                                                          const float* __restrict__ w2,
                                                          float* __restrict__ out_nodes,
                                                          float* __restrict__ out_edges) {
    const int t = threadIdx.x;
    if (blockIdx.x >= 625) {                 // finalize3 part: 500 blocks
        int idx = (int)(blockIdx.x - 625) * 256 + t;
        int e = idx >> 6, d = idx & 63;
        float v = fmaxf(g_acc2[idx] / g_csum[e], 0.f);
        out_edges[idx] = v * (gamma[d] * rsqrtf(1.f + 1e-5f)) + beta[d];
        g_acc2[idx] = 0.f;
        __syncthreads();                     // all csum reads in this block done
        if (d == 0) g_csum[e] = 0.f;
        return;
    }
    __shared__ float w1s[64 * 64];
    __shared__ float b1s[64], w2s[64], gs[64], bs[64];
#pragma unroll
    for (int i = 0; i < 16; i++) w1s[t + 256 * i] = w1[t + 256 * i];
    if (t < 64) {
        b1s[t] = b1[t]; w2s[t] = w2[t];
        gs[t] = gamma[t] * rsqrtf(1.f + 1e-5f); bs[t] = beta[t];
    }
    __syncthreads();
    const int warp = t >> 5, lane = t & 31;
    const int nbase = blockIdx.x * 32 + warp * 4;
    for (int it = 0; it < 4; it++) {
        int n = nbase + it;
        if (n >= NN) break;
        int off = n * 64;
        float f0 = fe_old[off + lane], f1 = fe_old[off + lane + 32];
        float nb0 = fmaf(g_node[off + lane],      gs[lane],      bs[lane]);
        float nb1 = fmaf(g_node[off + lane + 32], gs[lane + 32], bs[lane + 32]);
        float ha0 = b1s[lane], ha1 = b1s[lane + 32];
        float hb0 = ha0, hb1 = ha1;
#pragma unroll
        for (int k = 0; k < 64; k++) {
            float fk = __shfl_sync(0xffffffffu, (k < 32) ? f0 : f1, k & 31);
            float nk = __shfl_sync(0xffffffffu, (k < 32) ? nb0 : nb1, k & 31);
            float wa = w1s[k * 64 + lane], wb = w1s[k * 64 + lane + 32];
            ha0 = fmaf(fk, wa, ha0); ha1 = fmaf(fk, wb, ha1);
            hb0 = fmaf(nk, wa, hb0); hb1 = fmaf(nk, wb, hb1);
        }
        ha0 = tanhf(ha0); ha1 = tanhf(ha1);
        hb0 = tanhf(hb0); hb1 = tanhf(hb1);
        float pa = ha0 * w2s[lane] + ha1 * w2s[lane + 32];
        float pb = hb0 * w2s[lane] + hb1 * w2s[lane + 32];
#pragma unroll
        for (int o = 16; o > 0; o >>= 1) {
            pa += __shfl_down_sync(0xffffffffu, pa, o);
            pb += __shfl_down_sync(0xffffffffu, pb, o);
        }
        pa = __shfl_sync(0xffffffffu, pa, 0);
        pb = __shfl_sync(0xffffffffu, pb, 0);
        float s0 = 1.f / (1.f + expf(pb - pa));
        out_nodes[off + lane]      = s0 * f0 + (1.f - s0) * nb0;
        out_nodes[off + lane + 32] = s0 * f1 + (1.f - s0) * nb1;
    }
}

// ---------------- launch ----------------
#define SM_ET1 (65536 + 17408 + 18432)       // 101376
#define SM_ET3 (34816 + 36864)               // 71680
#define SM_N   (16384 + 36864 + 9216 + 256)  // 62720

extern "C" void kernel_launch(void* const* d_in, const int* in_sizes, int n_in,
                              void* d_out, int out_size) {
    const float* fe    = (const float*)d_in[0];
    const float* adj   = (const float*)d_in[1];
    const float* W2    = (const float*)d_in[2];
    const float* W3    = (const float*)d_in[3];
    const float* gamma = (const float*)d_in[4];
    const float* beta  = (const float*)d_in[5];
    const float* fw1   = (const float*)d_in[6];
    const float* fb1   = (const float*)d_in[7];
    const float* fw2   = (const float*)d_in[8];
    float* out = (float*)d_out;

    cudaFuncSetAttribute((const void*)gemm_et1, cudaFuncAttributeMaxDynamicSharedMemorySize, SM_ET1);
    cudaFuncSetAttribute((const void*)gemm_et3, cudaFuncAttributeMaxDynamicSharedMemorySize, SM_ET3);
    cudaFuncSetAttribute((const void*)gemm_n,   cudaFuncAttributeMaxDynamicSharedMemorySize, SM_N);

    const float* fe_cur = fe;
    for (int s = 0; s < NS; s++) {
        const float* A   = adj + (size_t)s * NN * NE;
        float* out_nodes = out + (size_t)s * (NN + NE) * 64;
        float* out_edges = out_nodes + (size_t)NN * 64;

        gemm_x_kernel<<<313, 256>>>(fe_cur, W2);
        gemm_et1<<<dim3(16, 18), 256, SM_ET1>>>(A);    // exp once + cache g_Ph + edge_pre + csum
        finalize1_kernel<<<125, 256>>>(W3);            // edge -> yT; zeros g_acc
        gemm_n<<<313, 256, SM_N>>>();                  // node + nT (2-stage, 3 CTAs/SM)
        gemm_et3<<<dim3(16, 18), 256, SM_ET3>>>();     // edge2_pre (2-stage, 3 CTAs/SM)
        fusion_fin3_kernel<<<1125, 256>>>(fe_cur, gamma, beta, fw1, fb1, fw2,
                                          out_nodes, out_edges);   // zeros acc2/csum

        fe_cur = out_nodes;
    }
}

// round 15
// speedup vs baseline: 3.1128x; 1.2289x over previous
#include <cuda_runtime.h>
#include <math.h>

#define NN 20000
#define NE 2000
#define NS 3
#define EPAD 2048
#define NPAIR 10016          // n-pairs (20032/2)

typedef unsigned int u32;

// ---------------- scratch (__device__ globals; zero-init, self-cleaning) ---------
__device__ __align__(16) u32 g_Ph[(size_t)NPAIR * EPAD]; // bf16-hi pairs of exp(adj): [npair][e]
__device__ __align__(16) u32 g_xTh[NPAIR * 64];          // (fe@W2)^T [npair][d] bf16-hi pairs
__device__ __align__(16) u32 g_yTh[1024 * 64];           // (edge@W3)^T [epair][d]
__device__ __align__(16) u32 g_nTh[NPAIR * 64];          // node^T [npair][d]
__device__ __align__(16) float g_acc [NE * 64];          // zeroed by finalize1
__device__ __align__(16) float g_acc2[NE * 64];          // zeroed by fusion_fin3
__device__ float g_csum[NE];                             // zeroed by fusion_fin3
__device__ __align__(16) float g_node[NN * 64];

// ---------------- helpers ----------------
__device__ __forceinline__ u32 smem_u32(const void* p) {
    u32 a; asm("{ .reg .u64 t; cvta.to.shared.u64 t, %1; cvt.u32.u64 %0, t; }" : "=r"(a) : "l"(p));
    return a;
}
__device__ __forceinline__ u32 bf16hi(float v) {      // RNE bf16, bits in top half
    u32 u = __float_as_uint(v);
    return (u + 0x7FFFu + ((u >> 16) & 1u)) & 0xFFFF0000u;
}
__device__ __forceinline__ u32 packhi2(float v0, float v1) {
    return (bf16hi(v0) >> 16) | bf16hi(v1);
}
__device__ __forceinline__ void MMA(float* c, const u32* a, const u32* b) {
    asm volatile("mma.sync.aligned.m16n8k16.row.col.f32.bf16.bf16.f32 "
        "{%0,%1,%2,%3}, {%4,%5,%6,%7}, {%8,%9}, {%0,%1,%2,%3};"
        : "+f"(c[0]), "+f"(c[1]), "+f"(c[2]), "+f"(c[3])
        : "r"(a[0]), "r"(a[1]), "r"(a[2]), "r"(a[3]), "r"(b[0]), "r"(b[1]));
}
__device__ __forceinline__ void red2(float* p, float a, float b) {
    asm volatile("red.global.add.v2.f32 [%0], {%1,%2};" :: "l"(p), "f"(a), "f"(b) : "memory");
}
__device__ __forceinline__ void cpa16(u32 dst, const void* src, u32 sz) {
    asm volatile("cp.async.cg.shared.global [%0], [%1], 16, %2;"
                 :: "r"(dst), "l"(src), "r"(sz) : "memory");
}
#define CPA_COMMIT() asm volatile("cp.async.commit_group;" ::: "memory")
#define CPA_WAIT1()  asm volatile("cp.async.wait_group 1;" ::: "memory")
#define CPA_WAIT0()  asm volatile("cp.async.wait_group 0;" ::: "memory")

// ---------------- gemm_x: x = fe @ W2, writes xT [npair][d] hi ----------------
__global__ __launch_bounds__(256) void gemm_x_kernel(const float* __restrict__ Fe,
                                                     const float* __restrict__ W2) {
    __shared__ __align__(16) float Fs[64][64];
    __shared__ __align__(16) float Ws[64][64];
    const int t  = threadIdx.x;
    const int n0 = blockIdx.x * 64;
    const int tx = t & 15, ty = t >> 4;
#pragma unroll
    for (int i = 0; i < 16; i++) {
        int idx = t + 256 * i;
        int r = idx >> 6, c = idx & 63;
        int n = n0 + r;
        Fs[r][c] = (n < NN) ? Fe[n * 64 + c] : 0.f;
        Ws[r][c] = W2[idx];
    }
    __syncthreads();
    float a[4][4];
#pragma unroll
    for (int i = 0; i < 4; i++)
#pragma unroll
        for (int j = 0; j < 4; j++) a[i][j] = 0.f;
#pragma unroll
    for (int k = 0; k < 64; k++) {
        float fv[4];
#pragma unroll
        for (int i = 0; i < 4; i++) fv[i] = Fs[ty * 4 + i][k];
        float4 w4 = *(const float4*)&Ws[k][tx * 4];
        float wv[4] = {w4.x, w4.y, w4.z, w4.w};
#pragma unroll
        for (int i = 0; i < 4; i++)
#pragma unroll
            for (int j = 0; j < 4; j++) a[i][j] = fmaf(fv[i], wv[j], a[i][j]);
    }
#pragma unroll
    for (int ip = 0; ip < 2; ip++)
#pragma unroll
        for (int j = 0; j < 4; j++) {
            int idx = ((n0 >> 1) + ty * 2 + ip) * 64 + tx * 4 + j;
            g_xTh[idx] = packhi2(a[2 * ip][j], a[2 * ip + 1][j]);
        }
}

// ---------------- GEMM1: acc[e,d] += sum_n exp(adj[n,e]) * x[n,d] ----------------
// 2-stage cp.async raw adj; B LDGs issued into regs BEFORE the wait; exp+pack in
// smem; caches g_Ph; ones->csum. B = bf16-hi only.
__global__ __launch_bounds__(256, 2) void gemm_et1(const float* __restrict__ A) {
    extern __shared__ __align__(16) char sm[];
    // raw[2][64][128]f32 @0 (65536) | Ah[32][136] @65536 (17408) | Bh[32][72] @82944 (9216)
    float* raw = (float*)sm;
    u32* Ah = (u32*)(sm + 65536);
    u32* Bh = (u32*)(sm + 82944);
    const u32 smb = smem_u32(sm);
    const int t = threadIdx.x, w = t >> 5, lane = t & 31;
    const int g = lane >> 2, tg = lane & 3;
    const int e0 = blockIdx.x * 128;
    const int sp = blockIdx.y;
    const int c0  = sp * 17 + (sp < 7 ? sp : 7);
    const int nch = 17 + (sp < 7 ? 1 : 0);
    const int wm = w >> 1, wn = w & 1;
    const int rowb = wm * 32;
    const int e_l = t & 127, half = t >> 7;
    const bool e_ok = (e0 + e_l) < NE;

    float c[2][4][4];
    float ce[2][4];
#pragma unroll
    for (int mt = 0; mt < 2; mt++) {
#pragma unroll
        for (int nt = 0; nt < 4; nt++)
#pragma unroll
            for (int q = 0; q < 4; q++) c[mt][nt][q] = 0.f;
#pragma unroll
        for (int q = 0; q < 4; q++) ce[mt][q] = 0.f;
    }
    // ones cols written once (nothing else touches cols 64-71)
    {
        int r = t >> 3, cc = 64 + (t & 7);
        Bh[r * 72 + cc] = (cc == 64) ? 0x3F803F80u : 0u;
    }

#define E1_PRE(cj, ss) do {                                                        \
    int n0j = (c0 + (cj)) * 64;                                                    \
    _Pragma("unroll")                                                              \
    for (int j = 0; j < 8; j++) {                                                  \
        int idx = t + 256 * j;                                                     \
        int row = idx >> 5, seg = idx & 31;                                        \
        int n = n0j + row;                                                         \
        u32 sz = (n < NN && (e0 + seg * 4) < NE) ? 16u : 0u;                       \
        cpa16(smb + (ss) * 32768u + (u32)(row * 128 + seg * 4) * 4u,               \
              A + (size_t)n * NE + e0 + seg * 4, sz);                              \
    }                                                                              \
} while (0)

    E1_PRE(0, 0);
    CPA_COMMIT();

    for (int ci = 0; ci < nch; ci++) {
        const int s = ci & 1;
        const int n0  = (c0 + ci) * 64;
        const int np0 = n0 >> 1;
        if (ci + 1 < nch) E1_PRE(ci + 1, s ^ 1);
        CPA_COMMIT();
        // ---- issue B LDGs into regs BEFORE the wait: latency overlaps cp.async ----
        u32 bhv[8];
        const int d = t & 63;
#pragma unroll
        for (int i = 0; i < 8; i++) {
            int r = (t >> 6) + 4 * i;
            bhv[i] = g_xTh[(np0 + r) * 64 + d];
        }
        CPA_WAIT1();
        __syncthreads();
#pragma unroll
        for (int i = 0; i < 8; i++) {
            int r = (t >> 6) + 4 * i;
            Bh[r * 72 + d] = bhv[i];
        }
        // ---- exp + pack from staged raw -> packed A + g_Ph cache ----
        {
            const float* rw = raw + s * 8192;
#pragma unroll
            for (int i = 0; i < 16; i++) {
                int p_l = 2 * i + half;
                int n = n0 + 2 * p_l;
                float v0 = (e_ok && n < NN)     ? __expf(rw[(2 * p_l) * 128 + e_l])     : 0.f;
                float v1 = (e_ok && n + 1 < NN) ? __expf(rw[(2 * p_l + 1) * 128 + e_l]) : 0.f;
                u32 h = packhi2(v0, v1);
                Ah[p_l * 136 + e_l] = h;
                g_Ph[(size_t)(np0 + p_l) * EPAD + e0 + e_l] = h;
            }
        }
        __syncthreads();
        // ---- mma ----
#pragma unroll
        for (int kt = 0; kt < 4; kt++) {
            int kp = kt * 8;
            u32 ah[2][4];
#pragma unroll
            for (int mt = 0; mt < 2; mt++) {
                int rb = rowb + mt * 16;
                ah[mt][0] = Ah[(kp + tg) * 136 + rb + g];
                ah[mt][1] = Ah[(kp + tg) * 136 + rb + g + 8];
                ah[mt][2] = Ah[(kp + tg + 4) * 136 + rb + g];
                ah[mt][3] = Ah[(kp + tg + 4) * 136 + rb + g + 8];
            }
#pragma unroll
            for (int nt = 0; nt < 4; nt++) {
                int cb = wn * 32 + nt * 8;
                u32 bh[2] = { Bh[(kp + tg) * 72 + cb + g], Bh[(kp + tg + 4) * 72 + cb + g] };
#pragma unroll
                for (int mt = 0; mt < 2; mt++) MMA(c[mt][nt], ah[mt], bh);
            }
            if (wn == 1) {
                u32 be[2] = { Bh[(kp + tg) * 72 + 64 + g], Bh[(kp + tg + 4) * 72 + 64 + g] };
#pragma unroll
                for (int mt = 0; mt < 2; mt++) MMA(ce[mt], ah[mt], be);
            }
        }
        __syncthreads();   // close MMA before next prefetch/B refill
    }
#undef E1_PRE
#pragma unroll
    for (int mt = 0; mt < 2; mt++)
#pragma unroll
        for (int nt = 0; nt < 4; nt++) {
            int row = e0 + rowb + mt * 16 + g;
            int col = wn * 32 + nt * 8 + 2 * tg;
            if (row < NE)     red2(&g_acc[row * 64 + col],       c[mt][nt][0], c[mt][nt][1]);
            if (row + 8 < NE) red2(&g_acc[(row + 8) * 64 + col], c[mt][nt][2], c[mt][nt][3]);
        }
    if (wn == 1 && tg == 0) {
#pragma unroll
        for (int mt = 0; mt < 2; mt++) {
            int row = e0 + rowb + mt * 16 + g;
            if (row < NE)     atomicAdd(&g_csum[row],     ce[mt][0]);
            if (row + 8 < NE) atomicAdd(&g_csum[row + 8], ce[mt][2]);
        }
    }
}

// ---------------- GEMM3: acc2[e,d] += sum_n exp(adj[n,e]) * node[n,d] -------------
// 2-stage cp.async for packed A (g_Ph) and B (nTh); 3 CTAs/SM.
__global__ __launch_bounds__(256, 3) void gemm_et3() {
    extern __shared__ __align__(16) char sm[];
    // Ah[2][32*136] @0 (34816) | Bh[2][32*72] @34816 (18432) = 53248
    const u32 smb = smem_u32(sm);
    const int t = threadIdx.x, w = t >> 5, lane = t & 31;
    const int g = lane >> 2, tg = lane & 3;
    const int e0 = blockIdx.x * 128;
    const int sp = blockIdx.y;
    const int c0  = sp * 17 + (sp < 7 ? sp : 7);
    const int nch = 17 + (sp < 7 ? 1 : 0);
    const int wm = w >> 1, wn = w & 1;
    const int rowb = wm * 32;

    float c[2][4][4];
#pragma unroll
    for (int mt = 0; mt < 2; mt++)
#pragma unroll
        for (int nt = 0; nt < 4; nt++)
#pragma unroll
            for (int q = 0; q < 4; q++) c[mt][nt][q] = 0.f;

#define E3_PRE(cj, ss) do {                                                        \
    int np0j = (c0 + (cj)) * 32;                                                   \
    _Pragma("unroll")                                                              \
    for (int j = 0; j < 4; j++) {                                                  \
        int idx = t + 256 * j;                                                     \
        int row = idx >> 5, seg = idx & 31;                                        \
        cpa16(smb + (ss) * 17408u + (u32)(row * 136 + seg * 4) * 4u,               \
              g_Ph + (size_t)(np0j + row) * EPAD + e0 + seg * 4, 16u);             \
    }                                                                              \
    _Pragma("unroll")                                                              \
    for (int j = 0; j < 2; j++) {                                                  \
        int k = t + 256 * j;                                                       \
        int r = k >> 4, s4 = k & 15;                                               \
        cpa16(smb + 34816u + (ss) * 9216u + (u32)(r * 72 + s4 * 4) * 4u,           \
              g_nTh + (size_t)np0j * 64 + k * 4, 16u);                             \
    }                                                                              \
} while (0)

    E3_PRE(0, 0);
    CPA_COMMIT();

    for (int ci = 0; ci < nch; ci++) {
        const int s = ci & 1;
        if (ci + 1 < nch) E3_PRE(ci + 1, s ^ 1);
        CPA_COMMIT();
        CPA_WAIT1();
        __syncthreads();
        const u32* Ap = (const u32*)(sm + s * 17408);
        const u32* Bh = (const u32*)(sm + 34816 + s * 9216);
#pragma unroll
        for (int kt = 0; kt < 4; kt++) {
            int kp = kt * 8;
            u32 ah[2][4];
#pragma unroll
            for (int mt = 0; mt < 2; mt++) {
                int rb = rowb + mt * 16;
                ah[mt][0] = Ap[(kp + tg) * 136 + rb + g];
                ah[mt][1] = Ap[(kp + tg) * 136 + rb + g + 8];
                ah[mt][2] = Ap[(kp + tg + 4) * 136 + rb + g];
                ah[mt][3] = Ap[(kp + tg + 4) * 136 + rb + g + 8];
            }
#pragma unroll
            for (int nt = 0; nt < 4; nt++) {
                int cb = wn * 32 + nt * 8;
                u32 bh[2] = { Bh[(kp + tg) * 72 + cb + g], Bh[(kp + tg + 4) * 72 + cb + g] };
#pragma unroll
                for (int mt = 0; mt < 2; mt++) MMA(c[mt][nt], ah[mt], bh);
            }
        }
        __syncthreads();   // close MMA before stage s is re-prefetched
    }
#undef E3_PRE
#pragma unroll
    for (int mt = 0; mt < 2; mt++)
#pragma unroll
        for (int nt = 0; nt < 4; nt++) {
            int row = e0 + rowb + mt * 16 + g;
            int col = wn * 32 + nt * 8 + 2 * tg;
            if (row < NE)     red2(&g_acc2[row * 64 + col],       c[mt][nt][0], c[mt][nt][1]);
            if (row + 8 < NE) red2(&g_acc2[(row + 8) * 64 + col], c[mt][nt][2], c[mt][nt][3]);
        }
}

// ---------------- finalize1: edge = relu(acc/csum); y = edge@W3 -> yTh; zero acc --
__global__ __launch_bounds__(256) void finalize1_kernel(const float* __restrict__ W3) {
    __shared__ __align__(16) float EsT[64][17];
    __shared__ __align__(16) float Ws[64][64];
    __shared__ __align__(16) float Ys[16][64];
    const int t  = threadIdx.x;
    const int e0 = blockIdx.x * 16;      // 125 blocks * 16 = 2000
#pragma unroll
    for (int i = 0; i < 16; i++) {
        int idx = t + 256 * i;
        Ws[idx >> 6][idx & 63] = W3[idx];
    }
#pragma unroll
    for (int i = 0; i < 4; i++) {
        int idx = t + 256 * i;
        int r = idx >> 6, c = idx & 63;
        int ge = e0 + r;
        EsT[c][r] = fmaxf(g_acc[ge * 64 + c] / g_csum[ge], 0.f);
        g_acc[ge * 64 + c] = 0.f;        // self-clean
    }
    __syncthreads();
    const int ty = t >> 4, tx = t & 15;
    float a0 = 0.f, a1 = 0.f, a2 = 0.f, a3 = 0.f;
#pragma unroll
    for (int k = 0; k < 64; k++) {
        float ev = EsT[k][ty];
        float4 w4 = *(const float4*)&Ws[k][tx * 4];
        a0 = fmaf(ev, w4.x, a0); a1 = fmaf(ev, w4.y, a1);
        a2 = fmaf(ev, w4.z, a2); a3 = fmaf(ev, w4.w, a3);
    }
    float4 r4 = {a0, a1, a2, a3};
    *(float4*)&Ys[ty][tx * 4] = r4;
    __syncthreads();
#pragma unroll
    for (int i = 0; i < 2; i++) {
        int idx = t + 256 * i;
        int pp = idx >> 6, d = idx & 63;
        int gp = (e0 >> 1) + pp;
        g_yTh[gp * 64 + d] = packhi2(Ys[2 * pp][d], Ys[2 * pp + 1][d]);
    }
}

// ---------------- GEMM2: node = relu((exp(adj)@y)/rsum); 2-stage A+B pipeline ----
__global__ __launch_bounds__(256, 3) void gemm_n() {
    extern __shared__ __align__(16) char sm[];
    // raw[2][2048]u32 @0 (16384) | Bh[2][2304] @16384 (18432)
    // A2h[64][36] @34816 (9216) | rsum @44032 (256) = 44288. bounce overlays @0.
    u32* raw = (u32*)sm;
    u32* A2h = (u32*)(sm + 34816);
    float* rsum   = (float*)(sm + 44032);
    float* bounce = (float*)sm;          // [64][68] = 17408B (raw + 1KB of B st0, post-drain)
    const u32 smb = smem_u32(sm);
    const int t = threadIdx.x, w = t >> 5, lane = t & 31;
    const int g = lane >> 2, tg = lane & 3;
    const int p0 = blockIdx.x * 32;
    const int n0 = p0 * 2;
    const int wm = w >> 1, wn = w & 1;
    const int rowb = wm * 16;

    float c[4][4];
    float ce[4];
#pragma unroll
    for (int nt = 0; nt < 4; nt++)
#pragma unroll
        for (int q = 0; q < 4; q++) c[nt][q] = 0.f;
#pragma unroll
    for (int q = 0; q < 4; q++) ce[q] = 0.f;

    // init ones cols (64-71) of both B stages; cp.async never writes them
    {
        int r = t >> 3, cc = 64 + (t & 7);
        u32 val = (cc == 64) ? 0x3F803F80u : 0u;
#pragma unroll
        for (int st = 0; st < 2; st++)
            ((u32*)(sm + 16384 + st * 9216))[r * 72 + cc] = val;
    }

#define N_PRE(cj, ss) do {                                                         \
    _Pragma("unroll")                                                              \
    for (int j = 0; j < 2; j++) {                                                  \
        int idx = t + 256 * j;                                                     \
        int row = idx >> 4, seg = idx & 15;                                        \
        cpa16(smb + (ss) * 8192u + (u32)(row * 64 + seg * 4) * 4u,                 \
              g_Ph + (size_t)(p0 + row) * EPAD + (cj) * 64 + seg * 4, 16u);        \
    }                                                                              \
    _Pragma("unroll")                                                              \
    for (int j = 0; j < 2; j++) {                                                  \
        int k = t + 256 * j;                                                       \
        int r = k >> 4, s4 = k & 15;                                               \
        cpa16(smb + 16384u + (ss) * 9216u + (u32)(r * 72 + s4 * 4) * 4u,           \
              g_yTh + (size_t)(cj) * 2048 + k * 4, 16u);                           \
    }                                                                              \
} while (0)

    N_PRE(0, 0);
    CPA_COMMIT();

    for (int ech = 0; ech < 32; ech++) {
        const int s = ech & 1;
        if (ech + 1 < 32) N_PRE(ech + 1, s ^ 1);
        CPA_COMMIT();
        CPA_WAIT1();
        __syncthreads();
        // ---- prmt repack staged g_Ph -> A2h [64 n][32 epair] ----
#pragma unroll
        for (int i = 0; i < 4; i++) {
            int pl = w + 8 * i;
            uint2 vh = *(const uint2*)&raw[s * 2048 + pl * 64 + 2 * lane];
            A2h[(2 * pl) * 36 + lane]     = __byte_perm(vh.x, vh.y, 0x5410);
            A2h[(2 * pl + 1) * 36 + lane] = __byte_perm(vh.x, vh.y, 0x7632);
        }
        __syncthreads();
        const u32* Bh = (const u32*)(sm + 16384 + s * 9216);
#pragma unroll
        for (int kt = 0; kt < 4; kt++) {
            int kp = kt * 8;
            u32 ah[4] = { A2h[(rowb + g) * 36 + kp + tg],     A2h[(rowb + g + 8) * 36 + kp + tg],
                          A2h[(rowb + g) * 36 + kp + tg + 4], A2h[(rowb + g + 8) * 36 + kp + tg + 4] };
#pragma unroll
            for (int nt = 0; nt < 4; nt++) {
                int cb = wn * 32 + nt * 8;
                u32 bh[2] = { Bh[(kp + tg) * 72 + cb + g], Bh[(kp + tg + 4) * 72 + cb + g] };
                MMA(c[nt], ah, bh);
            }
            if (wn == 1) {
                u32 be[2] = { Bh[(kp + tg) * 72 + 64 + g], Bh[(kp + tg + 4) * 72 + 64 + g] };
                MMA(ce, ah, be);
            }
        }
        __syncthreads();   // close MMA before stage s is re-prefetched
    }
#undef N_PRE
    CPA_WAIT0();           // drain before bounce overlays the raw/B region
    // ---- rsum from ones column ----
    if (wn == 1 && tg == 0) {
        rsum[rowb + g]     = ce[0];
        rsum[rowb + g + 8] = ce[2];
    }
    __syncthreads();
    float s0 = rsum[rowb + g],     ri0 = (s0 > 0.f) ? 1.f / s0 : 0.f;
    float s1 = rsum[rowb + g + 8], ri1 = (s1 > 0.f) ? 1.f / s1 : 0.f;
#pragma unroll
    for (int nt = 0; nt < 4; nt++) {
        int col = wn * 32 + nt * 8 + 2 * tg;
        bounce[(rowb + g) * 68 + col]         = fmaxf(c[nt][0], 0.f) * ri0;
        bounce[(rowb + g) * 68 + col + 1]     = fmaxf(c[nt][1], 0.f) * ri0;
        bounce[(rowb + g + 8) * 68 + col]     = fmaxf(c[nt][2], 0.f) * ri1;
        bounce[(rowb + g + 8) * 68 + col + 1] = fmaxf(c[nt][3], 0.f) * ri1;
    }
    __syncthreads();
#pragma unroll
    for (int i = 0; i < 4; i++) {            // g_node fp32 coalesced
        int idx = t + 256 * i;
        int r = idx >> 4, q = idx & 15;
        if (n0 + r < NN)
            *(float4*)&g_node[(n0 + r) * 64 + q * 4] = *(const float4*)&bounce[r * 68 + q * 4];
    }
#pragma unroll
    for (int i = 0; i < 8; i++) {            // nTh [npair][d]
        int idx = t + 256 * i;
        int d = idx & 63, pp = idx >> 6;
        g_nTh[(p0 + pp) * 64 + d] = packhi2(bounce[(2 * pp) * 68 + d],
                                            bounce[(2 * pp + 1) * 68 + d]);
    }
}

// ---------------- fusion + finalize3 merged; zeros acc2/csum ----------------
__global__ __launch_bounds__(256) void fusion_fin3_kernel(const float* __restrict__ fe_old,
                                                          const float* __restrict__ gamma,
                                                          const float* __restrict__ beta,
                                                          const float* __restrict__ w1,
                                                          const float* __restrict__ b1,
                                                          const float* __restrict__ w2,
                                                          float* __restrict__ out_nodes,
                                                          float* __restrict__ out_edges) {
    const int t = threadIdx.x;
    if (blockIdx.x >= 625) {                 // finalize3 part: 500 blocks
        int idx = (int)(blockIdx.x - 625) * 256 + t;
        int e = idx >> 6, d = idx & 63;
        float v = fmaxf(g_acc2[idx] / g_csum[e], 0.f);
        out_edges[idx] = v * (gamma[d] * rsqrtf(1.f + 1e-5f)) + beta[d];
        g_acc2[idx] = 0.f;
        __syncthreads();                     // all csum reads in this block done
        if (d == 0) g_csum[e] = 0.f;
        return;
    }
    __shared__ float w1s[64 * 64];
    __shared__ float b1s[64], w2s[64], gs[64], bs[64];
#pragma unroll
    for (int i = 0; i < 16; i++) w1s[t + 256 * i] = w1[t + 256 * i];
    if (t < 64) {
        b1s[t] = b1[t]; w2s[t] = w2[t];
        gs[t] = gamma[t] * rsqrtf(1.f + 1e-5f); bs[t] = beta[t];
    }
    __syncthreads();
    const int warp = t >> 5, lane = t & 31;
    const int nbase = blockIdx.x * 32 + warp * 4;
    for (int it = 0; it < 4; it++) {
        int n = nbase + it;
        if (n >= NN) break;
        int off = n * 64;
        float f0 = fe_old[off + lane], f1 = fe_old[off + lane + 32];
        float nb0 = fmaf(g_node[off + lane],      gs[lane],      bs[lane]);
        float nb1 = fmaf(g_node[off + lane + 32], gs[lane + 32], bs[lane + 32]);
        float ha0 = b1s[lane], ha1 = b1s[lane + 32];
        float hb0 = ha0, hb1 = ha1;
#pragma unroll
        for (int k = 0; k < 64; k++) {
            float fk = __shfl_sync(0xffffffffu, (k < 32) ? f0 : f1, k & 31);
            float nk = __shfl_sync(0xffffffffu, (k < 32) ? nb0 : nb1, k & 31);
            float wa = w1s[k * 64 + lane], wb = w1s[k * 64 + lane + 32];
            ha0 = fmaf(fk, wa, ha0); ha1 = fmaf(fk, wb, ha1);
            hb0 = fmaf(nk, wa, hb0); hb1 = fmaf(nk, wb, hb1);
        }
        ha0 = tanhf(ha0); ha1 = tanhf(ha1);
        hb0 = tanhf(hb0); hb1 = tanhf(hb1);
        float pa = ha0 * w2s[lane] + ha1 * w2s[lane + 32];
        float pb = hb0 * w2s[lane] + hb1 * w2s[lane + 32];
#pragma unroll
        for (int o = 16; o > 0; o >>= 1) {
            pa += __shfl_down_sync(0xffffffffu, pa, o);
            pb += __shfl_down_sync(0xffffffffu, pb, o);
        }
        pa = __shfl_sync(0xffffffffu, pa, 0);
        pb = __shfl_sync(0xffffffffu, pb, 0);
        float s0 = 1.f / (1.f + expf(pb - pa));
        out_nodes[off + lane]      = s0 * f0 + (1.f - s0) * nb0;
        out_nodes[off + lane + 32] = s0 * f1 + (1.f - s0) * nb1;
    }
}

// ---------------- launch ----------------
#define SM_ET1 (65536 + 17408 + 9216)        // 92160
#define SM_ET3 (34816 + 18432)               // 53248
#define SM_N   (16384 + 18432 + 9216 + 256)  // 44288

extern "C" void kernel_launch(void* const* d_in, const int* in_sizes, int n_in,
                              void* d_out, int out_size) {
    const float* fe    = (const float*)d_in[0];
    const float* adj   = (const float*)d_in[1];
    const float* W2    = (const float*)d_in[2];
    const float* W3    = (const float*)d_in[3];
    const float* gamma = (const float*)d_in[4];
    const float* beta  = (const float*)d_in[5];
    const float* fw1   = (const float*)d_in[6];
    const float* fb1   = (const float*)d_in[7];
    const float* fw2   = (const float*)d_in[8];
    float* out = (float*)d_out;

    cudaFuncSetAttribute((const void*)gemm_et1, cudaFuncAttributeMaxDynamicSharedMemorySize, SM_ET1);
    cudaFuncSetAttribute((const void*)gemm_et3, cudaFuncAttributeMaxDynamicSharedMemorySize, SM_ET3);
    cudaFuncSetAttribute((const void*)gemm_n,   cudaFuncAttributeMaxDynamicSharedMemorySize, SM_N);

    const float* fe_cur = fe;
    for (int s = 0; s < NS; s++) {
        const float* A   = adj + (size_t)s * NN * NE;
        float* out_nodes = out + (size_t)s * (NN + NE) * 64;
        float* out_edges = out_nodes + (size_t)NN * 64;

        gemm_x_kernel<<<313, 256>>>(fe_cur, W2);
        gemm_et1<<<dim3(16, 18), 256, SM_ET1>>>(A);    // exp once + cache g_Ph + edge_pre + csum
        finalize1_kernel<<<125, 256>>>(W3);            // edge -> yTh; zeros g_acc
        gemm_n<<<313, 256, SM_N>>>();                  // node + nTh (2-stage A+B)
        gemm_et3<<<dim3(16, 18), 256, SM_ET3>>>();     // edge2_pre (2-stage A+B)
        fusion_fin3_kernel<<<1125, 256>>>(fe_cur, gamma, beta, fw1, fb1, fw2,
                                          out_nodes, out_edges);   // zeros acc2/csum

        fe_cur = out_nodes;
    }
}

// round 16
// speedup vs baseline: 3.1151x; 1.0007x over previous
#include <cuda_runtime.h>
#include <math.h>

#define NN 20000
#define NE 2000
#define NS 3
#define EPAD 2048
#define NPAIR 10016          // n-pairs (20032/2)

typedef unsigned int u32;

// ---------------- scratch (__device__ globals; zero-init, self-cleaning) ---------
__device__ __align__(16) u32 g_Ph[(size_t)NPAIR * EPAD]; // bf16-hi pairs of exp(adj): [npair][e]
__device__ __align__(16) u32 g_xTh[NPAIR * 64];          // (fe@W2)^T [npair][d] bf16-hi pairs
__device__ __align__(16) u32 g_yTh[1024 * 64];           // (edge@W3)^T [epair][d]
__device__ __align__(16) u32 g_nTh[NPAIR * 64];          // node^T [npair][d]
__device__ __align__(16) float g_acc [NE * 64];          // zeroed by finalize1
__device__ __align__(16) float g_acc2[NE * 64];          // zeroed by fusion_fin3
__device__ __align__(16) float g_nacc[NN * 64];          // node partials; zeroed by finalize_n
__device__ float g_csum[NE];                             // zeroed by fusion_fin3
__device__ float g_rsum[NN];                             // zeroed by fusion_fin3
__device__ __align__(16) float g_node[NN * 64];

// ---------------- helpers ----------------
__device__ __forceinline__ u32 smem_u32(const void* p) {
    u32 a; asm("{ .reg .u64 t; cvta.to.shared.u64 t, %1; cvt.u32.u64 %0, t; }" : "=r"(a) : "l"(p));
    return a;
}
__device__ __forceinline__ u32 bf16hi(float v) {      // RNE bf16, bits in top half
    u32 u = __float_as_uint(v);
    return (u + 0x7FFFu + ((u >> 16) & 1u)) & 0xFFFF0000u;
}
__device__ __forceinline__ u32 packhi2(float v0, float v1) {
    return (bf16hi(v0) >> 16) | bf16hi(v1);
}
__device__ __forceinline__ void MMA(float* c, const u32* a, const u32* b) {
    asm volatile("mma.sync.aligned.m16n8k16.row.col.f32.bf16.bf16.f32 "
        "{%0,%1,%2,%3}, {%4,%5,%6,%7}, {%8,%9}, {%0,%1,%2,%3};"
        : "+f"(c[0]), "+f"(c[1]), "+f"(c[2]), "+f"(c[3])
        : "r"(a[0]), "r"(a[1]), "r"(a[2]), "r"(a[3]), "r"(b[0]), "r"(b[1]));
}
__device__ __forceinline__ void red2(float* p, float a, float b) {
    asm volatile("red.global.add.v2.f32 [%0], {%1,%2};" :: "l"(p), "f"(a), "f"(b) : "memory");
}
__device__ __forceinline__ void cpa16(u32 dst, const void* src, u32 sz) {
    asm volatile("cp.async.cg.shared.global [%0], [%1], 16, %2;"
                 :: "r"(dst), "l"(src), "r"(sz) : "memory");
}
#define CPA_COMMIT() asm volatile("cp.async.commit_group;" ::: "memory")
#define CPA_WAIT1()  asm volatile("cp.async.wait_group 1;" ::: "memory")

// ---------------- gemm_x: x = fe @ W2, writes xT [npair][d] hi ----------------
__global__ __launch_bounds__(256) void gemm_x_kernel(const float* __restrict__ Fe,
                                                     const float* __restrict__ W2) {
    __shared__ __align__(16) float Fs[64][64];
    __shared__ __align__(16) float Ws[64][64];
    const int t  = threadIdx.x;
    const int n0 = blockIdx.x * 64;
    const int tx = t & 15, ty = t >> 4;
#pragma unroll
    for (int i = 0; i < 16; i++) {
        int idx = t + 256 * i;
        int r = idx >> 6, c = idx & 63;
        int n = n0 + r;
        Fs[r][c] = (n < NN) ? Fe[n * 64 + c] : 0.f;
        Ws[r][c] = W2[idx];
    }
    __syncthreads();
    float a[4][4];
#pragma unroll
    for (int i = 0; i < 4; i++)
#pragma unroll
        for (int j = 0; j < 4; j++) a[i][j] = 0.f;
#pragma unroll
    for (int k = 0; k < 64; k++) {
        float fv[4];
#pragma unroll
        for (int i = 0; i < 4; i++) fv[i] = Fs[ty * 4 + i][k];
        float4 w4 = *(const float4*)&Ws[k][tx * 4];
        float wv[4] = {w4.x, w4.y, w4.z, w4.w};
#pragma unroll
        for (int i = 0; i < 4; i++)
#pragma unroll
            for (int j = 0; j < 4; j++) a[i][j] = fmaf(fv[i], wv[j], a[i][j]);
    }
#pragma unroll
    for (int ip = 0; ip < 2; ip++)
#pragma unroll
        for (int j = 0; j < 4; j++) {
            int idx = ((n0 >> 1) + ty * 2 + ip) * 64 + tx * 4 + j;
            g_xTh[idx] = packhi2(a[2 * ip][j], a[2 * ip + 1][j]);
        }
}

// ---------------- GEMM1: acc[e,d] += sum_n exp(adj[n,e]) * x[n,d] ----------------
__global__ __launch_bounds__(256, 2) void gemm_et1(const float* __restrict__ A) {
    extern __shared__ __align__(16) char sm[];
    // raw[2][64][128]f32 @0 (65536) | Ah[32][136] @65536 (17408) | Bh[32][72] @82944 (9216)
    float* raw = (float*)sm;
    u32* Ah = (u32*)(sm + 65536);
    u32* Bh = (u32*)(sm + 82944);
    const u32 smb = smem_u32(sm);
    const int t = threadIdx.x, w = t >> 5, lane = t & 31;
    const int g = lane >> 2, tg = lane & 3;
    const int e0 = blockIdx.x * 128;
    const int sp = blockIdx.y;
    const int c0  = sp * 17 + (sp < 7 ? sp : 7);
    const int nch = 17 + (sp < 7 ? 1 : 0);
    const int wm = w >> 1, wn = w & 1;
    const int rowb = wm * 32;
    const int e_l = t & 127, half = t >> 7;
    const bool e_ok = (e0 + e_l) < NE;

    float c[2][4][4];
    float ce[2][4];
#pragma unroll
    for (int mt = 0; mt < 2; mt++) {
#pragma unroll
        for (int nt = 0; nt < 4; nt++)
#pragma unroll
            for (int q = 0; q < 4; q++) c[mt][nt][q] = 0.f;
#pragma unroll
        for (int q = 0; q < 4; q++) ce[mt][q] = 0.f;
    }
    {
        int r = t >> 3, cc = 64 + (t & 7);
        Bh[r * 72 + cc] = (cc == 64) ? 0x3F803F80u : 0u;
    }

#define E1_PRE(cj, ss) do {                                                        \
    int n0j = (c0 + (cj)) * 64;                                                    \
    _Pragma("unroll")                                                              \
    for (int j = 0; j < 8; j++) {                                                  \
        int idx = t + 256 * j;                                                     \
        int row = idx >> 5, seg = idx & 31;                                        \
        int n = n0j + row;                                                         \
        u32 sz = (n < NN && (e0 + seg * 4) < NE) ? 16u : 0u;                       \
        cpa16(smb + (ss) * 32768u + (u32)(row * 128 + seg * 4) * 4u,               \
              A + (size_t)n * NE + e0 + seg * 4, sz);                              \
    }                                                                              \
} while (0)

    E1_PRE(0, 0);
    CPA_COMMIT();

    for (int ci = 0; ci < nch; ci++) {
        const int s = ci & 1;
        const int n0  = (c0 + ci) * 64;
        const int np0 = n0 >> 1;
        if (ci + 1 < nch) E1_PRE(ci + 1, s ^ 1);
        CPA_COMMIT();
        u32 bhv[8];
        const int d = t & 63;
#pragma unroll
        for (int i = 0; i < 8; i++) {
            int r = (t >> 6) + 4 * i;
            bhv[i] = g_xTh[(np0 + r) * 64 + d];
        }
        CPA_WAIT1();
        __syncthreads();
#pragma unroll
        for (int i = 0; i < 8; i++) {
            int r = (t >> 6) + 4 * i;
            Bh[r * 72 + d] = bhv[i];
        }
        {
            const float* rw = raw + s * 8192;
#pragma unroll
            for (int i = 0; i < 16; i++) {
                int p_l = 2 * i + half;
                int n = n0 + 2 * p_l;
                float v0 = (e_ok && n < NN)     ? __expf(rw[(2 * p_l) * 128 + e_l])     : 0.f;
                float v1 = (e_ok && n + 1 < NN) ? __expf(rw[(2 * p_l + 1) * 128 + e_l]) : 0.f;
                u32 h = packhi2(v0, v1);
                Ah[p_l * 136 + e_l] = h;
                g_Ph[(size_t)(np0 + p_l) * EPAD + e0 + e_l] = h;
            }
        }
        __syncthreads();
#pragma unroll
        for (int kt = 0; kt < 4; kt++) {
            int kp = kt * 8;
            u32 ah[2][4];
#pragma unroll
            for (int mt = 0; mt < 2; mt++) {
                int rb = rowb + mt * 16;
                ah[mt][0] = Ah[(kp + tg) * 136 + rb + g];
                ah[mt][1] = Ah[(kp + tg) * 136 + rb + g + 8];
                ah[mt][2] = Ah[(kp + tg + 4) * 136 + rb + g];
                ah[mt][3] = Ah[(kp + tg + 4) * 136 + rb + g + 8];
            }
#pragma unroll
            for (int nt = 0; nt < 4; nt++) {
                int cb = wn * 32 + nt * 8;
                u32 bh[2] = { Bh[(kp + tg) * 72 + cb + g], Bh[(kp + tg + 4) * 72 + cb + g] };
#pragma unroll
                for (int mt = 0; mt < 2; mt++) MMA(c[mt][nt], ah[mt], bh);
            }
            if (wn == 1) {
                u32 be[2] = { Bh[(kp + tg) * 72 + 64 + g], Bh[(kp + tg + 4) * 72 + 64 + g] };
#pragma unroll
                for (int mt = 0; mt < 2; mt++) MMA(ce[mt], ah[mt], be);
            }
        }
        __syncthreads();
    }
#undef E1_PRE
#pragma unroll
    for (int mt = 0; mt < 2; mt++)
#pragma unroll
        for (int nt = 0; nt < 4; nt++) {
            int row = e0 + rowb + mt * 16 + g;
            int col = wn * 32 + nt * 8 + 2 * tg;
            if (row < NE)     red2(&g_acc[row * 64 + col],       c[mt][nt][0], c[mt][nt][1]);
            if (row + 8 < NE) red2(&g_acc[(row + 8) * 64 + col], c[mt][nt][2], c[mt][nt][3]);
        }
    if (wn == 1 && tg == 0) {
#pragma unroll
        for (int mt = 0; mt < 2; mt++) {
            int row = e0 + rowb + mt * 16 + g;
            if (row < NE)     atomicAdd(&g_csum[row],     ce[mt][0]);
            if (row + 8 < NE) atomicAdd(&g_csum[row + 8], ce[mt][2]);
        }
    }
}

// ---------------- GEMM3: acc2[e,d] += sum_n exp(adj[n,e]) * node[n,d] -------------
// 2-stage cp.async for packed A (g_Ph) and B (nTh); 27 splits, 3 CTAs/SM.
__global__ __launch_bounds__(256, 3) void gemm_et3() {
    extern __shared__ __align__(16) char sm[];
    // Ah[2][32*136] @0 (34816) | Bh[2][32*72] @34816 (18432) = 53248
    const u32 smb = smem_u32(sm);
    const int t = threadIdx.x, w = t >> 5, lane = t & 31;
    const int g = lane >> 2, tg = lane & 3;
    const int e0 = blockIdx.x * 128;
    const int sp = blockIdx.y;
    const int c0  = sp * 11 + (sp < 16 ? sp : 16);
    const int nch = 11 + (sp < 16 ? 1 : 0);
    const int wm = w >> 1, wn = w & 1;
    const int rowb = wm * 32;

    float c[2][4][4];
#pragma unroll
    for (int mt = 0; mt < 2; mt++)
#pragma unroll
        for (int nt = 0; nt < 4; nt++)
#pragma unroll
            for (int q = 0; q < 4; q++) c[mt][nt][q] = 0.f;

#define E3_PRE(cj, ss) do {                                                        \
    int np0j = (c0 + (cj)) * 32;                                                   \
    _Pragma("unroll")                                                              \
    for (int j = 0; j < 4; j++) {                                                  \
        int idx = t + 256 * j;                                                     \
        int row = idx >> 5, seg = idx & 31;                                        \
        cpa16(smb + (ss) * 17408u + (u32)(row * 136 + seg * 4) * 4u,               \
              g_Ph + (size_t)(np0j + row) * EPAD + e0 + seg * 4, 16u);             \
    }                                                                              \
    _Pragma("unroll")                                                              \
    for (int j = 0; j < 2; j++) {                                                  \
        int k = t + 256 * j;                                                       \
        int r = k >> 4, s4 = k & 15;                                               \
        cpa16(smb + 34816u + (ss) * 9216u + (u32)(r * 72 + s4 * 4) * 4u,           \
              g_nTh + (size_t)np0j * 64 + k * 4, 16u);                             \
    }                                                                              \
} while (0)

    E3_PRE(0, 0);
    CPA_COMMIT();

    for (int ci = 0; ci < nch; ci++) {
        const int s = ci & 1;
        if (ci + 1 < nch) E3_PRE(ci + 1, s ^ 1);
        CPA_COMMIT();
        CPA_WAIT1();
        __syncthreads();
        const u32* Ap = (const u32*)(sm + s * 17408);
        const u32* Bh = (const u32*)(sm + 34816 + s * 9216);
#pragma unroll
        for (int kt = 0; kt < 4; kt++) {
            int kp = kt * 8;
            u32 ah[2][4];
#pragma unroll
            for (int mt = 0; mt < 2; mt++) {
                int rb = rowb + mt * 16;
                ah[mt][0] = Ap[(kp + tg) * 136 + rb + g];
                ah[mt][1] = Ap[(kp + tg) * 136 + rb + g + 8];
                ah[mt][2] = Ap[(kp + tg + 4) * 136 + rb + g];
                ah[mt][3] = Ap[(kp + tg + 4) * 136 + rb + g + 8];
            }
#pragma unroll
            for (int nt = 0; nt < 4; nt++) {
                int cb = wn * 32 + nt * 8;
                u32 bh[2] = { Bh[(kp + tg) * 72 + cb + g], Bh[(kp + tg + 4) * 72 + cb + g] };
#pragma unroll
                for (int mt = 0; mt < 2; mt++) MMA(c[mt][nt], ah[mt], bh);
            }
        }
        __syncthreads();
    }
#undef E3_PRE
#pragma unroll
    for (int mt = 0; mt < 2; mt++)
#pragma unroll
        for (int nt = 0; nt < 4; nt++) {
            int row = e0 + rowb + mt * 16 + g;
            int col = wn * 32 + nt * 8 + 2 * tg;
            if (row < NE)     red2(&g_acc2[row * 64 + col],       c[mt][nt][0], c[mt][nt][1]);
            if (row + 8 < NE) red2(&g_acc2[(row + 8) * 64 + col], c[mt][nt][2], c[mt][nt][3]);
        }
}

// ---------------- finalize1: edge = relu(acc/csum); y = edge@W3 -> yTh; zero acc --
__global__ __launch_bounds__(256) void finalize1_kernel(const float* __restrict__ W3) {
    __shared__ __align__(16) float EsT[64][17];
    __shared__ __align__(16) float Ws[64][64];
    __shared__ __align__(16) float Ys[16][64];
    const int t  = threadIdx.x;
    const int e0 = blockIdx.x * 16;      // 125 blocks * 16 = 2000
#pragma unroll
    for (int i = 0; i < 16; i++) {
        int idx = t + 256 * i;
        Ws[idx >> 6][idx & 63] = W3[idx];
    }
#pragma unroll
    for (int i = 0; i < 4; i++) {
        int idx = t + 256 * i;
        int r = idx >> 6, c = idx & 63;
        int ge = e0 + r;
        EsT[c][r] = fmaxf(g_acc[ge * 64 + c] / g_csum[ge], 0.f);
        g_acc[ge * 64 + c] = 0.f;        // self-clean
    }
    __syncthreads();
    const int ty = t >> 4, tx = t & 15;
    float a0 = 0.f, a1 = 0.f, a2 = 0.f, a3 = 0.f;
#pragma unroll
    for (int k = 0; k < 64; k++) {
        float ev = EsT[k][ty];
        float4 w4 = *(const float4*)&Ws[k][tx * 4];
        a0 = fmaf(ev, w4.x, a0); a1 = fmaf(ev, w4.y, a1);
        a2 = fmaf(ev, w4.z, a2); a3 = fmaf(ev, w4.w, a3);
    }
    float4 r4 = {a0, a1, a2, a3};
    *(float4*)&Ys[ty][tx * 4] = r4;
    __syncthreads();
#pragma unroll
    for (int i = 0; i < 2; i++) {
        int idx = t + 256 * i;
        int pp = idx >> 6, d = idx & 63;
        int gp = (e0 >> 1) + pp;
        g_yTh[gp * 64 + d] = packhi2(Ys[2 * pp][d], Ys[2 * pp + 1][d]);
    }
}

// ---------------- GEMM2: nacc[n,d] += sum_{e in split} exp(adj[n,e]) * y[e,d] ----
// Split-K over e (2 x 16 chunks); raw partials to g_nacc/g_rsum; finalize_n divides.
__global__ __launch_bounds__(256, 3) void gemm_n() {
    extern __shared__ __align__(16) char sm[];
    // raw[2][2048]u32 @0 (16384) | Bh[2][2304] @16384 (18432) | A2h[64][36] @34816 (9216)
    u32* raw = (u32*)sm;
    u32* A2h = (u32*)(sm + 34816);
    const u32 smb = smem_u32(sm);
    const int t = threadIdx.x, w = t >> 5, lane = t & 31;
    const int g = lane >> 2, tg = lane & 3;
    const int p0 = blockIdx.x * 32;
    const int n0 = p0 * 2;
    const int base = blockIdx.y * 16;    // e-chunk split: [base, base+16)
    const int wm = w >> 1, wn = w & 1;
    const int rowb = wm * 16;

    float c[4][4];
    float ce[4];
#pragma unroll
    for (int nt = 0; nt < 4; nt++)
#pragma unroll
        for (int q = 0; q < 4; q++) c[nt][q] = 0.f;
#pragma unroll
    for (int q = 0; q < 4; q++) ce[q] = 0.f;

    // init ones cols (64-71) of both B stages
    {
        int r = t >> 3, cc = 64 + (t & 7);
        u32 val = (cc == 64) ? 0x3F803F80u : 0u;
#pragma unroll
        for (int st = 0; st < 2; st++)
            ((u32*)(sm + 16384 + st * 9216))[r * 72 + cc] = val;
    }

#define N_PRE(cj, ss) do {                                                         \
    _Pragma("unroll")                                                              \
    for (int j = 0; j < 2; j++) {                                                  \
        int idx = t + 256 * j;                                                     \
        int row = idx >> 4, seg = idx & 15;                                        \
        cpa16(smb + (ss) * 8192u + (u32)(row * 64 + seg * 4) * 4u,                 \
              g_Ph + (size_t)(p0 + row) * EPAD + (cj) * 64 + seg * 4, 16u);        \
    }                                                                              \
    _Pragma("unroll")                                                              \
    for (int j = 0; j < 2; j++) {                                                  \
        int k = t + 256 * j;                                                       \
        int r = k >> 4, s4 = k & 15;                                               \
        cpa16(smb + 16384u + (ss) * 9216u + (u32)(r * 72 + s4 * 4) * 4u,           \
              g_yTh + (size_t)(cj) * 2048 + k * 4, 16u);                           \
    }                                                                              \
} while (0)

    N_PRE(base, 0);
    CPA_COMMIT();

    for (int ech = base; ech < base + 16; ech++) {
        const int s = ech & 1;
        if (ech + 1 < base + 16) N_PRE(ech + 1, s ^ 1);
        CPA_COMMIT();
        CPA_WAIT1();
        __syncthreads();
#pragma unroll
        for (int i = 0; i < 4; i++) {
            int pl = w + 8 * i;
            uint2 vh = *(const uint2*)&raw[s * 2048 + pl * 64 + 2 * lane];
            A2h[(2 * pl) * 36 + lane]     = __byte_perm(vh.x, vh.y, 0x5410);
            A2h[(2 * pl + 1) * 36 + lane] = __byte_perm(vh.x, vh.y, 0x7632);
        }
        __syncthreads();
        const u32* Bh = (const u32*)(sm + 16384 + s * 9216);
#pragma unroll
        for (int kt = 0; kt < 4; kt++) {
            int kp = kt * 8;
            u32 ah[4] = { A2h[(rowb + g) * 36 + kp + tg],     A2h[(rowb + g + 8) * 36 + kp + tg],
                          A2h[(rowb + g) * 36 + kp + tg + 4], A2h[(rowb + g + 8) * 36 + kp + tg + 4] };
#pragma unroll
            for (int nt = 0; nt < 4; nt++) {
                int cb = wn * 32 + nt * 8;
                u32 bh[2] = { Bh[(kp + tg) * 72 + cb + g], Bh[(kp + tg + 4) * 72 + cb + g] };
                MMA(c[nt], ah, bh);
            }
            if (wn == 1) {
                u32 be[2] = { Bh[(kp + tg) * 72 + 64 + g], Bh[(kp + tg + 4) * 72 + 64 + g] };
                MMA(ce, ah, be);
            }
        }
        __syncthreads();
    }
#undef N_PRE
    // ---- epilogue: raw partial sums -> g_nacc / g_rsum ----
    const int r0g = n0 + rowb + g;
#pragma unroll
    for (int nt = 0; nt < 4; nt++) {
        int col = wn * 32 + nt * 8 + 2 * tg;
        if (r0g < NN)     red2(&g_nacc[r0g * 64 + col],       c[nt][0], c[nt][1]);
        if (r0g + 8 < NN) red2(&g_nacc[(r0g + 8) * 64 + col], c[nt][2], c[nt][3]);
    }
    if (wn == 1 && tg == 0) {
        if (r0g < NN)     atomicAdd(&g_rsum[r0g],     ce[0]);
        if (r0g + 8 < NN) atomicAdd(&g_rsum[r0g + 8], ce[2]);
    }
}

// ---------------- finalize_n: node = relu(nacc/rsum); writes g_node + nTh ----------
__global__ __launch_bounds__(256) void finalize_n_kernel() {
    const int t = threadIdx.x;
    const int p0 = blockIdx.x * 32;          // 313 blocks -> pairs [p0, p0+32)
#pragma unroll
    for (int i = 0; i < 8; i++) {
        int idx = t + 256 * i;
        int pp = p0 + (idx >> 6);
        int d  = idx & 63;
        int n  = 2 * pp;
        float v0 = 0.f, v1 = 0.f;
        if (n < NN) {
            float s0 = g_rsum[n];
            v0 = fmaxf(g_nacc[n * 64 + d], 0.f) * ((s0 > 0.f) ? 1.f / s0 : 0.f);
            g_node[n * 64 + d] = v0;
            g_nacc[n * 64 + d] = 0.f;        // self-clean
        }
        if (n + 1 < NN) {
            float s1 = g_rsum[n + 1];
            v1 = fmaxf(g_nacc[(n + 1) * 64 + d], 0.f) * ((s1 > 0.f) ? 1.f / s1 : 0.f);
            g_node[(n + 1) * 64 + d] = v1;
            g_nacc[(n + 1) * 64 + d] = 0.f;
        }
        g_nTh[pp * 64 + d] = packhi2(v0, v1);
    }
}

// ---------------- fusion + finalize3 merged; zeros acc2/csum/rsum ----------------
__global__ __launch_bounds__(256) void fusion_fin3_kernel(const float* __restrict__ fe_old,
                                                          const float* __restrict__ gamma,
                                                          const float* __restrict__ beta,
                                                          const float* __restrict__ w1,
                                                          const float* __restrict__ b1,
                                                          const float* __restrict__ w2,
                                                          float* __restrict__ out_nodes,
                                                          float* __restrict__ out_edges) {
    const int t = threadIdx.x;
    if (blockIdx.x >= 625) {                 // finalize3 part: 500 blocks
        int idx = (int)(blockIdx.x - 625) * 256 + t;
        int e = idx >> 6, d = idx & 63;
        float v = fmaxf(g_acc2[idx] / g_csum[e], 0.f);
        out_edges[idx] = v * (gamma[d] * rsqrtf(1.f + 1e-5f)) + beta[d];
        g_acc2[idx] = 0.f;
        if (idx < NN) g_rsum[idx] = 0.f;     // rsum consumed by finalize_n earlier
        __syncthreads();                     // all csum reads in this block done
        if (d == 0) g_csum[e] = 0.f;
        return;
    }
    __shared__ float w1s[64 * 64];
    __shared__ float b1s[64], w2s[64], gs[64], bs[64];
#pragma unroll
    for (int i = 0; i < 16; i++) w1s[t + 256 * i] = w1[t + 256 * i];
    if (t < 64) {
        b1s[t] = b1[t]; w2s[t] = w2[t];
        gs[t] = gamma[t] * rsqrtf(1.f + 1e-5f); bs[t] = beta[t];
    }
    __syncthreads();
    const int warp = t >> 5, lane = t & 31;
    const int nbase = blockIdx.x * 32 + warp * 4;
    for (int it = 0; it < 4; it++) {
        int n = nbase + it;
        if (n >= NN) break;
        int off = n * 64;
        float f0 = fe_old[off + lane], f1 = fe_old[off + lane + 32];
        float nb0 = fmaf(g_node[off + lane],      gs[lane],      bs[lane]);
        float nb1 = fmaf(g_node[off + lane + 32], gs[lane + 32], bs[lane + 32]);
        float ha0 = b1s[lane], ha1 = b1s[lane + 32];
        float hb0 = ha0, hb1 = ha1;
#pragma unroll
        for (int k = 0; k < 64; k++) {
            float fk = __shfl_sync(0xffffffffu, (k < 32) ? f0 : f1, k & 31);
            float nk = __shfl_sync(0xffffffffu, (k < 32) ? nb0 : nb1, k & 31);
            float wa = w1s[k * 64 + lane], wb = w1s[k * 64 + lane + 32];
            ha0 = fmaf(fk, wa, ha0); ha1 = fmaf(fk, wb, ha1);
            hb0 = fmaf(nk, wa, hb0); hb1 = fmaf(nk, wb, hb1);
        }
        ha0 = tanhf(ha0); ha1 = tanhf(ha1);
        hb0 = tanhf(hb0); hb1 = tanhf(hb1);
        float pa = ha0 * w2s[lane] + ha1 * w2s[lane + 32];
        float pb = hb0 * w2s[lane] + hb1 * w2s[lane + 32];
#pragma unroll
        for (int o = 16; o > 0; o >>= 1) {
            pa += __shfl_down_sync(0xffffffffu, pa, o);
            pb += __shfl_down_sync(0xffffffffu, pb, o);
        }
        pa = __shfl_sync(0xffffffffu, pa, 0);
        pb = __shfl_sync(0xffffffffu, pb, 0);
        float s0 = 1.f / (1.f + expf(pb - pa));
        out_nodes[off + lane]      = s0 * f0 + (1.f - s0) * nb0;
        out_nodes[off + lane + 32] = s0 * f1 + (1.f - s0) * nb1;
    }
}

// ---------------- launch ----------------
#define SM_ET1 (65536 + 17408 + 9216)        // 92160
#define SM_ET3 (34816 + 18432)               // 53248
#define SM_N   (16384 + 18432 + 9216)        // 44032

extern "C" void kernel_launch(void* const* d_in, const int* in_sizes, int n_in,
                              void* d_out, int out_size) {
    const float* fe    = (const float*)d_in[0];
    const float* adj   = (const float*)d_in[1];
    const float* W2    = (const float*)d_in[2];
    const float* W3    = (const float*)d_in[3];
    const float* gamma = (const float*)d_in[4];
    const float* beta  = (const float*)d_in[5];
    const float* fw1   = (const float*)d_in[6];
    const float* fb1   = (const float*)d_in[7];
    const float* fw2   = (const float*)d_in[8];
    float* out = (float*)d_out;

    cudaFuncSetAttribute((const void*)gemm_et1, cudaFuncAttributeMaxDynamicSharedMemorySize, SM_ET1);
    cudaFuncSetAttribute((const void*)gemm_et3, cudaFuncAttributeMaxDynamicSharedMemorySize, SM_ET3);
    cudaFuncSetAttribute((const void*)gemm_n,   cudaFuncAttributeMaxDynamicSharedMemorySize, SM_N);

    const float* fe_cur = fe;
    for (int s = 0; s < NS; s++) {
        const float* A   = adj + (size_t)s * NN * NE;
        float* out_nodes = out + (size_t)s * (NN + NE) * 64;
        float* out_edges = out_nodes + (size_t)NN * 64;

        gemm_x_kernel<<<313, 256>>>(fe_cur, W2);
        gemm_et1<<<dim3(16, 18), 256, SM_ET1>>>(A);    // exp once + cache g_Ph + edge_pre + csum
        finalize1_kernel<<<125, 256>>>(W3);            // edge -> yTh; zeros g_acc
        gemm_n<<<dim3(313, 2), 256, SM_N>>>();         // node partials (split-K over e)
        finalize_n_kernel<<<313, 256>>>();             // node = relu(nacc/rsum); nTh; clean nacc
        gemm_et3<<<dim3(16, 27), 256, SM_ET3>>>();     // edge2_pre (27 splits)
        fusion_fin3_kernel<<<1125, 256>>>(fe_cur, gamma, beta, fw1, fb1, fw2,
                                          out_nodes, out_edges);   // zeros acc2/csum/rsum

        fe_cur = out_nodes;
    }
}

// round 17
// speedup vs baseline: 3.1608x; 1.0147x over previous
#include <cuda_runtime.h>
#include <math.h>

#define NN 20000
#define NE 2000
#define NS 3
#define EPAD 2048
#define NPAIR 10016          // n-pairs (20032/2)

typedef unsigned int u32;

// ---------------- scratch (__device__ globals; zero-init, self-cleaning) ---------
__device__ __align__(16) u32 g_Ph[(size_t)NPAIR * EPAD]; // bf16-hi pairs of exp(adj): [npair][e]
__device__ __align__(16) u32 g_xTh[NPAIR * 64];          // (fe@W2)^T [npair][d] bf16-hi pairs
__device__ __align__(16) u32 g_yTh[1024 * 64];           // (edge@W3)^T [epair][d]
__device__ __align__(16) u32 g_nTh[NPAIR * 64];          // node^T [npair][d]
__device__ __align__(16) float g_acc [NE * 64];          // zeroed by finalize1
__device__ __align__(16) float g_acc2[NE * 64];          // zeroed by fusion_fin3
__device__ __align__(16) float g_nacc[NN * 64];          // node partials; zeroed by finalize_n
__device__ float g_csum[NE];                             // zeroed by fusion_fin3
__device__ float g_rsum[NN];                             // zeroed by fusion_fin3
__device__ __align__(16) float g_node[NN * 64];

// ---------------- helpers ----------------
__device__ __forceinline__ u32 smem_u32(const void* p) {
    u32 a; asm("{ .reg .u64 t; cvta.to.shared.u64 t, %1; cvt.u32.u64 %0, t; }" : "=r"(a) : "l"(p));
    return a;
}
__device__ __forceinline__ u32 bf16hi(float v) {      // RNE bf16, bits in top half
    u32 u = __float_as_uint(v);
    return (u + 0x7FFFu + ((u >> 16) & 1u)) & 0xFFFF0000u;
}
__device__ __forceinline__ u32 packhi2(float v0, float v1) {
    return (bf16hi(v0) >> 16) | bf16hi(v1);
}
__device__ __forceinline__ void MMA(float* c, const u32* a, const u32* b) {
    asm volatile("mma.sync.aligned.m16n8k16.row.col.f32.bf16.bf16.f32 "
        "{%0,%1,%2,%3}, {%4,%5,%6,%7}, {%8,%9}, {%0,%1,%2,%3};"
        : "+f"(c[0]), "+f"(c[1]), "+f"(c[2]), "+f"(c[3])
        : "r"(a[0]), "r"(a[1]), "r"(a[2]), "r"(a[3]), "r"(b[0]), "r"(b[1]));
}
__device__ __forceinline__ void red2(float* p, float a, float b) {
    asm volatile("red.global.add.v2.f32 [%0], {%1,%2};" :: "l"(p), "f"(a), "f"(b) : "memory");
}
__device__ __forceinline__ void cpa16(u32 dst, const void* src, u32 sz) {
    asm volatile("cp.async.cg.shared.global [%0], [%1], 16, %2;"
                 :: "r"(dst), "l"(src), "r"(sz) : "memory");
}
#define CPA_COMMIT() asm volatile("cp.async.commit_group;" ::: "memory")
#define CPA_WAIT1()  asm volatile("cp.async.wait_group 1;" ::: "memory")

// ---------------- gemm_x: x = fe @ W2, writes xT [npair][d] hi ----------------
__global__ __launch_bounds__(256) void gemm_x_kernel(const float* __restrict__ Fe,
                                                     const float* __restrict__ W2) {
    __shared__ __align__(16) float Fs[64][64];
    __shared__ __align__(16) float Ws[64][64];
    const int t  = threadIdx.x;
    const int n0 = blockIdx.x * 64;
    const int tx = t & 15, ty = t >> 4;
#pragma unroll
    for (int i = 0; i < 16; i++) {
        int idx = t + 256 * i;
        int r = idx >> 6, c = idx & 63;
        int n = n0 + r;
        Fs[r][c] = (n < NN) ? Fe[n * 64 + c] : 0.f;
        Ws[r][c] = W2[idx];
    }
    __syncthreads();
    float a[4][4];
#pragma unroll
    for (int i = 0; i < 4; i++)
#pragma unroll
        for (int j = 0; j < 4; j++) a[i][j] = 0.f;
#pragma unroll
    for (int k = 0; k < 64; k++) {
        float fv[4];
#pragma unroll
        for (int i = 0; i < 4; i++) fv[i] = Fs[ty * 4 + i][k];
        float4 w4 = *(const float4*)&Ws[k][tx * 4];
        float wv[4] = {w4.x, w4.y, w4.z, w4.w};
#pragma unroll
        for (int i = 0; i < 4; i++)
#pragma unroll
            for (int j = 0; j < 4; j++) a[i][j] = fmaf(fv[i], wv[j], a[i][j]);
    }
#pragma unroll
    for (int ip = 0; ip < 2; ip++)
#pragma unroll
        for (int j = 0; j < 4; j++) {
            int idx = ((n0 >> 1) + ty * 2 + ip) * 64 + tx * 4 + j;
            g_xTh[idx] = packhi2(a[2 * ip][j], a[2 * ip + 1][j]);
        }
}

// ---------------- GEMM1: acc[e,d] += sum_n exp(adj[n,e]) * x[n,d] ----------------
__global__ __launch_bounds__(256, 2) void gemm_et1(const float* __restrict__ A) {
    extern __shared__ __align__(16) char sm[];
    // raw[2][64][128]f32 @0 (65536) | Ah[32][136] @65536 (17408) | Bh[32][72] @82944 (9216)
    float* raw = (float*)sm;
    u32* Ah = (u32*)(sm + 65536);
    u32* Bh = (u32*)(sm + 82944);
    const u32 smb = smem_u32(sm);
    const int t = threadIdx.x, w = t >> 5, lane = t & 31;
    const int g = lane >> 2, tg = lane & 3;
    const int e0 = blockIdx.x * 128;
    const int sp = blockIdx.y;
    const int c0  = sp * 17 + (sp < 7 ? sp : 7);
    const int nch = 17 + (sp < 7 ? 1 : 0);
    const int wm = w >> 1, wn = w & 1;
    const int rowb = wm * 32;
    const int e_l = t & 127, half = t >> 7;
    const bool e_ok = (e0 + e_l) < NE;

    float c[2][4][4];
    float ce[2][4];
#pragma unroll
    for (int mt = 0; mt < 2; mt++) {
#pragma unroll
        for (int nt = 0; nt < 4; nt++)
#pragma unroll
            for (int q = 0; q < 4; q++) c[mt][nt][q] = 0.f;
#pragma unroll
        for (int q = 0; q < 4; q++) ce[mt][q] = 0.f;
    }
    {
        int r = t >> 3, cc = 64 + (t & 7);
        Bh[r * 72 + cc] = (cc == 64) ? 0x3F803F80u : 0u;
    }

#define E1_PRE(cj, ss) do {                                                        \
    int n0j = (c0 + (cj)) * 64;                                                    \
    _Pragma("unroll")                                                              \
    for (int j = 0; j < 8; j++) {                                                  \
        int idx = t + 256 * j;                                                     \
        int row = idx >> 5, seg = idx & 31;                                        \
        int n = n0j + row;                                                         \
        u32 sz = (n < NN && (e0 + seg * 4) < NE) ? 16u : 0u;                       \
        cpa16(smb + (ss) * 32768u + (u32)(row * 128 + seg * 4) * 4u,               \
              A + (size_t)n * NE + e0 + seg * 4, sz);                              \
    }                                                                              \
} while (0)

    E1_PRE(0, 0);
    CPA_COMMIT();

    for (int ci = 0; ci < nch; ci++) {
        const int s = ci & 1;
        const int n0  = (c0 + ci) * 64;
        const int np0 = n0 >> 1;
        if (ci + 1 < nch) E1_PRE(ci + 1, s ^ 1);
        CPA_COMMIT();
        u32 bhv[8];
        const int d = t & 63;
#pragma unroll
        for (int i = 0; i < 8; i++) {
            int r = (t >> 6) + 4 * i;
            bhv[i] = g_xTh[(np0 + r) * 64 + d];
        }
        CPA_WAIT1();
        __syncthreads();
#pragma unroll
        for (int i = 0; i < 8; i++) {
            int r = (t >> 6) + 4 * i;
            Bh[r * 72 + d] = bhv[i];
        }
        {
            const float* rw = raw + s * 8192;
#pragma unroll
            for (int i = 0; i < 16; i++) {
                int p_l = 2 * i + half;
                int n = n0 + 2 * p_l;
                float v0 = (e_ok && n < NN)     ? __expf(rw[(2 * p_l) * 128 + e_l])     : 0.f;
                float v1 = (e_ok && n + 1 < NN) ? __expf(rw[(2 * p_l + 1) * 128 + e_l]) : 0.f;
                u32 h = packhi2(v0, v1);
                Ah[p_l * 136 + e_l] = h;
                g_Ph[(size_t)(np0 + p_l) * EPAD + e0 + e_l] = h;
            }
        }
        __syncthreads();
#pragma unroll
        for (int kt = 0; kt < 4; kt++) {
            int kp = kt * 8;
            u32 ah[2][4];
#pragma unroll
            for (int mt = 0; mt < 2; mt++) {
                int rb = rowb + mt * 16;
                ah[mt][0] = Ah[(kp + tg) * 136 + rb + g];
                ah[mt][1] = Ah[(kp + tg) * 136 + rb + g + 8];
                ah[mt][2] = Ah[(kp + tg + 4) * 136 + rb + g];
                ah[mt][3] = Ah[(kp + tg + 4) * 136 + rb + g + 8];
            }
#pragma unroll
            for (int nt = 0; nt < 4; nt++) {
                int cb = wn * 32 + nt * 8;
                u32 bh[2] = { Bh[(kp + tg) * 72 + cb + g], Bh[(kp + tg + 4) * 72 + cb + g] };
#pragma unroll
                for (int mt = 0; mt < 2; mt++) MMA(c[mt][nt], ah[mt], bh);
            }
            if (wn == 1) {
                u32 be[2] = { Bh[(kp + tg) * 72 + 64 + g], Bh[(kp + tg + 4) * 72 + 64 + g] };
#pragma unroll
                for (int mt = 0; mt < 2; mt++) MMA(ce[mt], ah[mt], be);
            }
        }
        __syncthreads();
    }
#undef E1_PRE
#pragma unroll
    for (int mt = 0; mt < 2; mt++)
#pragma unroll
        for (int nt = 0; nt < 4; nt++) {
            int row = e0 + rowb + mt * 16 + g;
            int col = wn * 32 + nt * 8 + 2 * tg;
            if (row < NE)     red2(&g_acc[row * 64 + col],       c[mt][nt][0], c[mt][nt][1]);
            if (row + 8 < NE) red2(&g_acc[(row + 8) * 64 + col], c[mt][nt][2], c[mt][nt][3]);
        }
    if (wn == 1 && tg == 0) {
#pragma unroll
        for (int mt = 0; mt < 2; mt++) {
            int row = e0 + rowb + mt * 16 + g;
            if (row < NE)     atomicAdd(&g_csum[row],     ce[mt][0]);
            if (row + 8 < NE) atomicAdd(&g_csum[row + 8], ce[mt][2]);
        }
    }
}

// ---------------- GEMM3: acc2[e,d] += sum_n exp(adj[n,e]) * node[n,d] -------------
__global__ __launch_bounds__(256, 3) void gemm_et3() {
    extern __shared__ __align__(16) char sm[];
    // Ah[2][32*136] @0 (34816) | Bh[2][32*72] @34816 (18432) = 53248
    const u32 smb = smem_u32(sm);
    const int t = threadIdx.x, w = t >> 5, lane = t & 31;
    const int g = lane >> 2, tg = lane & 3;
    const int e0 = blockIdx.x * 128;
    const int sp = blockIdx.y;
    const int c0  = sp * 11 + (sp < 16 ? sp : 16);
    const int nch = 11 + (sp < 16 ? 1 : 0);
    const int wm = w >> 1, wn = w & 1;
    const int rowb = wm * 32;

    float c[2][4][4];
#pragma unroll
    for (int mt = 0; mt < 2; mt++)
#pragma unroll
        for (int nt = 0; nt < 4; nt++)
#pragma unroll
            for (int q = 0; q < 4; q++) c[mt][nt][q] = 0.f;

#define E3_PRE(cj, ss) do {                                                        \
    int np0j = (c0 + (cj)) * 32;                                                   \
    _Pragma("unroll")                                                              \
    for (int j = 0; j < 4; j++) {                                                  \
        int idx = t + 256 * j;                                                     \
        int row = idx >> 5, seg = idx & 31;                                        \
        cpa16(smb + (ss) * 17408u + (u32)(row * 136 + seg * 4) * 4u,               \
              g_Ph + (size_t)(np0j + row) * EPAD + e0 + seg * 4, 16u);             \
    }                                                                              \
    _Pragma("unroll")                                                              \
    for (int j = 0; j < 2; j++) {                                                  \
        int k = t + 256 * j;                                                       \
        int r = k >> 4, s4 = k & 15;                                               \
        cpa16(smb + 34816u + (ss) * 9216u + (u32)(r * 72 + s4 * 4) * 4u,           \
              g_nTh + (size_t)np0j * 64 + k * 4, 16u);                             \
    }                                                                              \
} while (0)

    E3_PRE(0, 0);
    CPA_COMMIT();

    for (int ci = 0; ci < nch; ci++) {
        const int s = ci & 1;
        if (ci + 1 < nch) E3_PRE(ci + 1, s ^ 1);
        CPA_COMMIT();
        CPA_WAIT1();
        __syncthreads();
        const u32* Ap = (const u32*)(sm + s * 17408);
        const u32* Bh = (const u32*)(sm + 34816 + s * 9216);
#pragma unroll
        for (int kt = 0; kt < 4; kt++) {
            int kp = kt * 8;
            u32 ah[2][4];
#pragma unroll
            for (int mt = 0; mt < 2; mt++) {
                int rb = rowb + mt * 16;
                ah[mt][0] = Ap[(kp + tg) * 136 + rb + g];
                ah[mt][1] = Ap[(kp + tg) * 136 + rb + g + 8];
                ah[mt][2] = Ap[(kp + tg + 4) * 136 + rb + g];
                ah[mt][3] = Ap[(kp + tg + 4) * 136 + rb + g + 8];
            }
#pragma unroll
            for (int nt = 0; nt < 4; nt++) {
                int cb = wn * 32 + nt * 8;
                u32 bh[2] = { Bh[(kp + tg) * 72 + cb + g], Bh[(kp + tg + 4) * 72 + cb + g] };
#pragma unroll
                for (int mt = 0; mt < 2; mt++) MMA(c[mt][nt], ah[mt], bh);
            }
        }
        __syncthreads();
    }
#undef E3_PRE
#pragma unroll
    for (int mt = 0; mt < 2; mt++)
#pragma unroll
        for (int nt = 0; nt < 4; nt++) {
            int row = e0 + rowb + mt * 16 + g;
            int col = wn * 32 + nt * 8 + 2 * tg;
            if (row < NE)     red2(&g_acc2[row * 64 + col],       c[mt][nt][0], c[mt][nt][1]);
            if (row + 8 < NE) red2(&g_acc2[(row + 8) * 64 + col], c[mt][nt][2], c[mt][nt][3]);
        }
}

// ---------------- finalize1: edge = relu(acc/csum); y = edge@W3 -> yTh; zero acc --
__global__ __launch_bounds__(256) void finalize1_kernel(const float* __restrict__ W3) {
    __shared__ __align__(16) float EsT[64][17];
    __shared__ __align__(16) float Ws[64][64];
    __shared__ __align__(16) float Ys[16][64];
    const int t  = threadIdx.x;
    const int e0 = blockIdx.x * 16;      // 125 blocks * 16 = 2000
#pragma unroll
    for (int i = 0; i < 16; i++) {
        int idx = t + 256 * i;
        Ws[idx >> 6][idx & 63] = W3[idx];
    }
#pragma unroll
    for (int i = 0; i < 4; i++) {
        int idx = t + 256 * i;
        int r = idx >> 6, c = idx & 63;
        int ge = e0 + r;
        EsT[c][r] = fmaxf(g_acc[ge * 64 + c] / g_csum[ge], 0.f);
        g_acc[ge * 64 + c] = 0.f;        // self-clean
    }
    __syncthreads();
    const int ty = t >> 4, tx = t & 15;
    float a0 = 0.f, a1 = 0.f, a2 = 0.f, a3 = 0.f;
#pragma unroll
    for (int k = 0; k < 64; k++) {
        float ev = EsT[k][ty];
        float4 w4 = *(const float4*)&Ws[k][tx * 4];
        a0 = fmaf(ev, w4.x, a0); a1 = fmaf(ev, w4.y, a1);
        a2 = fmaf(ev, w4.z, a2); a3 = fmaf(ev, w4.w, a3);
    }
    float4 r4 = {a0, a1, a2, a3};
    *(float4*)&Ys[ty][tx * 4] = r4;
    __syncthreads();
#pragma unroll
    for (int i = 0; i < 2; i++) {
        int idx = t + 256 * i;
        int pp = idx >> 6, d = idx & 63;
        int gp = (e0 >> 1) + pp;
        g_yTh[gp * 64 + d] = packhi2(Ys[2 * pp][d], Ys[2 * pp + 1][d]);
    }
}

// ---------------- GEMM2: nacc[n,d] += sum_{e in split} exp(adj[n,e]) * y[e,d] ----
// Split-K over e; A-fragments built DIRECTLY from staged g_Ph pairs via prmt
// (no A2h bounce, no repack STS, one fewer sync per chunk). raw rows padded to
// 72 u32 so the LDS.64 fragment loads are bank-conflict-free.
__global__ __launch_bounds__(256, 3) void gemm_n() {
    extern __shared__ __align__(16) char sm[];
    // raw[2][32][72]u32 @0 (18432) | Bh[2][32*72]u32 @18432 (18432) = 36864
    u32* raw = (u32*)sm;
    const u32 smb = smem_u32(sm);
    const int t = threadIdx.x, w = t >> 5, lane = t & 31;
    const int g = lane >> 2, tg = lane & 3;
    const int p0 = blockIdx.x * 32;
    const int n0 = p0 * 2;
    const int base = blockIdx.y * 16;    // e-chunk split: [base, base+16)
    const int wm = w >> 1, wn = w & 1;
    const int rowb = wm * 16;
    const int plA = (rowb + g) >> 1;     // rows rowb+g, rowb+g+8 -> pairs plA, plA+4
    const u32 sel = (g & 1) ? 0x7632u : 0x5410u;

    float c[4][4];
    float ce[4];
#pragma unroll
    for (int nt = 0; nt < 4; nt++)
#pragma unroll
        for (int q = 0; q < 4; q++) c[nt][q] = 0.f;
#pragma unroll
    for (int q = 0; q < 4; q++) ce[q] = 0.f;

    // init ones cols (64-71) of both B stages
    {
        int r = t >> 3, cc = 64 + (t & 7);
        u32 val = (cc == 64) ? 0x3F803F80u : 0u;
#pragma unroll
        for (int st = 0; st < 2; st++)
            ((u32*)(sm + 18432 + st * 9216))[r * 72 + cc] = val;
    }

#define N_PRE(cj, ss) do {                                                         \
    _Pragma("unroll")                                                              \
    for (int j = 0; j < 2; j++) {                                                  \
        int idx = t + 256 * j;                                                     \
        int row = idx >> 4, seg = idx & 15;                                        \
        cpa16(smb + (ss) * 9216u + (u32)(row * 72 + seg * 4) * 4u,                 \
              g_Ph + (size_t)(p0 + row) * EPAD + (cj) * 64 + seg * 4, 16u);        \
    }                                                                              \
    _Pragma("unroll")                                                              \
    for (int j = 0; j < 2; j++) {                                                  \
        int k = t + 256 * j;                                                       \
        int r = k >> 4, s4 = k & 15;                                               \
        cpa16(smb + 18432u + (ss) * 9216u + (u32)(r * 72 + s4 * 4) * 4u,           \
              g_yTh + (size_t)(cj) * 2048 + k * 4, 16u);                           \
    }                                                                              \
} while (0)

    N_PRE(base, 0);
    CPA_COMMIT();

    for (int ech = base; ech < base + 16; ech++) {
        const int s = ech & 1;
        if (ech + 1 < base + 16) N_PRE(ech + 1, s ^ 1);
        CPA_COMMIT();
        CPA_WAIT1();
        __syncthreads();
        const u32* rw = raw + s * 2304;                // 32*72
        const u32* Bh = (const u32*)(sm + 18432 + s * 9216);
#pragma unroll
        for (int kt = 0; kt < 4; kt++) {
            int kp = kt * 8;
            uint2 vA0 = *(const uint2*)&rw[plA * 72 + 2 * (kp + tg)];
            uint2 vA1 = *(const uint2*)&rw[plA * 72 + 2 * (kp + tg + 4)];
            uint2 vB0 = *(const uint2*)&rw[(plA + 4) * 72 + 2 * (kp + tg)];
            uint2 vB1 = *(const uint2*)&rw[(plA + 4) * 72 + 2 * (kp + tg + 4)];
            u32 ah[4] = { __byte_perm(vA0.x, vA0.y, sel),
                          __byte_perm(vB0.x, vB0.y, sel),
                          __byte_perm(vA1.x, vA1.y, sel),
                          __byte_perm(vB1.x, vB1.y, sel) };
#pragma unroll
            for (int nt = 0; nt < 4; nt++) {
                int cb = wn * 32 + nt * 8;
                u32 bh[2] = { Bh[(kp + tg) * 72 + cb + g], Bh[(kp + tg + 4) * 72 + cb + g] };
                MMA(c[nt], ah, bh);
            }
            if (wn == 1) {
                u32 be[2] = { Bh[(kp + tg) * 72 + 64 + g], Bh[(kp + tg + 4) * 72 + 64 + g] };
                MMA(ce, ah, be);
            }
        }
        __syncthreads();   // close MMA before stage s is re-prefetched
    }
#undef N_PRE
    // ---- epilogue: raw partial sums -> g_nacc / g_rsum ----
    const int r0g = n0 + rowb + g;
#pragma unroll
    for (int nt = 0; nt < 4; nt++) {
        int col = wn * 32 + nt * 8 + 2 * tg;
        if (r0g < NN)     red2(&g_nacc[r0g * 64 + col],       c[nt][0], c[nt][1]);
        if (r0g + 8 < NN) red2(&g_nacc[(r0g + 8) * 64 + col], c[nt][2], c[nt][3]);
    }
    if (wn == 1 && tg == 0) {
        if (r0g < NN)     atomicAdd(&g_rsum[r0g],     ce[0]);
        if (r0g + 8 < NN) atomicAdd(&g_rsum[r0g + 8], ce[2]);
    }
}

// ---------------- finalize_n: node = relu(nacc/rsum); writes g_node + nTh ----------
__global__ __launch_bounds__(256) void finalize_n_kernel() {
    const int t = threadIdx.x;
    const int p0 = blockIdx.x * 32;          // 313 blocks -> pairs [p0, p0+32)
#pragma unroll
    for (int i = 0; i < 8; i++) {
        int idx = t + 256 * i;
        int pp = p0 + (idx >> 6);
        int d  = idx & 63;
        int n  = 2 * pp;
        float v0 = 0.f, v1 = 0.f;
        if (n < NN) {
            float s0 = g_rsum[n];
            v0 = fmaxf(g_nacc[n * 64 + d], 0.f) * ((s0 > 0.f) ? 1.f / s0 : 0.f);
            g_node[n * 64 + d] = v0;
            g_nacc[n * 64 + d] = 0.f;        // self-clean
        }
        if (n + 1 < NN) {
            float s1 = g_rsum[n + 1];
            v1 = fmaxf(g_nacc[(n + 1) * 64 + d], 0.f) * ((s1 > 0.f) ? 1.f / s1 : 0.f);
            g_node[(n + 1) * 64 + d] = v1;
            g_nacc[(n + 1) * 64 + d] = 0.f;
        }
        g_nTh[pp * 64 + d] = packhi2(v0, v1);
    }
}

// ---------------- fusion + finalize3 merged; zeros acc2/csum/rsum ----------------
__global__ __launch_bounds__(256) void fusion_fin3_kernel(const float* __restrict__ fe_old,
                                                          const float* __restrict__ gamma,
                                                          const float* __restrict__ beta,
                                                          const float* __restrict__ w1,
                                                          const float* __restrict__ b1,
                                                          const float* __restrict__ w2,
                                                          float* __restrict__ out_nodes,
                                                          float* __restrict__ out_edges) {
    const int t = threadIdx.x;
    if (blockIdx.x >= 625) {                 // finalize3 part: 500 blocks
        int idx = (int)(blockIdx.x - 625) * 256 + t;
        int e = idx >> 6, d = idx & 63;
        float v = fmaxf(g_acc2[idx] / g_csum[e], 0.f);
        out_edges[idx] = v * (gamma[d] * rsqrtf(1.f + 1e-5f)) + beta[d];
        g_acc2[idx] = 0.f;
        if (idx < NN) g_rsum[idx] = 0.f;     // rsum consumed by finalize_n earlier
        __syncthreads();                     // all csum reads in this block done
        if (d == 0) g_csum[e] = 0.f;
        return;
    }
    __shared__ float w1s[64 * 64];
    __shared__ float b1s[64], w2s[64], gs[64], bs[64];
#pragma unroll
    for (int i = 0; i < 16; i++) w1s[t + 256 * i] = w1[t + 256 * i];
    if (t < 64) {
        b1s[t] = b1[t]; w2s[t] = w2[t];
        gs[t] = gamma[t] * rsqrtf(1.f + 1e-5f); bs[t] = beta[t];
    }
    __syncthreads();
    const int warp = t >> 5, lane = t & 31;
    const int nbase = blockIdx.x * 32 + warp * 4;
    for (int it = 0; it < 4; it++) {
        int n = nbase + it;
        if (n >= NN) break;
        int off = n * 64;
        float f0 = fe_old[off + lane], f1 = fe_old[off + lane + 32];
        float nb0 = fmaf(g_node[off + lane],      gs[lane],      bs[lane]);
        float nb1 = fmaf(g_node[off + lane + 32], gs[lane + 32], bs[lane + 32]);
        float ha0 = b1s[lane], ha1 = b1s[lane + 32];
        float hb0 = ha0, hb1 = ha1;
#pragma unroll
        for (int k = 0; k < 64; k++) {
            float fk = __shfl_sync(0xffffffffu, (k < 32) ? f0 : f1, k & 31);
            float nk = __shfl_sync(0xffffffffu, (k < 32) ? nb0 : nb1, k & 31);
            float wa = w1s[k * 64 + lane], wb = w1s[k * 64 + lane + 32];
            ha0 = fmaf(fk, wa, ha0); ha1 = fmaf(fk, wb, ha1);
            hb0 = fmaf(nk, wa, hb0); hb1 = fmaf(nk, wb, hb1);
        }
        ha0 = tanhf(ha0); ha1 = tanhf(ha1);
        hb0 = tanhf(hb0); hb1 = tanhf(hb1);
        float pa = ha0 * w2s[lane] + ha1 * w2s[lane + 32];
        float pb = hb0 * w2s[lane] + hb1 * w2s[lane + 32];
#pragma unroll
        for (int o = 16; o > 0; o >>= 1) {
            pa += __shfl_down_sync(0xffffffffu, pa, o);
            pb += __shfl_down_sync(0xffffffffu, pb, o);
        }
        pa = __shfl_sync(0xffffffffu, pa, 0);
        pb = __shfl_sync(0xffffffffu, pb, 0);
        float s0 = 1.f / (1.f + expf(pb - pa));
        out_nodes[off + lane]      = s0 * f0 + (1.f - s0) * nb0;
        out_nodes[off + lane + 32] = s0 * f1 + (1.f - s0) * nb1;
    }
}

// ---------------- launch ----------------
#define SM_ET1 (65536 + 17408 + 9216)        // 92160
#define SM_ET3 (34816 + 18432)               // 53248
#define SM_N   (18432 + 18432)               // 36864

extern "C" void kernel_launch(void* const* d_in, const int* in_sizes, int n_in,
                              void* d_out, int out_size) {
    const float* fe    = (const float*)d_in[0];
    const float* adj   = (const float*)d_in[1];
    const float* W2    = (const float*)d_in[2];
    const float* W3    = (const float*)d_in[3];
    const float* gamma = (const float*)d_in[4];
    const float* beta  = (const float*)d_in[5];
    const float* fw1   = (const float*)d_in[6];
    const float* fb1   = (const float*)d_in[7];
    const float* fw2   = (const float*)d_in[8];
    float* out = (float*)d_out;

    cudaFuncSetAttribute((const void*)gemm_et1, cudaFuncAttributeMaxDynamicSharedMemorySize, SM_ET1);
    cudaFuncSetAttribute((const void*)gemm_et3, cudaFuncAttributeMaxDynamicSharedMemorySize, SM_ET3);
    cudaFuncSetAttribute((const void*)gemm_n,   cudaFuncAttributeMaxDynamicSharedMemorySize, SM_N);

    const float* fe_cur = fe;
    for (int s = 0; s < NS; s++) {
        const float* A   = adj + (size_t)s * NN * NE;
        float* out_nodes = out + (size_t)s * (NN + NE) * 64;
        float* out_edges = out_nodes + (size_t)NN * 64;

        gemm_x_kernel<<<313, 256>>>(fe_cur, W2);
        gemm_et1<<<dim3(16, 18), 256, SM_ET1>>>(A);    // exp once + cache g_Ph + edge_pre + csum
        finalize1_kernel<<<125, 256>>>(W3);            // edge -> yTh; zeros g_acc
        gemm_n<<<dim3(313, 2), 256, SM_N>>>();         // node partials (direct-prmt fragments)
        finalize_n_kernel<<<313, 256>>>();             // node = relu(nacc/rsum); nTh; clean nacc
        gemm_et3<<<dim3(16, 27), 256, SM_ET3>>>();     // edge2_pre (27 splits)
        fusion_fin3_kernel<<<1125, 256>>>(fe_cur, gamma, beta, fw1, fb1, fw2,
                                          out_nodes, out_edges);   // zeros acc2/csum/rsum

        fe_cur = out_nodes;
    }
}